// round 1
// baseline (speedup 1.0000x reference)
#include <cuda_runtime.h>
#include <cstdint>
#include <cstddef>

// ---------------- problem constants ----------------
#define LNUM 4
#define BB   64
#define NTOK 197
#define CDIM 768
#define NH   12
#define HDIM 64
#define HF   2048
#define C3   (3*CDIM)
#define TTOK (BB*NTOK)          // 12608
#define SCALE 0.125f            // 64^-0.5
#define EPS 1e-6f

// ---------------- scratch (device globals: no allocs allowed) ----------------
__device__ float g_y   [(size_t)TTOK*CDIM];
__device__ float g_qkv [(size_t)TTOK*C3];
__device__ float g_o   [(size_t)TTOK*CDIM];
__device__ float g_gate[(size_t)TTOK*HF];
__device__ float g_up  [(size_t)TTOK*HF];
__device__ float g_u   [(size_t)TTOK*HF];
__device__ float g_bias3[LNUM*C3];

// ---------------- block reduction helper ----------------
__device__ __forceinline__ float2 block_sum2(float2 v) {
    __shared__ float2 red[8];
    int lane = threadIdx.x & 31, warp = threadIdx.x >> 5;
#pragma unroll
    for (int off = 16; off; off >>= 1) {
        v.x += __shfl_xor_sync(0xffffffffu, v.x, off);
        v.y += __shfl_xor_sync(0xffffffffu, v.y, off);
    }
    if (lane == 0) red[warp] = v;
    __syncthreads();
    if (warp == 0) {
        float2 w = (lane < 8) ? red[lane] : make_float2(0.f, 0.f);
#pragma unroll
        for (int off = 4; off; off >>= 1) {
            w.x += __shfl_xor_sync(0xffffffffu, w.x, off);
            w.y += __shfl_xor_sync(0xffffffffu, w.y, off);
        }
        if (lane == 0) red[0] = w;
    }
    __syncthreads();
    return red[0];
}

// ---------------- LayerNorm over last dim (CD = 768 or 2048) ----------------
template <int CD>
__global__ __launch_bounds__(256) void ln_kernel(
    const float* __restrict__ in, const float* __restrict__ gamma,
    const float* __restrict__ beta, float* __restrict__ out)
{
    constexpr int PER = CD / 256;
    const size_t base = (size_t)blockIdx.x * CD;
    float v[PER];
    float2 s = make_float2(0.f, 0.f);
#pragma unroll
    for (int i = 0; i < PER; i++) {
        v[i] = in[base + i*256 + threadIdx.x];
        s.x += v[i]; s.y += v[i]*v[i];
    }
    s = block_sum2(s);
    float mean = s.x * (1.f / CD);
    float var  = s.y * (1.f / CD) - mean * mean;
    float inv  = rsqrtf(var + EPS);
#pragma unroll
    for (int i = 0; i < PER; i++) {
        int c = i*256 + threadIdx.x;
        out[base + c] = (v[i] - mean) * inv * gamma[c] + beta[c];
    }
}

// ---------------- SwiGLU + inner LayerNorm (HF = 2048) ----------------
__global__ __launch_bounds__(256) void swiglu_ln_kernel(
    const float* __restrict__ G, const float* __restrict__ X,
    const float* __restrict__ gamma, const float* __restrict__ beta,
    float* __restrict__ out)
{
    const size_t base = (size_t)blockIdx.x * HF;
    float u[8];
    float2 s = make_float2(0.f, 0.f);
#pragma unroll
    for (int i = 0; i < 8; i++) {
        int c = i*256 + threadIdx.x;
        float g = G[base + c];
        float x = X[base + c];
        float uu = (g / (1.f + __expf(-g))) * x;   // silu(g) * x
        u[i] = uu; s.x += uu; s.y += uu*uu;
    }
    s = block_sum2(s);
    float mean = s.x * (1.f / HF);
    float var  = s.y * (1.f / HF) - mean * mean;
    float inv  = rsqrtf(var + EPS);
#pragma unroll
    for (int i = 0; i < 8; i++) {
        int c = i*256 + threadIdx.x;
        out[base + c] = (u[i] - mean) * inv * gamma[c] + beta[c];
    }
}

// ---------------- fused qkv bias build: [q_bias | 0 | v_bias] per layer ----------------
__global__ void bias3_kernel(float* __restrict__ bias3,
                             const float* __restrict__ qb,
                             const float* __restrict__ vb)
{
    int idx = blockIdx.x * blockDim.x + threadIdx.x;   // L*C3 = 9216
    if (idx >= LNUM * C3) return;
    int l = idx / C3, j = idx % C3;
    float v = 0.f;
    if (j < CDIM)            v = qb[l*CDIM + j];
    else if (j >= 2*CDIM)    v = vb[l*CDIM + (j - 2*CDIM)];
    bias3[idx] = v;
}

// ---------------- RoPE (interleaved rotate-half), in place on qkv, skip CLS ----------------
__global__ void rope_kernel(float* __restrict__ qkv, const float* __restrict__ rope)
{
    int idx = blockIdx.x * blockDim.x + threadIdx.x;   // T*NH*32
    if (idx >= TTOK * NH * (HDIM/2)) return;
    int pair = idx & 31;
    int h    = (idx >> 5) % NH;
    int t    = idx / (32 * NH);
    int n    = t % NTOK;
    if (n == 0) return;                                 // CLS token untouched
    const float* rp = rope + (size_t)(n - 1) * (2*HDIM);
    int d0 = pair*2, d1 = d0 + 1;
    float s0 = rp[d0],        s1 = rp[d1];
    float c0 = rp[HDIM + d0], c1 = rp[HDIM + d1];
    size_t base = (size_t)t * C3 + h * HDIM;
    // q
    {
        float x0 = qkv[base + d0], x1 = qkv[base + d1];
        qkv[base + d0] = x0*c0 - x1*s0;
        qkv[base + d1] = x1*c1 + x0*s1;
    }
    // k
    {
        size_t kb = base + CDIM;
        float x0 = qkv[kb + d0], x1 = qkv[kb + d1];
        qkv[kb + d0] = x0*c0 - x1*s0;
        qkv[kb + d1] = x1*c1 + x0*s1;
    }
}

// ---------------- attention: one block per (batch, head); K,V resident in smem ----------------
#define KP 65                                  // pitch to avoid bank conflicts
#define ATTN_SMEM ((2*NTOK*KP + 8*HDIM + 8*NTOK) * 4)

__global__ __launch_bounds__(256) void attn_kernel(
    const float* __restrict__ qkv, float* __restrict__ o)
{
    extern __shared__ float sm[];
    float* Ks = sm;                   // [197][65]
    float* Vs = Ks + NTOK*KP;         // [197][65]
    float* qs = Vs + NTOK*KP;         // [8][64]
    float* ps = qs + 8*HDIM;          // [8][197]

    int bh = blockIdx.x;
    int b = bh / NH, h = bh % NH;
    size_t t0 = (size_t)b * NTOK;
    int tid = threadIdx.x, warp = tid >> 5, lane = tid & 31;

    for (int i = tid; i < NTOK*HDIM; i += 256) {
        int r = i >> 6, d = i & 63;
        size_t src = (t0 + r) * C3 + h * HDIM + d;
        Ks[r*KP + d] = qkv[src + CDIM];
        Vs[r*KP + d] = qkv[src + 2*CDIM];
    }
    __syncthreads();

    for (int r = warp; r < NTOK; r += 8) {
        const float* qrow = &qkv[(t0 + r) * C3 + h * HDIM];
        qs[warp*HDIM + lane]      = qrow[lane]      * SCALE;
        qs[warp*HDIM + lane + 32] = qrow[lane + 32] * SCALE;
        __syncwarp();

        float sc[7];
        float mx = -1e30f;
        int nc = 0;
        for (int c = lane; c < NTOK; c += 32) {
            float s = 0.f;
#pragma unroll
            for (int d = 0; d < HDIM; d++)
                s += qs[warp*HDIM + d] * Ks[c*KP + d];
            sc[nc++] = s;
            mx = fmaxf(mx, s);
        }
#pragma unroll
        for (int off = 16; off; off >>= 1)
            mx = fmaxf(mx, __shfl_xor_sync(0xffffffffu, mx, off));
        float sum = 0.f;
        for (int i = 0; i < nc; i++) { sc[i] = __expf(sc[i] - mx); sum += sc[i]; }
#pragma unroll
        for (int off = 16; off; off >>= 1)
            sum += __shfl_xor_sync(0xffffffffu, sum, off);
        float inv = 1.f / sum;
        nc = 0;
        for (int c = lane; c < NTOK; c += 32) ps[warp*NTOK + c] = sc[nc++] * inv;
        __syncwarp();

        float a0 = 0.f, a1 = 0.f;
        for (int c = 0; c < NTOK; c++) {
            float p = ps[warp*NTOK + c];
            a0 += p * Vs[c*KP + lane];
            a1 += p * Vs[c*KP + lane + 32];
        }
        size_t dst = (t0 + r) * CDIM + h * HDIM;
        o[dst + lane]      = a0;
        o[dst + lane + 32] = a1;
        __syncwarp();
    }
}

// ---------------- generic fp32 GEMM: out[M,N] = A[M,K] @ W[N,K]^T + bias (+ residual) ----------------
// 128x128x8 tile, 256 threads, 2x2 float4 micro-tiles, padded smem (pitch 132).
#define SP 132
__global__ __launch_bounds__(256) void gemm_kernel(
    const float* __restrict__ A, const float* __restrict__ W,
    const float* __restrict__ bias, float* __restrict__ out,
    int M, int N, int K, int residual)
{
    __shared__ float As[8*SP];
    __shared__ float Ws[8*SP];
    const int tid  = threadIdx.x;
    const int tx   = tid & 15;
    const int ty   = tid >> 4;
    const int bm   = blockIdx.y, bn = blockIdx.x;
    const int lrow = tid >> 1;
    const int lk   = (tid & 1) * 4;

    const float* Ap = A + (size_t)(bm*128 + lrow) * K + lk;
    const float* Wp = W + (size_t)(bn*128 + lrow) * K + lk;
    const bool aok  = (bm*128 + lrow) < M;

    float acc[2][2][4][4];
#pragma unroll
    for (int ii = 0; ii < 2; ii++)
#pragma unroll
        for (int jj = 0; jj < 2; jj++)
#pragma unroll
            for (int i = 0; i < 4; i++)
#pragma unroll
                for (int j = 0; j < 4; j++) acc[ii][jj][i][j] = 0.f;

    for (int k0 = 0; k0 < K; k0 += 8) {
        float4 av = aok ? *(const float4*)Ap : make_float4(0.f, 0.f, 0.f, 0.f);
        float4 wv = *(const float4*)Wp;
        __syncthreads();
        As[(lk+0)*SP + lrow] = av.x; As[(lk+1)*SP + lrow] = av.y;
        As[(lk+2)*SP + lrow] = av.z; As[(lk+3)*SP + lrow] = av.w;
        Ws[(lk+0)*SP + lrow] = wv.x; Ws[(lk+1)*SP + lrow] = wv.y;
        Ws[(lk+2)*SP + lrow] = wv.z; Ws[(lk+3)*SP + lrow] = wv.w;
        __syncthreads();
#pragma unroll
        for (int kk = 0; kk < 8; kk++) {
            float4 a0 = *(const float4*)&As[kk*SP + ty*4];
            float4 a1 = *(const float4*)&As[kk*SP + 64 + ty*4];
            float4 b0 = *(const float4*)&Ws[kk*SP + tx*4];
            float4 b1 = *(const float4*)&Ws[kk*SP + 64 + tx*4];
            float a[2][4] = {{a0.x,a0.y,a0.z,a0.w},{a1.x,a1.y,a1.z,a1.w}};
            float bb[2][4] = {{b0.x,b0.y,b0.z,b0.w},{b1.x,b1.y,b1.z,b1.w}};
#pragma unroll
            for (int ii = 0; ii < 2; ii++)
#pragma unroll
                for (int i = 0; i < 4; i++)
#pragma unroll
                    for (int jj = 0; jj < 2; jj++)
#pragma unroll
                        for (int j = 0; j < 4; j++)
                            acc[ii][jj][i][j] += a[ii][i] * bb[jj][j];
        }
        Ap += 8; Wp += 8;
    }

#pragma unroll
    for (int ii = 0; ii < 2; ii++)
#pragma unroll
        for (int i = 0; i < 4; i++) {
            int row = bm*128 + ii*64 + ty*4 + i;
            if (row >= M) continue;
#pragma unroll
            for (int jj = 0; jj < 2; jj++) {
                int col = bn*128 + jj*64 + tx*4;
                float4 bv = *(const float4*)&bias[col];
                float4 r;
                r.x = acc[ii][jj][i][0] + bv.x;
                r.y = acc[ii][jj][i][1] + bv.y;
                r.z = acc[ii][jj][i][2] + bv.z;
                r.w = acc[ii][jj][i][3] + bv.w;
                float* op = out + (size_t)row * N + col;
                if (residual) {
                    float4 ov = *(const float4*)op;
                    r.x += ov.x; r.y += ov.y; r.z += ov.z; r.w += ov.w;
                }
                *(float4*)op = r;
            }
        }
}

// ---------------- host orchestration ----------------
extern "C" void kernel_launch(void* const* d_in, const int* in_sizes, int n_in,
                              void* d_out, int out_size)
{
    const float* x      = (const float*)d_in[0];
    const float* rope   = (const float*)d_in[1];
    const float* qkv_w  = (const float*)d_in[2];
    const float* q_bias = (const float*)d_in[3];
    const float* v_bias = (const float*)d_in[4];
    const float* proj_w = (const float*)d_in[5];
    const float* proj_b = (const float*)d_in[6];
    const float* n1_g   = (const float*)d_in[7];
    const float* n1_b   = (const float*)d_in[8];
    const float* n2_g   = (const float*)d_in[9];
    const float* n2_b   = (const float*)d_in[10];
    const float* w1g    = (const float*)d_in[11];
    const float* b1g    = (const float*)d_in[12];
    const float* w1x    = (const float*)d_in[13];
    const float* b1x    = (const float*)d_in[14];
    const float* nm_g   = (const float*)d_in[15];
    const float* nm_b   = (const float*)d_in[16];
    const float* w2     = (const float*)d_in[17];
    const float* b2     = (const float*)d_in[18];
    float* out = (float*)d_out;

    float *y, *qkv, *o, *gate, *up, *u, *bias3;
    cudaGetSymbolAddress((void**)&y,     g_y);
    cudaGetSymbolAddress((void**)&qkv,   g_qkv);
    cudaGetSymbolAddress((void**)&o,     g_o);
    cudaGetSymbolAddress((void**)&gate,  g_gate);
    cudaGetSymbolAddress((void**)&up,    g_up);
    cudaGetSymbolAddress((void**)&u,     g_u);
    cudaGetSymbolAddress((void**)&bias3, g_bias3);

    cudaFuncSetAttribute(attn_kernel,
        cudaFuncAttributeMaxDynamicSharedMemorySize, ATTN_SMEM);

    // h (residual stream) lives in d_out
    cudaMemcpyAsync(out, x, (size_t)TTOK * CDIM * sizeof(float),
                    cudaMemcpyDeviceToDevice);

    bias3_kernel<<<(LNUM*C3 + 255)/256, 256>>>(bias3, q_bias, v_bias);

    const int MB = (TTOK + 127) / 128;                    // 99
    const int ropeThreads = TTOK * NH * (HDIM/2);

    for (int l = 0; l < LNUM; l++) {
        // attention half
        ln_kernel<CDIM><<<TTOK, 256>>>(out, n1_g + l*CDIM, n1_b + l*CDIM, y);
        gemm_kernel<<<dim3(C3/128, MB), 256>>>(
            y, qkv_w + (size_t)l*C3*CDIM, bias3 + l*C3, qkv, TTOK, C3, CDIM, 0);
        rope_kernel<<<(ropeThreads + 255)/256, 256>>>(qkv, rope);
        attn_kernel<<<BB*NH, 256, ATTN_SMEM>>>(qkv, o);
        gemm_kernel<<<dim3(CDIM/128, MB), 256>>>(
            o, proj_w + (size_t)l*CDIM*CDIM, proj_b + l*CDIM, out, TTOK, CDIM, CDIM, 1);

        // MLP half
        ln_kernel<CDIM><<<TTOK, 256>>>(out, n2_g + l*CDIM, n2_b + l*CDIM, y);
        gemm_kernel<<<dim3(HF/128, MB), 256>>>(
            y, w1g + (size_t)l*HF*CDIM, b1g + l*HF, gate, TTOK, HF, CDIM, 0);
        gemm_kernel<<<dim3(HF/128, MB), 256>>>(
            y, w1x + (size_t)l*HF*CDIM, b1x + l*HF, up, TTOK, HF, CDIM, 0);
        swiglu_ln_kernel<<<TTOK, 256>>>(gate, up, nm_g + l*HF, nm_b + l*HF, u);
        gemm_kernel<<<dim3(CDIM/128, MB), 256>>>(
            u, w2 + (size_t)l*CDIM*HF, b2 + l*CDIM, out, TTOK, CDIM, HF, 1);
    }
}

// round 4
// speedup vs baseline: 2.4213x; 2.4213x over previous
#include <cuda_runtime.h>
#include <cstdint>
#include <cstddef>

// ---------------- problem constants ----------------
#define LNUM 4
#define BB   64
#define NTOK 197
#define CDIM 768
#define NH   12
#define HDIM 64
#define HF   2048
#define C3   (3*CDIM)
#define TTOK (BB*NTOK)          // 12608
#define SCALE 0.125f
#define EPS 1e-6f

// ---------------- scratch (device globals: no allocs allowed) ----------------
__device__ float g_y   [(size_t)TTOK*CDIM];
__device__ float g_qkv [(size_t)TTOK*C3];
__device__ float g_o   [(size_t)TTOK*CDIM];
__device__ float g_gate[(size_t)TTOK*HF];
__device__ float g_up  [(size_t)TTOK*HF];
__device__ float g_u   [(size_t)TTOK*HF];
__device__ float g_bias3[LNUM*C3];

// ================= tf32 mma.sync GEMM (sm_80+ ISA, Blackwell tensor pipe) ====
// out[M,N] = A[M,K] @ W[N,K]^T + bias (+ residual)
// Block 128x128x32, 256 thr, 8 warps (2 in M x 4 in N), warp tile 64x32.
#define BM 128
#define BN 128
#define BK 32
#define SPITCH 36                         // floats; frag addr (4q+l+k) mod 32 distinct
#define BUFSZ  (BM * SPITCH)              // floats per A (or W) buffer
#define GEMM_SMEM (4 * BUFSZ * 4)         // 73728 bytes (dynamic!)

__device__ __forceinline__ uint32_t smem_addr_u32(const void* p) {
    uint32_t a;
    asm("{ .reg .u64 t; cvta.to.shared.u64 t, %1; cvt.u32.u64 %0, t; }"
        : "=r"(a) : "l"(p));
    return a;
}
__device__ __forceinline__ void cp16(uint32_t dst, const float* src, int sz) {
    asm volatile("cp.async.cg.shared.global [%0], [%1], 16, %2;"
                 :: "r"(dst), "l"(__cvta_generic_to_global(src)), "r"(sz));
}
__device__ __forceinline__ uint32_t f2tf32(float v) {
    uint32_t t;
    asm("cvt.rna.tf32.f32 %0, %1;" : "=r"(t) : "f"(v));
    return t;
}
__device__ __forceinline__ void mma_tf32(float* d, const uint32_t* a, const uint32_t* b) {
    asm volatile(
        "mma.sync.aligned.m16n8k8.row.col.f32.tf32.tf32.f32 "
        "{%0,%1,%2,%3}, {%4,%5,%6,%7}, {%8,%9}, {%0,%1,%2,%3};"
        : "+f"(d[0]), "+f"(d[1]), "+f"(d[2]), "+f"(d[3])
        : "r"(a[0]), "r"(a[1]), "r"(a[2]), "r"(a[3]), "r"(b[0]), "r"(b[1]));
}

__global__ __launch_bounds__(256, 2) void tc_gemm(
    const float* __restrict__ A, const float* __restrict__ W,
    const float* __restrict__ bias, float* __restrict__ out,
    int M, int N, int K, int residual)
{
    extern __shared__ float sm[];         // As0 | Ws0 | As1 | Ws1  (72 KB)
    float* As0 = sm;
    float* Ws0 = sm + BUFSZ;

    const int tid  = threadIdx.x;
    const int wid  = tid >> 5, lane = tid & 31;
    const int wm   = wid & 1;             // 0..1 -> rows wm*64
    const int wn   = wid >> 1;            // 0..3 -> cols wn*32
    const int qid  = lane >> 2;           // 0..7
    const int lid  = lane & 3;            // 0..3
    const int m0   = blockIdx.y * BM, n0 = blockIdx.x * BN;

    // ---- fill slots: 4 float4 per thread per tile (A and W each) ----
    uint32_t aS[4], wS[4];
    const float* aG[4]; const float* wG[4]; int aSz[4];
#pragma unroll
    for (int i = 0; i < 4; i++) {
        int g = tid + i * 256;            // 0..1023
        int r = g >> 3, s = g & 7;        // row, 16B segment
        uint32_t off = (uint32_t)(r * SPITCH + s * 4) * 4u;
        aS[i] = smem_addr_u32(As0) + off;
        wS[i] = smem_addr_u32(Ws0) + off;
        int arow = m0 + r;
        int ok = arow < M;
        aSz[i] = ok ? 16 : 0;
        aG[i]  = A + (size_t)(ok ? arow : 0) * K + s * 4;
        wG[i]  = W + (size_t)(n0 + r) * K + s * 4;
    }
    const uint32_t bufStride = (uint32_t)(2 * BUFSZ) * 4u;

    float acc[4][4][4];
#pragma unroll
    for (int mf = 0; mf < 4; mf++)
#pragma unroll
        for (int nf = 0; nf < 4; nf++)
#pragma unroll
            for (int q = 0; q < 4; q++) acc[mf][nf][q] = 0.f;

    const int NCH = K / BK;

    // prefetch chunk 0 into buffer 0
#pragma unroll
    for (int i = 0; i < 4; i++) { cp16(aS[i], aG[i], aSz[i]); cp16(wS[i], wG[i], 16); }
    asm volatile("cp.async.commit_group;");

    const float* Asw = As0 + (size_t)(wm * 64) * SPITCH;       // warp's A rows
    const float* Wsw = Ws0 + (size_t)(wn * 32) * SPITCH;       // warp's W rows

    for (int c = 0; c < NCH; c++) {
        const int buf = c & 1;
        if (c + 1 < NCH) {
            const uint32_t bo = ((c + 1) & 1) ? bufStride : 0u;
            const int koff = (c + 1) * BK;
#pragma unroll
            for (int i = 0; i < 4; i++) {
                cp16(aS[i] + bo, aG[i] + koff, aSz[i]);
                cp16(wS[i] + bo, wG[i] + koff, 16);
            }
            asm volatile("cp.async.commit_group;");
            asm volatile("cp.async.wait_group 1;" ::: "memory");
        } else {
            asm volatile("cp.async.wait_group 0;" ::: "memory");
        }
        __syncthreads();

        const float* Ab = Asw + (size_t)buf * 2 * BUFSZ;
        const float* Wb = Wsw + (size_t)buf * 2 * BUFSZ;
#pragma unroll
        for (int ks = 0; ks < 4; ks++) {
            const int k = ks * 8;
            uint32_t afr[4][4], bfr[4][2];
#pragma unroll
            for (int mf = 0; mf < 4; mf++) {
                const float* p = Ab + (size_t)(mf * 16 + qid) * SPITCH + k + lid;
                afr[mf][0] = f2tf32(p[0]);
                afr[mf][1] = f2tf32(p[8 * SPITCH]);
                afr[mf][2] = f2tf32(p[4]);
                afr[mf][3] = f2tf32(p[8 * SPITCH + 4]);
            }
#pragma unroll
            for (int nf = 0; nf < 4; nf++) {
                const float* p = Wb + (size_t)(nf * 8 + qid) * SPITCH + k + lid;
                bfr[nf][0] = f2tf32(p[0]);
                bfr[nf][1] = f2tf32(p[4]);
            }
#pragma unroll
            for (int mf = 0; mf < 4; mf++)
#pragma unroll
                for (int nf = 0; nf < 4; nf++)
                    mma_tf32(acc[mf][nf], afr[mf], bfr[nf]);
        }
        __syncthreads();
    }

    // ---- epilogue: direct float2 stores with bias (+residual) ----
#pragma unroll
    for (int mf = 0; mf < 4; mf++) {
        int r0 = m0 + wm * 64 + mf * 16 + qid;
        int r1 = r0 + 8;
#pragma unroll
        for (int nf = 0; nf < 4; nf++) {
            int col = n0 + wn * 32 + nf * 8 + 2 * lid;
            float2 bv = *(const float2*)&bias[col];
            if (r0 < M) {
                float* op = out + (size_t)r0 * N + col;
                float2 v = make_float2(acc[mf][nf][0] + bv.x, acc[mf][nf][1] + bv.y);
                if (residual) { float2 o2 = *(const float2*)op; v.x += o2.x; v.y += o2.y; }
                *(float2*)op = v;
            }
            if (r1 < M) {
                float* op = out + (size_t)r1 * N + col;
                float2 v = make_float2(acc[mf][nf][2] + bv.x, acc[mf][nf][3] + bv.y);
                if (residual) { float2 o2 = *(const float2*)op; v.x += o2.x; v.y += o2.y; }
                *(float2*)op = v;
            }
        }
    }
}

// ---------------- block reduction helper ----------------
__device__ __forceinline__ float2 block_sum2(float2 v) {
    __shared__ float2 red[8];
    int lane = threadIdx.x & 31, warp = threadIdx.x >> 5;
#pragma unroll
    for (int off = 16; off; off >>= 1) {
        v.x += __shfl_xor_sync(0xffffffffu, v.x, off);
        v.y += __shfl_xor_sync(0xffffffffu, v.y, off);
    }
    if (lane == 0) red[warp] = v;
    __syncthreads();
    if (warp == 0) {
        float2 w = (lane < 8) ? red[lane] : make_float2(0.f, 0.f);
#pragma unroll
        for (int off = 4; off; off >>= 1) {
            w.x += __shfl_xor_sync(0xffffffffu, w.x, off);
            w.y += __shfl_xor_sync(0xffffffffu, w.y, off);
        }
        if (lane == 0) red[0] = w;
    }
    __syncthreads();
    return red[0];
}

// ---------------- LayerNorm ----------------
template <int CD>
__global__ __launch_bounds__(256) void ln_kernel(
    const float* __restrict__ in, const float* __restrict__ gamma,
    const float* __restrict__ beta, float* __restrict__ out)
{
    constexpr int PER = CD / 256;
    const size_t base = (size_t)blockIdx.x * CD;
    float v[PER];
    float2 s = make_float2(0.f, 0.f);
#pragma unroll
    for (int i = 0; i < PER; i++) {
        v[i] = in[base + i*256 + threadIdx.x];
        s.x += v[i]; s.y += v[i]*v[i];
    }
    s = block_sum2(s);
    float mean = s.x * (1.f / CD);
    float var  = s.y * (1.f / CD) - mean * mean;
    float inv  = rsqrtf(var + EPS);
#pragma unroll
    for (int i = 0; i < PER; i++) {
        int c = i*256 + threadIdx.x;
        out[base + c] = (v[i] - mean) * inv * gamma[c] + beta[c];
    }
}

// ---------------- SwiGLU + inner LayerNorm ----------------
__global__ __launch_bounds__(256) void swiglu_ln_kernel(
    const float* __restrict__ G, const float* __restrict__ X,
    const float* __restrict__ gamma, const float* __restrict__ beta,
    float* __restrict__ out)
{
    const size_t base = (size_t)blockIdx.x * HF;
    float u[8];
    float2 s = make_float2(0.f, 0.f);
#pragma unroll
    for (int i = 0; i < 8; i++) {
        int c = i*256 + threadIdx.x;
        float g = G[base + c];
        float x = X[base + c];
        float uu = (g / (1.f + __expf(-g))) * x;
        u[i] = uu; s.x += uu; s.y += uu*uu;
    }
    s = block_sum2(s);
    float mean = s.x * (1.f / HF);
    float var  = s.y * (1.f / HF) - mean * mean;
    float inv  = rsqrtf(var + EPS);
#pragma unroll
    for (int i = 0; i < 8; i++) {
        int c = i*256 + threadIdx.x;
        out[base + c] = (u[i] - mean) * inv * gamma[c] + beta[c];
    }
}

// ---------------- qkv bias build ----------------
__global__ void bias3_kernel(float* __restrict__ bias3,
                             const float* __restrict__ qb,
                             const float* __restrict__ vb)
{
    int idx = blockIdx.x * blockDim.x + threadIdx.x;
    if (idx >= LNUM * C3) return;
    int l = idx / C3, j = idx % C3;
    float v = 0.f;
    if (j < CDIM)         v = qb[l*CDIM + j];
    else if (j >= 2*CDIM) v = vb[l*CDIM + (j - 2*CDIM)];
    bias3[idx] = v;
}

// ---------------- RoPE ----------------
__global__ void rope_kernel(float* __restrict__ qkv, const float* __restrict__ rope)
{
    int idx = blockIdx.x * blockDim.x + threadIdx.x;
    if (idx >= TTOK * NH * (HDIM/2)) return;
    int pair = idx & 31;
    int h    = (idx >> 5) % NH;
    int t    = idx / (32 * NH);
    int n    = t % NTOK;
    if (n == 0) return;
    const float* rp = rope + (size_t)(n - 1) * (2*HDIM);
    int d0 = pair*2, d1 = d0 + 1;
    float s0 = rp[d0],        s1 = rp[d1];
    float c0 = rp[HDIM + d0], c1 = rp[HDIM + d1];
    size_t base = (size_t)t * C3 + h * HDIM;
    {
        float x0 = qkv[base + d0], x1 = qkv[base + d1];
        qkv[base + d0] = x0*c0 - x1*s0;
        qkv[base + d1] = x1*c1 + x0*s1;
    }
    {
        size_t kb = base + CDIM;
        float x0 = qkv[kb + d0], x1 = qkv[kb + d1];
        qkv[kb + d0] = x0*c0 - x1*s0;
        qkv[kb + d1] = x1*c1 + x0*s1;
    }
}

// ---------------- attention ----------------
#define KP 65
#define ATTN_SMEM ((2*NTOK*KP + 8*HDIM + 8*NTOK) * 4)

__global__ __launch_bounds__(256) void attn_kernel(
    const float* __restrict__ qkv, float* __restrict__ o)
{
    extern __shared__ float smA[];
    float* Ks = smA;
    float* Vs = Ks + NTOK*KP;
    float* qs = Vs + NTOK*KP;
    float* ps = qs + 8*HDIM;

    int bh = blockIdx.x;
    int b = bh / NH, h = bh % NH;
    size_t t0 = (size_t)b * NTOK;
    int tid = threadIdx.x, warp = tid >> 5, lane = tid & 31;

    for (int i = tid; i < NTOK*HDIM; i += 256) {
        int r = i >> 6, d = i & 63;
        size_t src = (t0 + r) * C3 + h * HDIM + d;
        Ks[r*KP + d] = qkv[src + CDIM];
        Vs[r*KP + d] = qkv[src + 2*CDIM];
    }
    __syncthreads();

    for (int r = warp; r < NTOK; r += 8) {
        const float* qrow = &qkv[(t0 + r) * C3 + h * HDIM];
        qs[warp*HDIM + lane]      = qrow[lane]      * SCALE;
        qs[warp*HDIM + lane + 32] = qrow[lane + 32] * SCALE;
        __syncwarp();

        float sc[7];
        float mx = -1e30f;
        int nc = 0;
        for (int c = lane; c < NTOK; c += 32) {
            float s = 0.f;
#pragma unroll
            for (int d = 0; d < HDIM; d++)
                s += qs[warp*HDIM + d] * Ks[c*KP + d];
            sc[nc++] = s;
            mx = fmaxf(mx, s);
        }
#pragma unroll
        for (int off = 16; off; off >>= 1)
            mx = fmaxf(mx, __shfl_xor_sync(0xffffffffu, mx, off));
        float sum = 0.f;
        for (int i = 0; i < nc; i++) { sc[i] = __expf(sc[i] - mx); sum += sc[i]; }
#pragma unroll
        for (int off = 16; off; off >>= 1)
            sum += __shfl_xor_sync(0xffffffffu, sum, off);
        float inv = 1.f / sum;
        nc = 0;
        for (int c = lane; c < NTOK; c += 32) ps[warp*NTOK + c] = sc[nc++] * inv;
        __syncwarp();

        float a0 = 0.f, a1 = 0.f;
        for (int c = 0; c < NTOK; c++) {
            float p = ps[warp*NTOK + c];
            a0 += p * Vs[c*KP + lane];
            a1 += p * Vs[c*KP + lane + 32];
        }
        size_t dst = (t0 + r) * CDIM + h * HDIM;
        o[dst + lane]      = a0;
        o[dst + lane + 32] = a1;
        __syncwarp();
    }
}

// ---------------- host orchestration ----------------
extern "C" void kernel_launch(void* const* d_in, const int* in_sizes, int n_in,
                              void* d_out, int out_size)
{
    const float* x      = (const float*)d_in[0];
    const float* rope   = (const float*)d_in[1];
    const float* qkv_w  = (const float*)d_in[2];
    const float* q_bias = (const float*)d_in[3];
    const float* v_bias = (const float*)d_in[4];
    const float* proj_w = (const float*)d_in[5];
    const float* proj_b = (const float*)d_in[6];
    const float* n1_g   = (const float*)d_in[7];
    const float* n1_b   = (const float*)d_in[8];
    const float* n2_g   = (const float*)d_in[9];
    const float* n2_b   = (const float*)d_in[10];
    const float* w1g    = (const float*)d_in[11];
    const float* b1g    = (const float*)d_in[12];
    const float* w1x    = (const float*)d_in[13];
    const float* b1x    = (const float*)d_in[14];
    const float* nm_g   = (const float*)d_in[15];
    const float* nm_b   = (const float*)d_in[16];
    const float* w2     = (const float*)d_in[17];
    const float* b2     = (const float*)d_in[18];
    float* out = (float*)d_out;

    float *y, *qkv, *o, *gate, *up, *u, *bias3;
    cudaGetSymbolAddress((void**)&y,     g_y);
    cudaGetSymbolAddress((void**)&qkv,   g_qkv);
    cudaGetSymbolAddress((void**)&o,     g_o);
    cudaGetSymbolAddress((void**)&gate,  g_gate);
    cudaGetSymbolAddress((void**)&up,    g_up);
    cudaGetSymbolAddress((void**)&u,     g_u);
    cudaGetSymbolAddress((void**)&bias3, g_bias3);

    cudaFuncSetAttribute(attn_kernel,
        cudaFuncAttributeMaxDynamicSharedMemorySize, ATTN_SMEM);
    cudaFuncSetAttribute(tc_gemm,
        cudaFuncAttributeMaxDynamicSharedMemorySize, GEMM_SMEM);

    cudaMemcpyAsync(out, x, (size_t)TTOK * CDIM * sizeof(float),
                    cudaMemcpyDeviceToDevice);

    bias3_kernel<<<(LNUM*C3 + 255)/256, 256>>>(bias3, q_bias, v_bias);

    const int MB = (TTOK + BM - 1) / BM;     // 99
    const int ropeThreads = TTOK * NH * (HDIM/2);

    for (int l = 0; l < LNUM; l++) {
        ln_kernel<CDIM><<<TTOK, 256>>>(out, n1_g + l*CDIM, n1_b + l*CDIM, y);
        tc_gemm<<<dim3(C3/BN, MB), 256, GEMM_SMEM>>>(
            y, qkv_w + (size_t)l*C3*CDIM, bias3 + l*C3, qkv, TTOK, C3, CDIM, 0);
        rope_kernel<<<(ropeThreads + 255)/256, 256>>>(qkv, rope);
        attn_kernel<<<BB*NH, 256, ATTN_SMEM>>>(qkv, o);
        tc_gemm<<<dim3(CDIM/BN, MB), 256, GEMM_SMEM>>>(
            o, proj_w + (size_t)l*CDIM*CDIM, proj_b + l*CDIM, out, TTOK, CDIM, CDIM, 1);

        ln_kernel<CDIM><<<TTOK, 256>>>(out, n2_g + l*CDIM, n2_b + l*CDIM, y);
        tc_gemm<<<dim3(HF/BN, MB), 256, GEMM_SMEM>>>(
            y, w1g + (size_t)l*HF*CDIM, b1g + l*HF, gate, TTOK, HF, CDIM, 0);
        tc_gemm<<<dim3(HF/BN, MB), 256, GEMM_SMEM>>>(
            y, w1x + (size_t)l*HF*CDIM, b1x + l*HF, up, TTOK, HF, CDIM, 0);
        swiglu_ln_kernel<<<TTOK, 256>>>(gate, up, nm_g + l*HF, nm_b + l*HF, u);
        tc_gemm<<<dim3(CDIM/BN, MB), 256, GEMM_SMEM>>>(
            u, w2 + (size_t)l*CDIM*HF, b2 + l*CDIM, out, TTOK, CDIM, HF, 1);
    }
}

// round 5
// speedup vs baseline: 2.5069x; 1.0353x over previous
#include <cuda_runtime.h>
#include <cstdint>
#include <cstddef>

// ---------------- problem constants ----------------
#define LNUM 4
#define BB   64
#define NTOK 197
#define CDIM 768
#define NH   12
#define HDIM 64
#define HF   2048
#define C3   (3*CDIM)
#define TTOK (BB*NTOK)          // 12608
#define SCALE 0.125f
#define EPS 1e-6f

// ---------------- scratch (device globals: no allocs allowed) ----------------
__device__ float g_y   [(size_t)TTOK*CDIM];
__device__ float g_qkv [(size_t)TTOK*C3];
__device__ float g_o   [(size_t)TTOK*CDIM];
__device__ float g_gate[(size_t)TTOK*HF];
__device__ float g_up  [(size_t)TTOK*HF];
__device__ float g_u   [(size_t)TTOK*HF];
__device__ float g_bias3[LNUM*C3];

// pre-rounded (tf32) weights: qkv | proj | w1g | w1x | w2
#define WC_QKV  0
#define WC_PROJ ((size_t)LNUM*C3*CDIM)                       //  7,077,888
#define WC_W1G  (WC_PROJ + (size_t)LNUM*CDIM*CDIM)           //  9,437,184
#define WC_W1X  (WC_W1G + (size_t)LNUM*HF*CDIM)              // 15,728,640
#define WC_W2   (WC_W1X + (size_t)LNUM*HF*CDIM)              // 22,020,096
#define WC_TOT  (WC_W2 + (size_t)LNUM*CDIM*HF)               // 28,311,552
__device__ float g_wc[WC_TOT];

__device__ __forceinline__ uint32_t f2tf32(float v) {
    uint32_t t;
    asm("cvt.rna.tf32.f32 %0, %1;" : "=r"(t) : "f"(v));
    return t;
}
__device__ __forceinline__ float roundtf(float v) {
    return __uint_as_float(f2tf32(v));
}

// ---------------- weight pre-round kernel (float4 vectorized) ----------------
__global__ __launch_bounds__(256) void cvt4_kernel(
    const float* __restrict__ in, float* __restrict__ out, int n4)
{
    int i = blockIdx.x * blockDim.x + threadIdx.x;
    if (i >= n4) return;
    float4 v = ((const float4*)in)[i];
    v.x = roundtf(v.x); v.y = roundtf(v.y);
    v.z = roundtf(v.z); v.w = roundtf(v.w);
    ((float4*)out)[i] = v;
}

// ================= tf32 mma.sync GEMM (sm_80+ ISA, Blackwell tensor pipe) ====
// out[M,N] = A[M,K] @ W[N,K]^T + bias (+ residual). A and W pre-rounded to tf32.
// Block 128x128x32, 256 thr, 8 warps (2 in M x 4 in N), warp tile 64x32.
#define BM 128
#define BN 128
#define BK 32
#define SPITCH 36
#define BUFSZ  (BM * SPITCH)
#define GEMM_SMEM (4 * BUFSZ * 4)         // 73728 bytes (dynamic)

__device__ __forceinline__ uint32_t smem_addr_u32(const void* p) {
    uint32_t a;
    asm("{ .reg .u64 t; cvta.to.shared.u64 t, %1; cvt.u32.u64 %0, t; }"
        : "=r"(a) : "l"(p));
    return a;
}
__device__ __forceinline__ void cp16(uint32_t dst, const float* src, int sz) {
    asm volatile("cp.async.cg.shared.global [%0], [%1], 16, %2;"
                 :: "r"(dst), "l"(__cvta_generic_to_global(src)), "r"(sz));
}
__device__ __forceinline__ void mma_tf32(float* d, const uint32_t* a, const uint32_t* b) {
    asm volatile(
        "mma.sync.aligned.m16n8k8.row.col.f32.tf32.tf32.f32 "
        "{%0,%1,%2,%3}, {%4,%5,%6,%7}, {%8,%9}, {%0,%1,%2,%3};"
        : "+f"(d[0]), "+f"(d[1]), "+f"(d[2]), "+f"(d[3])
        : "r"(a[0]), "r"(a[1]), "r"(a[2]), "r"(a[3]), "r"(b[0]), "r"(b[1]));
}

__global__ __launch_bounds__(256, 2) void tc_gemm(
    const float* __restrict__ A, const float* __restrict__ W,
    const float* __restrict__ bias, float* __restrict__ out,
    int M, int N, int K, int residual)
{
    extern __shared__ float sm[];         // As0 | Ws0 | As1 | Ws1
    float* As0 = sm;
    float* Ws0 = sm + BUFSZ;

    const int tid  = threadIdx.x;
    const int wid  = tid >> 5, lane = tid & 31;
    const int wm   = wid & 1;
    const int wn   = wid >> 1;
    const int qid  = lane >> 2;
    const int lid  = lane & 3;
    const int m0   = blockIdx.y * BM, n0 = blockIdx.x * BN;

    uint32_t aS[4], wS[4];
    const float* aG[4]; const float* wG[4]; int aSz[4];
#pragma unroll
    for (int i = 0; i < 4; i++) {
        int g = tid + i * 256;
        int r = g >> 3, s = g & 7;
        uint32_t off = (uint32_t)(r * SPITCH + s * 4) * 4u;
        aS[i] = smem_addr_u32(As0) + off;
        wS[i] = smem_addr_u32(Ws0) + off;
        int arow = m0 + r;
        int ok = arow < M;
        aSz[i] = ok ? 16 : 0;
        aG[i]  = A + (size_t)(ok ? arow : 0) * K + s * 4;
        wG[i]  = W + (size_t)(n0 + r) * K + s * 4;
    }
    const uint32_t bufStride = (uint32_t)(2 * BUFSZ) * 4u;

    float acc[4][4][4];
#pragma unroll
    for (int mf = 0; mf < 4; mf++)
#pragma unroll
        for (int nf = 0; nf < 4; nf++)
#pragma unroll
            for (int q = 0; q < 4; q++) acc[mf][nf][q] = 0.f;

    const int NCH = K / BK;

#pragma unroll
    for (int i = 0; i < 4; i++) { cp16(aS[i], aG[i], aSz[i]); cp16(wS[i], wG[i], 16); }
    asm volatile("cp.async.commit_group;");

    const float* Asw = As0 + (size_t)(wm * 64) * SPITCH;
    const float* Wsw = Ws0 + (size_t)(wn * 32) * SPITCH;

    for (int c = 0; c < NCH; c++) {
        const int buf = c & 1;
        if (c + 1 < NCH) {
            const uint32_t bo = ((c + 1) & 1) ? bufStride : 0u;
            const int koff = (c + 1) * BK;
#pragma unroll
            for (int i = 0; i < 4; i++) {
                cp16(aS[i] + bo, aG[i] + koff, aSz[i]);
                cp16(wS[i] + bo, wG[i] + koff, 16);
            }
            asm volatile("cp.async.commit_group;");
            asm volatile("cp.async.wait_group 1;" ::: "memory");
        } else {
            asm volatile("cp.async.wait_group 0;" ::: "memory");
        }
        __syncthreads();

        const float* Ab = Asw + (size_t)buf * 2 * BUFSZ;
        const float* Wb = Wsw + (size_t)buf * 2 * BUFSZ;
#pragma unroll
        for (int ks = 0; ks < 4; ks++) {
            const int k = ks * 8;
            uint32_t afr[4][4], bfr[4][2];
#pragma unroll
            for (int mf = 0; mf < 4; mf++) {
                const uint32_t* p = (const uint32_t*)
                    (Ab + (size_t)(mf * 16 + qid) * SPITCH + k + lid);
                afr[mf][0] = p[0];
                afr[mf][1] = p[8 * SPITCH];
                afr[mf][2] = p[4];
                afr[mf][3] = p[8 * SPITCH + 4];
            }
#pragma unroll
            for (int nf = 0; nf < 4; nf++) {
                const uint32_t* p = (const uint32_t*)
                    (Wb + (size_t)(nf * 8 + qid) * SPITCH + k + lid);
                bfr[nf][0] = p[0];
                bfr[nf][1] = p[4];
            }
#pragma unroll
            for (int mf = 0; mf < 4; mf++)
#pragma unroll
                for (int nf = 0; nf < 4; nf++)
                    mma_tf32(acc[mf][nf], afr[mf], bfr[nf]);
        }
        __syncthreads();
    }

    // ---- epilogue: direct float2 stores with bias (+residual) ----
#pragma unroll
    for (int mf = 0; mf < 4; mf++) {
        int r0 = m0 + wm * 64 + mf * 16 + qid;
        int r1 = r0 + 8;
#pragma unroll
        for (int nf = 0; nf < 4; nf++) {
            int col = n0 + wn * 32 + nf * 8 + 2 * lid;
            float2 bv = *(const float2*)&bias[col];
            if (r0 < M) {
                float* op = out + (size_t)r0 * N + col;
                float2 v = make_float2(acc[mf][nf][0] + bv.x, acc[mf][nf][1] + bv.y);
                if (residual) { float2 o2 = *(const float2*)op; v.x += o2.x; v.y += o2.y; }
                *(float2*)op = v;
            }
            if (r1 < M) {
                float* op = out + (size_t)r1 * N + col;
                float2 v = make_float2(acc[mf][nf][2] + bv.x, acc[mf][nf][3] + bv.y);
                if (residual) { float2 o2 = *(const float2*)op; v.x += o2.x; v.y += o2.y; }
                *(float2*)op = v;
            }
        }
    }
}

// ---------------- block reduction helper ----------------
__device__ __forceinline__ float2 block_sum2(float2 v) {
    __shared__ float2 red[8];
    int lane = threadIdx.x & 31, warp = threadIdx.x >> 5;
#pragma unroll
    for (int off = 16; off; off >>= 1) {
        v.x += __shfl_xor_sync(0xffffffffu, v.x, off);
        v.y += __shfl_xor_sync(0xffffffffu, v.y, off);
    }
    if (lane == 0) red[warp] = v;
    __syncthreads();
    if (warp == 0) {
        float2 w = (lane < 8) ? red[lane] : make_float2(0.f, 0.f);
#pragma unroll
        for (int off = 4; off; off >>= 1) {
            w.x += __shfl_xor_sync(0xffffffffu, w.x, off);
            w.y += __shfl_xor_sync(0xffffffffu, w.y, off);
        }
        if (lane == 0) red[0] = w;
    }
    __syncthreads();
    return red[0];
}

// ---------------- LayerNorm (output pre-rounded to tf32 for GEMM A) ----------
template <int CD>
__global__ __launch_bounds__(256) void ln_kernel(
    const float* __restrict__ in, const float* __restrict__ gamma,
    const float* __restrict__ beta, float* __restrict__ out)
{
    constexpr int PER = CD / 256;
    const size_t base = (size_t)blockIdx.x * CD;
    float v[PER];
    float2 s = make_float2(0.f, 0.f);
#pragma unroll
    for (int i = 0; i < PER; i++) {
        v[i] = in[base + i*256 + threadIdx.x];
        s.x += v[i]; s.y += v[i]*v[i];
    }
    s = block_sum2(s);
    float mean = s.x * (1.f / CD);
    float var  = s.y * (1.f / CD) - mean * mean;
    float inv  = rsqrtf(var + EPS);
#pragma unroll
    for (int i = 0; i < PER; i++) {
        int c = i*256 + threadIdx.x;
        out[base + c] = roundtf((v[i] - mean) * inv * gamma[c] + beta[c]);
    }
}

// ---------------- SwiGLU + inner LayerNorm (output tf32-rounded) -------------
__global__ __launch_bounds__(256) void swiglu_ln_kernel(
    const float* __restrict__ G, const float* __restrict__ X,
    const float* __restrict__ gamma, const float* __restrict__ beta,
    float* __restrict__ out)
{
    const size_t base = (size_t)blockIdx.x * HF;
    float u[8];
    float2 s = make_float2(0.f, 0.f);
#pragma unroll
    for (int i = 0; i < 8; i++) {
        int c = i*256 + threadIdx.x;
        float g = G[base + c];
        float x = X[base + c];
        float uu = (g / (1.f + __expf(-g))) * x;
        u[i] = uu; s.x += uu; s.y += uu*uu;
    }
    s = block_sum2(s);
    float mean = s.x * (1.f / HF);
    float var  = s.y * (1.f / HF) - mean * mean;
    float inv  = rsqrtf(var + EPS);
#pragma unroll
    for (int i = 0; i < 8; i++) {
        int c = i*256 + threadIdx.x;
        out[base + c] = roundtf((u[i] - mean) * inv * gamma[c] + beta[c]);
    }
}

// ---------------- qkv bias build ----------------
__global__ void bias3_kernel(float* __restrict__ bias3,
                             const float* __restrict__ qb,
                             const float* __restrict__ vb)
{
    int idx = blockIdx.x * blockDim.x + threadIdx.x;
    if (idx >= LNUM * C3) return;
    int l = idx / C3, j = idx % C3;
    float v = 0.f;
    if (j < CDIM)         v = qb[l*CDIM + j];
    else if (j >= 2*CDIM) v = vb[l*CDIM + (j - 2*CDIM)];
    bias3[idx] = v;
}

// ---------------- RoPE ----------------
__global__ void rope_kernel(float* __restrict__ qkv, const float* __restrict__ rope)
{
    int idx = blockIdx.x * blockDim.x + threadIdx.x;
    if (idx >= TTOK * NH * (HDIM/2)) return;
    int pair = idx & 31;
    int h    = (idx >> 5) % NH;
    int t    = idx / (32 * NH);
    int n    = t % NTOK;
    if (n == 0) return;
    const float* rp = rope + (size_t)(n - 1) * (2*HDIM);
    int d0 = pair*2, d1 = d0 + 1;
    float s0 = rp[d0],        s1 = rp[d1];
    float c0 = rp[HDIM + d0], c1 = rp[HDIM + d1];
    size_t base = (size_t)t * C3 + h * HDIM;
    {
        float x0 = qkv[base + d0], x1 = qkv[base + d1];
        qkv[base + d0] = x0*c0 - x1*s0;
        qkv[base + d1] = x1*c1 + x0*s1;
    }
    {
        size_t kb = base + CDIM;
        float x0 = qkv[kb + d0], x1 = qkv[kb + d1];
        qkv[kb + d0] = x0*c0 - x1*s0;
        qkv[kb + d1] = x1*c1 + x0*s1;
    }
}

// ---------------- attention (output tf32-rounded: feeds proj GEMM) -----------
#define KP 65
#define ATTN_SMEM ((2*NTOK*KP + 8*HDIM + 8*NTOK) * 4)

__global__ __launch_bounds__(256) void attn_kernel(
    const float* __restrict__ qkv, float* __restrict__ o)
{
    extern __shared__ float smA[];
    float* Ks = smA;
    float* Vs = Ks + NTOK*KP;
    float* qs = Vs + NTOK*KP;
    float* ps = qs + 8*HDIM;

    int bh = blockIdx.x;
    int b = bh / NH, h = bh % NH;
    size_t t0 = (size_t)b * NTOK;
    int tid = threadIdx.x, warp = tid >> 5, lane = tid & 31;

    for (int i = tid; i < NTOK*HDIM; i += 256) {
        int r = i >> 6, d = i & 63;
        size_t src = (t0 + r) * C3 + h * HDIM + d;
        Ks[r*KP + d] = qkv[src + CDIM];
        Vs[r*KP + d] = qkv[src + 2*CDIM];
    }
    __syncthreads();

    for (int r = warp; r < NTOK; r += 8) {
        const float* qrow = &qkv[(t0 + r) * C3 + h * HDIM];
        qs[warp*HDIM + lane]      = qrow[lane]      * SCALE;
        qs[warp*HDIM + lane + 32] = qrow[lane + 32] * SCALE;
        __syncwarp();

        float sc[7];
        float mx = -1e30f;
        int nc = 0;
        for (int c = lane; c < NTOK; c += 32) {
            float s = 0.f;
#pragma unroll
            for (int d = 0; d < HDIM; d++)
                s += qs[warp*HDIM + d] * Ks[c*KP + d];
            sc[nc++] = s;
            mx = fmaxf(mx, s);
        }
#pragma unroll
        for (int off = 16; off; off >>= 1)
            mx = fmaxf(mx, __shfl_xor_sync(0xffffffffu, mx, off));
        float sum = 0.f;
        for (int i = 0; i < nc; i++) { sc[i] = __expf(sc[i] - mx); sum += sc[i]; }
#pragma unroll
        for (int off = 16; off; off >>= 1)
            sum += __shfl_xor_sync(0xffffffffu, sum, off);
        float inv = 1.f / sum;
        nc = 0;
        for (int c = lane; c < NTOK; c += 32) ps[warp*NTOK + c] = sc[nc++] * inv;
        __syncwarp();

        float a0 = 0.f, a1 = 0.f;
        for (int c = 0; c < NTOK; c++) {
            float p = ps[warp*NTOK + c];
            a0 += p * Vs[c*KP + lane];
            a1 += p * Vs[c*KP + lane + 32];
        }
        size_t dst = (t0 + r) * CDIM + h * HDIM;
        o[dst + lane]      = roundtf(a0);
        o[dst + lane + 32] = roundtf(a1);
        __syncwarp();
    }
}

// ---------------- host orchestration ----------------
extern "C" void kernel_launch(void* const* d_in, const int* in_sizes, int n_in,
                              void* d_out, int out_size)
{
    const float* x      = (const float*)d_in[0];
    const float* rope   = (const float*)d_in[1];
    const float* qkv_w  = (const float*)d_in[2];
    const float* q_bias = (const float*)d_in[3];
    const float* v_bias = (const float*)d_in[4];
    const float* proj_w = (const float*)d_in[5];
    const float* proj_b = (const float*)d_in[6];
    const float* n1_g   = (const float*)d_in[7];
    const float* n1_b   = (const float*)d_in[8];
    const float* n2_g   = (const float*)d_in[9];
    const float* n2_b   = (const float*)d_in[10];
    const float* w1g    = (const float*)d_in[11];
    const float* b1g    = (const float*)d_in[12];
    const float* w1x    = (const float*)d_in[13];
    const float* b1x    = (const float*)d_in[14];
    const float* nm_g   = (const float*)d_in[15];
    const float* nm_b   = (const float*)d_in[16];
    const float* w2     = (const float*)d_in[17];
    const float* b2     = (const float*)d_in[18];
    float* out = (float*)d_out;

    float *y, *qkv, *o, *gate, *up, *u, *bias3, *wc;
    cudaGetSymbolAddress((void**)&y,     g_y);
    cudaGetSymbolAddress((void**)&qkv,   g_qkv);
    cudaGetSymbolAddress((void**)&o,     g_o);
    cudaGetSymbolAddress((void**)&gate,  g_gate);
    cudaGetSymbolAddress((void**)&up,    g_up);
    cudaGetSymbolAddress((void**)&u,     g_u);
    cudaGetSymbolAddress((void**)&bias3, g_bias3);
    cudaGetSymbolAddress((void**)&wc,    g_wc);

    float* qkvw_c = wc + WC_QKV;
    float* projw_c = wc + WC_PROJ;
    float* w1g_c  = wc + WC_W1G;
    float* w1x_c  = wc + WC_W1X;
    float* w2_c   = wc + WC_W2;

    cudaFuncSetAttribute(attn_kernel,
        cudaFuncAttributeMaxDynamicSharedMemorySize, ATTN_SMEM);
    cudaFuncSetAttribute(tc_gemm,
        cudaFuncAttributeMaxDynamicSharedMemorySize, GEMM_SMEM);

    cudaMemcpyAsync(out, x, (size_t)TTOK * CDIM * sizeof(float),
                    cudaMemcpyDeviceToDevice);

    // pre-round all weights to tf32 once per launch
    {
        int n;
        n = LNUM*C3*CDIM/4;  cvt4_kernel<<<(n+255)/256, 256>>>(qkv_w,  qkvw_c,  n);
        n = LNUM*CDIM*CDIM/4;cvt4_kernel<<<(n+255)/256, 256>>>(proj_w, projw_c, n);
        n = LNUM*HF*CDIM/4;  cvt4_kernel<<<(n+255)/256, 256>>>(w1g,    w1g_c,   n);
        n = LNUM*HF*CDIM/4;  cvt4_kernel<<<(n+255)/256, 256>>>(w1x,    w1x_c,   n);
        n = LNUM*CDIM*HF/4;  cvt4_kernel<<<(n+255)/256, 256>>>(w2,     w2_c,    n);
    }

    bias3_kernel<<<(LNUM*C3 + 255)/256, 256>>>(bias3, q_bias, v_bias);

    const int MB = (TTOK + BM - 1) / BM;     // 99
    const int ropeThreads = TTOK * NH * (HDIM/2);

    for (int l = 0; l < LNUM; l++) {
        ln_kernel<CDIM><<<TTOK, 256>>>(out, n1_g + l*CDIM, n1_b + l*CDIM, y);
        tc_gemm<<<dim3(C3/BN, MB), 256, GEMM_SMEM>>>(
            y, qkvw_c + (size_t)l*C3*CDIM, bias3 + l*C3, qkv, TTOK, C3, CDIM, 0);
        rope_kernel<<<(ropeThreads + 255)/256, 256>>>(qkv, rope);
        attn_kernel<<<BB*NH, 256, ATTN_SMEM>>>(qkv, o);
        tc_gemm<<<dim3(CDIM/BN, MB), 256, GEMM_SMEM>>>(
            o, projw_c + (size_t)l*CDIM*CDIM, proj_b + l*CDIM, out, TTOK, CDIM, CDIM, 1);

        ln_kernel<CDIM><<<TTOK, 256>>>(out, n2_g + l*CDIM, n2_b + l*CDIM, y);
        tc_gemm<<<dim3(HF/BN, MB), 256, GEMM_SMEM>>>(
            y, w1g_c + (size_t)l*HF*CDIM, b1g + l*HF, gate, TTOK, HF, CDIM, 0);
        tc_gemm<<<dim3(HF/BN, MB), 256, GEMM_SMEM>>>(
            y, w1x_c + (size_t)l*HF*CDIM, b1x + l*HF, up, TTOK, HF, CDIM, 0);
        swiglu_ln_kernel<<<TTOK, 256>>>(gate, up, nm_g + l*HF, nm_b + l*HF, u);
        tc_gemm<<<dim3(CDIM/BN, MB), 256, GEMM_SMEM>>>(
            u, w2_c + (size_t)l*CDIM*HF, b2 + l*CDIM, out, TTOK, CDIM, HF, 1);
    }
}

// round 6
// speedup vs baseline: 3.5020x; 1.3969x over previous
#include <cuda_runtime.h>
#include <cuda_fp16.h>
#include <cstdint>
#include <cstddef>

// ---------------- problem constants ----------------
#define LNUM 4
#define BB   64
#define NTOK 197
#define CDIM 768
#define NH   12
#define HDIM 64
#define HF   2048
#define C3   (3*CDIM)
#define TTOK (BB*NTOK)          // 12608
#define SCALE 0.125f
#define EPS 1e-6f

// ---------------- scratch (device globals: no allocs allowed) ----------------
__device__ __half g_y   [(size_t)TTOK*CDIM];     // fp16 GEMM A operands
__device__ __half g_o   [(size_t)TTOK*CDIM];
__device__ __half g_u   [(size_t)TTOK*HF];
__device__ float  g_qkv [(size_t)TTOK*C3];       // fp32 intermediates
__device__ float  g_gate[(size_t)TTOK*HF];
__device__ float  g_up  [(size_t)TTOK*HF];
__device__ float  g_bias3[LNUM*C3];

// pre-converted fp16 weights: qkv | proj | w1g | w1x | w2
#define WC_QKV  0
#define WC_PROJ ((size_t)LNUM*C3*CDIM)
#define WC_W1G  (WC_PROJ + (size_t)LNUM*CDIM*CDIM)
#define WC_W1X  (WC_W1G + (size_t)LNUM*HF*CDIM)
#define WC_W2   (WC_W1X + (size_t)LNUM*HF*CDIM)
#define WC_TOT  (WC_W2 + (size_t)LNUM*CDIM*HF)   // 28,311,552 halves
__device__ __half g_wc[WC_TOT];

// ---------------- weight fp32 -> fp16 conversion (vectorized) ----------------
__global__ __launch_bounds__(256) void cvth_kernel(
    const float* __restrict__ in, __half* __restrict__ out, int n4)
{
    int i = blockIdx.x * blockDim.x + threadIdx.x;
    if (i >= n4) return;
    float4 v = ((const float4*)in)[i];
    __half2 h0 = __floats2half2_rn(v.x, v.y);
    __half2 h1 = __floats2half2_rn(v.z, v.w);
    ((__half2*)out)[2*i]   = h0;
    ((__half2*)out)[2*i+1] = h1;
}

// ================= fp16 mma.sync GEMM (m16n8k16, Blackwell legacy tensor pipe) ====
// out[M,N](fp32) = A[M,K](fp16) @ W[N,K](fp16)^T + bias (+ residual)
// Block 128x128x64, 256 thr, 8 warps (2 in M x 4 in N), warp tile 64x32.
#define BM 128
#define BN 128
#define BK 64
#define SPH   72                          // smem pitch in halves (64 + 8 pad)
#define BUFH  (BM * SPH)                  // halves per buffer
#define GEMM_SMEM (4 * BUFH * 2)          // 73728 bytes (dynamic)

__device__ __forceinline__ uint32_t smem_addr_u32(const void* p) {
    uint32_t a;
    asm("{ .reg .u64 t; cvta.to.shared.u64 t, %1; cvt.u32.u64 %0, t; }"
        : "=r"(a) : "l"(p));
    return a;
}
__device__ __forceinline__ void cp16(uint32_t dst, const void* src, int sz) {
    asm volatile("cp.async.cg.shared.global [%0], [%1], 16, %2;"
                 :: "r"(dst), "l"(__cvta_generic_to_global(src)), "r"(sz));
}
__device__ __forceinline__ void mma_f16(float* d, const uint32_t* a, const uint32_t* b) {
    asm volatile(
        "mma.sync.aligned.m16n8k16.row.col.f32.f16.f16.f32 "
        "{%0,%1,%2,%3}, {%4,%5,%6,%7}, {%8,%9}, {%0,%1,%2,%3};"
        : "+f"(d[0]), "+f"(d[1]), "+f"(d[2]), "+f"(d[3])
        : "r"(a[0]), "r"(a[1]), "r"(a[2]), "r"(a[3]), "r"(b[0]), "r"(b[1]));
}

__global__ __launch_bounds__(256, 2) void tc_gemm(
    const __half* __restrict__ A, const __half* __restrict__ W,
    const float* __restrict__ bias, float* __restrict__ out,
    int M, int N, int K, int residual)
{
    extern __shared__ __half sm[];        // As0 | Ws0 | As1 | Ws1
    __half* As0 = sm;
    __half* Ws0 = sm + BUFH;

    const int tid  = threadIdx.x;
    const int wid  = tid >> 5, lane = tid & 31;
    const int wm   = wid & 1;             // rows wm*64
    const int wn   = wid >> 1;            // cols wn*32
    const int qid  = lane >> 2;           // 0..7
    const int lid  = lane & 3;            // 0..3
    const int m0   = blockIdx.y * BM, n0 = blockIdx.x * BN;

    // fill slots: 4 x 16B per thread per tile (128 rows x 128B each)
    uint32_t aS[4], wS[4];
    const __half* aG[4]; const __half* wG[4]; int aSz[4];
#pragma unroll
    for (int i = 0; i < 4; i++) {
        int g = tid + i * 256;            // 0..1023
        int r = g >> 3, s = g & 7;        // row, 16B (8-half) segment
        uint32_t off = (uint32_t)(r * SPH + s * 8) * 2u;
        aS[i] = smem_addr_u32(As0) + off;
        wS[i] = smem_addr_u32(Ws0) + off;
        int arow = m0 + r;
        int ok = arow < M;
        aSz[i] = ok ? 16 : 0;
        aG[i]  = A + (size_t)(ok ? arow : 0) * K + s * 8;
        wG[i]  = W + (size_t)(n0 + r) * K + s * 8;
    }
    const uint32_t bufStride = (uint32_t)(2 * BUFH) * 2u;

    float acc[4][4][4];
#pragma unroll
    for (int mf = 0; mf < 4; mf++)
#pragma unroll
        for (int nf = 0; nf < 4; nf++)
#pragma unroll
            for (int q = 0; q < 4; q++) acc[mf][nf][q] = 0.f;

    const int NCH = K / BK;

#pragma unroll
    for (int i = 0; i < 4; i++) { cp16(aS[i], aG[i], aSz[i]); cp16(wS[i], wG[i], 16); }
    asm volatile("cp.async.commit_group;");

    const __half* Asw = As0 + (size_t)(wm * 64) * SPH;
    const __half* Wsw = Ws0 + (size_t)(wn * 32) * SPH;

    for (int c = 0; c < NCH; c++) {
        const int buf = c & 1;
        if (c + 1 < NCH) {
            const uint32_t bo = ((c + 1) & 1) ? bufStride : 0u;
            const int koff = (c + 1) * BK;
#pragma unroll
            for (int i = 0; i < 4; i++) {
                cp16(aS[i] + bo, aG[i] + koff, aSz[i]);
                cp16(wS[i] + bo, wG[i] + koff, 16);
            }
            asm volatile("cp.async.commit_group;");
            asm volatile("cp.async.wait_group 1;" ::: "memory");
        } else {
            asm volatile("cp.async.wait_group 0;" ::: "memory");
        }
        __syncthreads();

        const __half* Ab = Asw + (size_t)buf * 2 * BUFH;
        const __half* Wb = Wsw + (size_t)buf * 2 * BUFH;
#pragma unroll
        for (int ks = 0; ks < 4; ks++) {
            const int k = ks * 16;
            uint32_t afr[4][4], bfr[4][2];
#pragma unroll
            for (int mf = 0; mf < 4; mf++) {
                const __half* p = Ab + (size_t)(mf * 16 + qid) * SPH + k + 2 * lid;
                afr[mf][0] = *(const uint32_t*)p;
                afr[mf][1] = *(const uint32_t*)(p + 8 * SPH);
                afr[mf][2] = *(const uint32_t*)(p + 8);
                afr[mf][3] = *(const uint32_t*)(p + 8 * SPH + 8);
            }
#pragma unroll
            for (int nf = 0; nf < 4; nf++) {
                const __half* p = Wb + (size_t)(nf * 8 + qid) * SPH + k + 2 * lid;
                bfr[nf][0] = *(const uint32_t*)p;
                bfr[nf][1] = *(const uint32_t*)(p + 8);
            }
#pragma unroll
            for (int mf = 0; mf < 4; mf++)
#pragma unroll
                for (int nf = 0; nf < 4; nf++)
                    mma_f16(acc[mf][nf], afr[mf], bfr[nf]);
        }
        __syncthreads();
    }

    // ---- epilogue: float2 stores with bias (+residual), fp32 ----
#pragma unroll
    for (int mf = 0; mf < 4; mf++) {
        int r0 = m0 + wm * 64 + mf * 16 + qid;
        int r1 = r0 + 8;
#pragma unroll
        for (int nf = 0; nf < 4; nf++) {
            int col = n0 + wn * 32 + nf * 8 + 2 * lid;
            float2 bv = *(const float2*)&bias[col];
            if (r0 < M) {
                float* op = out + (size_t)r0 * N + col;
                float2 v = make_float2(acc[mf][nf][0] + bv.x, acc[mf][nf][1] + bv.y);
                if (residual) { float2 o2 = *(const float2*)op; v.x += o2.x; v.y += o2.y; }
                *(float2*)op = v;
            }
            if (r1 < M) {
                float* op = out + (size_t)r1 * N + col;
                float2 v = make_float2(acc[mf][nf][2] + bv.x, acc[mf][nf][3] + bv.y);
                if (residual) { float2 o2 = *(const float2*)op; v.x += o2.x; v.y += o2.y; }
                *(float2*)op = v;
            }
        }
    }
}

// ---------------- block reduction helper ----------------
__device__ __forceinline__ float2 block_sum2(float2 v) {
    __shared__ float2 red[8];
    int lane = threadIdx.x & 31, warp = threadIdx.x >> 5;
#pragma unroll
    for (int off = 16; off; off >>= 1) {
        v.x += __shfl_xor_sync(0xffffffffu, v.x, off);
        v.y += __shfl_xor_sync(0xffffffffu, v.y, off);
    }
    if (lane == 0) red[warp] = v;
    __syncthreads();
    if (warp == 0) {
        float2 w = (lane < 8) ? red[lane] : make_float2(0.f, 0.f);
#pragma unroll
        for (int off = 4; off; off >>= 1) {
            w.x += __shfl_xor_sync(0xffffffffu, w.x, off);
            w.y += __shfl_xor_sync(0xffffffffu, w.y, off);
        }
        if (lane == 0) red[0] = w;
    }
    __syncthreads();
    return red[0];
}

// ---------------- LayerNorm (fp32 in, fp16 out for GEMM A) ----------
template <int CD>
__global__ __launch_bounds__(256) void ln_kernel(
    const float* __restrict__ in, const float* __restrict__ gamma,
    const float* __restrict__ beta, __half* __restrict__ out)
{
    constexpr int PER = CD / 256;
    const size_t base = (size_t)blockIdx.x * CD;
    float v[PER];
    float2 s = make_float2(0.f, 0.f);
#pragma unroll
    for (int i = 0; i < PER; i++) {
        v[i] = in[base + i*256 + threadIdx.x];
        s.x += v[i]; s.y += v[i]*v[i];
    }
    s = block_sum2(s);
    float mean = s.x * (1.f / CD);
    float var  = s.y * (1.f / CD) - mean * mean;
    float inv  = rsqrtf(var + EPS);
#pragma unroll
    for (int i = 0; i < PER; i++) {
        int c = i*256 + threadIdx.x;
        out[base + c] = __float2half_rn((v[i] - mean) * inv * gamma[c] + beta[c]);
    }
}

// ---------------- SwiGLU + inner LayerNorm (fp32 in, fp16 out) -------------
__global__ __launch_bounds__(256) void swiglu_ln_kernel(
    const float* __restrict__ G, const float* __restrict__ X,
    const float* __restrict__ gamma, const float* __restrict__ beta,
    __half* __restrict__ out)
{
    const size_t base = (size_t)blockIdx.x * HF;
    float u[8];
    float2 s = make_float2(0.f, 0.f);
#pragma unroll
    for (int i = 0; i < 8; i++) {
        int c = i*256 + threadIdx.x;
        float g = G[base + c];
        float x = X[base + c];
        float uu = (g / (1.f + __expf(-g))) * x;
        u[i] = uu; s.x += uu; s.y += uu*uu;
    }
    s = block_sum2(s);
    float mean = s.x * (1.f / HF);
    float var  = s.y * (1.f / HF) - mean * mean;
    float inv  = rsqrtf(var + EPS);
#pragma unroll
    for (int i = 0; i < 8; i++) {
        int c = i*256 + threadIdx.x;
        out[base + c] = __float2half_rn((u[i] - mean) * inv * gamma[c] + beta[c]);
    }
}

// ---------------- qkv bias build ----------------
__global__ void bias3_kernel(float* __restrict__ bias3,
                             const float* __restrict__ qb,
                             const float* __restrict__ vb)
{
    int idx = blockIdx.x * blockDim.x + threadIdx.x;
    if (idx >= LNUM * C3) return;
    int l = idx / C3, j = idx % C3;
    float v = 0.f;
    if (j < CDIM)         v = qb[l*CDIM + j];
    else if (j >= 2*CDIM) v = vb[l*CDIM + (j - 2*CDIM)];
    bias3[idx] = v;
}

// ---------------- RoPE (fp32, in place on qkv) ----------------
__global__ void rope_kernel(float* __restrict__ qkv, const float* __restrict__ rope)
{
    int idx = blockIdx.x * blockDim.x + threadIdx.x;
    if (idx >= TTOK * NH * (HDIM/2)) return;
    int pair = idx & 31;
    int h    = (idx >> 5) % NH;
    int t    = idx / (32 * NH);
    int n    = t % NTOK;
    if (n == 0) return;
    const float* rp = rope + (size_t)(n - 1) * (2*HDIM);
    int d0 = pair*2, d1 = d0 + 1;
    float s0 = rp[d0],        s1 = rp[d1];
    float c0 = rp[HDIM + d0], c1 = rp[HDIM + d1];
    size_t base = (size_t)t * C3 + h * HDIM;
    {
        float x0 = qkv[base + d0], x1 = qkv[base + d1];
        qkv[base + d0] = x0*c0 - x1*s0;
        qkv[base + d1] = x1*c1 + x0*s1;
    }
    {
        size_t kb = base + CDIM;
        float x0 = qkv[kb + d0], x1 = qkv[kb + d1];
        qkv[kb + d0] = x0*c0 - x1*s0;
        qkv[kb + d1] = x1*c1 + x0*s1;
    }
}

// ---------------- attention (fp32 math, fp16 output feeds proj GEMM) ---------
#define KP 65
#define ATTN_SMEM ((2*NTOK*KP + 8*HDIM + 8*NTOK) * 4)

__global__ __launch_bounds__(256) void attn_kernel(
    const float* __restrict__ qkv, __half* __restrict__ o)
{
    extern __shared__ float smA[];
    float* Ks = smA;
    float* Vs = Ks + NTOK*KP;
    float* qs = Vs + NTOK*KP;
    float* ps = qs + 8*HDIM;

    int bh = blockIdx.x;
    int b = bh / NH, h = bh % NH;
    size_t t0 = (size_t)b * NTOK;
    int tid = threadIdx.x, warp = tid >> 5, lane = tid & 31;

    for (int i = tid; i < NTOK*HDIM; i += 256) {
        int r = i >> 6, d = i & 63;
        size_t src = (t0 + r) * C3 + h * HDIM + d;
        Ks[r*KP + d] = qkv[src + CDIM];
        Vs[r*KP + d] = qkv[src + 2*CDIM];
    }
    __syncthreads();

    for (int r = warp; r < NTOK; r += 8) {
        const float* qrow = &qkv[(t0 + r) * C3 + h * HDIM];
        qs[warp*HDIM + lane]      = qrow[lane]      * SCALE;
        qs[warp*HDIM + lane + 32] = qrow[lane + 32] * SCALE;
        __syncwarp();

        float sc[7];
        float mx = -1e30f;
        int nc = 0;
        for (int c = lane; c < NTOK; c += 32) {
            float s = 0.f;
#pragma unroll
            for (int d = 0; d < HDIM; d++)
                s += qs[warp*HDIM + d] * Ks[c*KP + d];
            sc[nc++] = s;
            mx = fmaxf(mx, s);
        }
#pragma unroll
        for (int off = 16; off; off >>= 1)
            mx = fmaxf(mx, __shfl_xor_sync(0xffffffffu, mx, off));
        float sum = 0.f;
        for (int i = 0; i < nc; i++) { sc[i] = __expf(sc[i] - mx); sum += sc[i]; }
#pragma unroll
        for (int off = 16; off; off >>= 1)
            sum += __shfl_xor_sync(0xffffffffu, sum, off);
        float inv = 1.f / sum;
        nc = 0;
        for (int c = lane; c < NTOK; c += 32) ps[warp*NTOK + c] = sc[nc++] * inv;
        __syncwarp();

        float a0 = 0.f, a1 = 0.f;
        for (int c = 0; c < NTOK; c++) {
            float p = ps[warp*NTOK + c];
            a0 += p * Vs[c*KP + lane];
            a1 += p * Vs[c*KP + lane + 32];
        }
        size_t dst = (t0 + r) * CDIM + h * HDIM;
        o[dst + lane]      = __float2half_rn(a0);
        o[dst + lane + 32] = __float2half_rn(a1);
        __syncwarp();
    }
}

// ---------------- host orchestration ----------------
extern "C" void kernel_launch(void* const* d_in, const int* in_sizes, int n_in,
                              void* d_out, int out_size)
{
    const float* x      = (const float*)d_in[0];
    const float* rope   = (const float*)d_in[1];
    const float* qkv_w  = (const float*)d_in[2];
    const float* q_bias = (const float*)d_in[3];
    const float* v_bias = (const float*)d_in[4];
    const float* proj_w = (const float*)d_in[5];
    const float* proj_b = (const float*)d_in[6];
    const float* n1_g   = (const float*)d_in[7];
    const float* n1_b   = (const float*)d_in[8];
    const float* n2_g   = (const float*)d_in[9];
    const float* n2_b   = (const float*)d_in[10];
    const float* w1g    = (const float*)d_in[11];
    const float* b1g    = (const float*)d_in[12];
    const float* w1x    = (const float*)d_in[13];
    const float* b1x    = (const float*)d_in[14];
    const float* nm_g   = (const float*)d_in[15];
    const float* nm_b   = (const float*)d_in[16];
    const float* w2     = (const float*)d_in[17];
    const float* b2     = (const float*)d_in[18];
    float* out = (float*)d_out;

    __half *y, *o, *u, *wc;
    float *qkv, *gate, *up, *bias3;
    cudaGetSymbolAddress((void**)&y,     g_y);
    cudaGetSymbolAddress((void**)&o,     g_o);
    cudaGetSymbolAddress((void**)&u,     g_u);
    cudaGetSymbolAddress((void**)&qkv,   g_qkv);
    cudaGetSymbolAddress((void**)&gate,  g_gate);
    cudaGetSymbolAddress((void**)&up,    g_up);
    cudaGetSymbolAddress((void**)&bias3, g_bias3);
    cudaGetSymbolAddress((void**)&wc,    g_wc);

    __half* qkvw_c = wc + WC_QKV;
    __half* projw_c = wc + WC_PROJ;
    __half* w1g_c  = wc + WC_W1G;
    __half* w1x_c  = wc + WC_W1X;
    __half* w2_c   = wc + WC_W2;

    cudaFuncSetAttribute(attn_kernel,
        cudaFuncAttributeMaxDynamicSharedMemorySize, ATTN_SMEM);
    cudaFuncSetAttribute(tc_gemm,
        cudaFuncAttributeMaxDynamicSharedMemorySize, GEMM_SMEM);

    cudaMemcpyAsync(out, x, (size_t)TTOK * CDIM * sizeof(float),
                    cudaMemcpyDeviceToDevice);

    // pre-convert all weights to fp16 once per launch
    {
        int n;
        n = LNUM*C3*CDIM/4;   cvth_kernel<<<(n+255)/256, 256>>>(qkv_w,  qkvw_c,  n);
        n = LNUM*CDIM*CDIM/4; cvth_kernel<<<(n+255)/256, 256>>>(proj_w, projw_c, n);
        n = LNUM*HF*CDIM/4;   cvth_kernel<<<(n+255)/256, 256>>>(w1g,    w1g_c,   n);
        n = LNUM*HF*CDIM/4;   cvth_kernel<<<(n+255)/256, 256>>>(w1x,    w1x_c,   n);
        n = LNUM*CDIM*HF/4;   cvth_kernel<<<(n+255)/256, 256>>>(w2,     w2_c,    n);
    }

    bias3_kernel<<<(LNUM*C3 + 255)/256, 256>>>(bias3, q_bias, v_bias);

    const int MB = (TTOK + BM - 1) / BM;     // 99
    const int ropeThreads = TTOK * NH * (HDIM/2);

    for (int l = 0; l < LNUM; l++) {
        ln_kernel<CDIM><<<TTOK, 256>>>(out, n1_g + l*CDIM, n1_b + l*CDIM, y);
        tc_gemm<<<dim3(C3/BN, MB), 256, GEMM_SMEM>>>(
            y, qkvw_c + (size_t)l*C3*CDIM, bias3 + l*C3, qkv, TTOK, C3, CDIM, 0);
        rope_kernel<<<(ropeThreads + 255)/256, 256>>>(qkv, rope);
        attn_kernel<<<BB*NH, 256, ATTN_SMEM>>>(qkv, o);
        tc_gemm<<<dim3(CDIM/BN, MB), 256, GEMM_SMEM>>>(
            o, projw_c + (size_t)l*CDIM*CDIM, proj_b + l*CDIM, out, TTOK, CDIM, CDIM, 1);

        ln_kernel<CDIM><<<TTOK, 256>>>(out, n2_g + l*CDIM, n2_b + l*CDIM, y);
        tc_gemm<<<dim3(HF/BN, MB), 256, GEMM_SMEM>>>(
            y, w1g_c + (size_t)l*HF*CDIM, b1g + l*HF, gate, TTOK, HF, CDIM, 0);
        tc_gemm<<<dim3(HF/BN, MB), 256, GEMM_SMEM>>>(
            y, w1x_c + (size_t)l*HF*CDIM, b1x + l*HF, up, TTOK, HF, CDIM, 0);
        swiglu_ln_kernel<<<TTOK, 256>>>(gate, up, nm_g + l*HF, nm_b + l*HF, u);
        tc_gemm<<<dim3(CDIM/BN, MB), 256, GEMM_SMEM>>>(
            u, w2_c + (size_t)l*CDIM*HF, b2 + l*CDIM, out, TTOK, CDIM, HF, 1);
    }
}

// round 7
// speedup vs baseline: 3.6128x; 1.0316x over previous
#include <cuda_runtime.h>
#include <cuda_fp16.h>
#include <cstdint>
#include <cstddef>

// ---------------- problem constants ----------------
#define LNUM 4
#define BB   64
#define NTOK 197
#define CDIM 768
#define NH   12
#define HDIM 64
#define HF   2048
#define C3   (3*CDIM)
#define TTOK (BB*NTOK)          // 12608
#define SCALE 0.125f
#define EPS 1e-6f

// ---------------- scratch (device globals: no allocs allowed) ----------------
__device__ __half g_y   [(size_t)TTOK*CDIM];     // fp16 GEMM A operands
__device__ __half g_o   [(size_t)TTOK*CDIM];
__device__ __half g_u   [(size_t)TTOK*HF];
__device__ float  g_qkv [(size_t)TTOK*C3];       // fp32 intermediates
__device__ float  g_gate[(size_t)TTOK*HF];
__device__ float  g_up  [(size_t)TTOK*HF];
__device__ float  g_bias3[LNUM*C3];

// pre-converted fp16 weights: qkv | proj | w1g | w1x | w2
#define WC_QKV  0
#define WC_PROJ ((size_t)LNUM*C3*CDIM)
#define WC_W1G  (WC_PROJ + (size_t)LNUM*CDIM*CDIM)
#define WC_W1X  (WC_W1G + (size_t)LNUM*HF*CDIM)
#define WC_W2   (WC_W1X + (size_t)LNUM*HF*CDIM)
#define WC_TOT  (WC_W2 + (size_t)LNUM*CDIM*HF)   // 28,311,552 halves
__device__ __half g_wc[WC_TOT];

// ---------------- weight fp32 -> fp16 conversion (vectorized) ----------------
__global__ __launch_bounds__(256) void cvth_kernel(
    const float* __restrict__ in, __half* __restrict__ out, int n4)
{
    int i = blockIdx.x * blockDim.x + threadIdx.x;
    if (i >= n4) return;
    float4 v = ((const float4*)in)[i];
    __half2 h0 = __floats2half2_rn(v.x, v.y);
    __half2 h1 = __floats2half2_rn(v.z, v.w);
    ((__half2*)out)[2*i]   = h0;
    ((__half2*)out)[2*i+1] = h1;
}

// ================= fp16 mma.sync GEMM (m16n8k16) + ldmatrix fragments ====
// out[M,N](fp32) = A[M,K](fp16) @ W[N,K](fp16)^T + bias (+ residual)
// Block 128x128x64, 256 thr, 8 warps (2 in M x 4 in N), warp tile 64x32.
#define BM 128
#define BN 128
#define BK 64
#define SPH   72                          // smem pitch in halves (64 + 8 pad)
#define BUFH  (BM * SPH)                  // halves per buffer
#define GEMM_SMEM (4 * BUFH * 2)          // 73728 bytes (dynamic)

__device__ __forceinline__ uint32_t smem_addr_u32(const void* p) {
    uint32_t a;
    asm("{ .reg .u64 t; cvta.to.shared.u64 t, %1; cvt.u32.u64 %0, t; }"
        : "=r"(a) : "l"(p));
    return a;
}
__device__ __forceinline__ void cp16(uint32_t dst, const void* src, int sz) {
    asm volatile("cp.async.cg.shared.global [%0], [%1], 16, %2;"
                 :: "r"(dst), "l"(__cvta_generic_to_global(src)), "r"(sz));
}
__device__ __forceinline__ void ldsm_x4(uint32_t* r, uint32_t addr) {
    asm volatile("ldmatrix.sync.aligned.m8n8.x4.shared.b16 {%0,%1,%2,%3}, [%4];"
        : "=r"(r[0]), "=r"(r[1]), "=r"(r[2]), "=r"(r[3]) : "r"(addr));
}
__device__ __forceinline__ void mma_f16(float* d, const uint32_t* a, const uint32_t* b) {
    asm volatile(
        "mma.sync.aligned.m16n8k16.row.col.f32.f16.f16.f32 "
        "{%0,%1,%2,%3}, {%4,%5,%6,%7}, {%8,%9}, {%0,%1,%2,%3};"
        : "+f"(d[0]), "+f"(d[1]), "+f"(d[2]), "+f"(d[3])
        : "r"(a[0]), "r"(a[1]), "r"(a[2]), "r"(a[3]), "r"(b[0]), "r"(b[1]));
}

__global__ __launch_bounds__(256, 2) void tc_gemm(
    const __half* __restrict__ A, const __half* __restrict__ W,
    const float* __restrict__ bias, float* __restrict__ out,
    int M, int N, int K, int residual)
{
    extern __shared__ __half sm[];        // As0 | Ws0 | As1 | Ws1
    __half* As0 = sm;
    __half* Ws0 = sm + BUFH;

    const int tid  = threadIdx.x;
    const int wid  = tid >> 5, lane = tid & 31;
    const int wm   = wid & 1;             // rows wm*64
    const int wn   = wid >> 1;            // cols wn*32
    const int qid  = lane >> 2;           // 0..7
    const int lid  = lane & 3;            // 0..3
    const int m0   = blockIdx.y * BM, n0 = blockIdx.x * BN;

    // fill slots: 4 x 16B per thread per tile (128 rows x 128B each)
    uint32_t aS[4], wS[4];
    const __half* aG[4]; const __half* wG[4]; int aSz[4];
#pragma unroll
    for (int i = 0; i < 4; i++) {
        int g = tid + i * 256;            // 0..1023
        int r = g >> 3, s = g & 7;        // row, 16B (8-half) segment
        uint32_t off = (uint32_t)(r * SPH + s * 8) * 2u;
        aS[i] = smem_addr_u32(As0) + off;
        wS[i] = smem_addr_u32(Ws0) + off;
        int arow = m0 + r;
        int ok = arow < M;
        aSz[i] = ok ? 16 : 0;
        aG[i]  = A + (size_t)(ok ? arow : 0) * K + s * 8;
        wG[i]  = W + (size_t)(n0 + r) * K + s * 8;
    }
    const uint32_t bufStride = (uint32_t)(2 * BUFH) * 2u;   // bytes

    // ldmatrix per-thread bases (within warp tile, buffer 0)
    // A (m16k16 x4): lanes 0-15 -> rows, lanes 16-31 -> same rows col +8
    const uint32_t a_lm = smem_addr_u32(
        As0 + (size_t)(wm * 64 + (lane & 15)) * SPH + (lane >> 4) * 8);
    // B (two n8k16 tiles per x4): row = np*16 + ((lane>>4)&1)*8 + (lane&7),
    // col offset = ((lane>>3)&1)*8
    const uint32_t b_lm = smem_addr_u32(
        Ws0 + (size_t)(wn * 32 + ((lane >> 4) & 1) * 8 + (lane & 7)) * SPH
            + ((lane >> 3) & 1) * 8);

    float acc[4][4][4];
#pragma unroll
    for (int mf = 0; mf < 4; mf++)
#pragma unroll
        for (int nf = 0; nf < 4; nf++)
#pragma unroll
            for (int q = 0; q < 4; q++) acc[mf][nf][q] = 0.f;

    const int NCH = K / BK;

#pragma unroll
    for (int i = 0; i < 4; i++) { cp16(aS[i], aG[i], aSz[i]); cp16(wS[i], wG[i], 16); }
    asm volatile("cp.async.commit_group;");

    for (int c = 0; c < NCH; c++) {
        const int buf = c & 1;
        if (c + 1 < NCH) {
            const uint32_t bo = ((c + 1) & 1) ? bufStride : 0u;
            const int koff = (c + 1) * BK;
#pragma unroll
            for (int i = 0; i < 4; i++) {
                cp16(aS[i] + bo, aG[i] + koff, aSz[i]);
                cp16(wS[i] + bo, wG[i] + koff, 16);
            }
            asm volatile("cp.async.commit_group;");
            asm volatile("cp.async.wait_group 1;" ::: "memory");
        } else {
            asm volatile("cp.async.wait_group 0;" ::: "memory");
        }
        __syncthreads();

        const uint32_t bofs = buf ? bufStride : 0u;
#pragma unroll
        for (int ks = 0; ks < 4; ks++) {
            uint32_t afr[4][4], bfr[4][2];
#pragma unroll
            for (int mf = 0; mf < 4; mf++)
                ldsm_x4(afr[mf], a_lm + bofs + (uint32_t)(mf * 16 * SPH + ks * 16) * 2u);
#pragma unroll
            for (int np = 0; np < 2; np++)
                ldsm_x4(&bfr[2*np][0], b_lm + bofs + (uint32_t)(np * 16 * SPH + ks * 16) * 2u);
#pragma unroll
            for (int mf = 0; mf < 4; mf++)
#pragma unroll
                for (int nf = 0; nf < 4; nf++)
                    mma_f16(acc[mf][nf], afr[mf], bfr[nf]);
        }
        __syncthreads();
    }

    // ---- epilogue: float2 stores with bias (+residual), fp32 ----
#pragma unroll
    for (int mf = 0; mf < 4; mf++) {
        int r0 = m0 + wm * 64 + mf * 16 + qid;
        int r1 = r0 + 8;
#pragma unroll
        for (int nf = 0; nf < 4; nf++) {
            int col = n0 + wn * 32 + nf * 8 + 2 * lid;
            float2 bv = *(const float2*)&bias[col];
            if (r0 < M) {
                float* op = out + (size_t)r0 * N + col;
                float2 v = make_float2(acc[mf][nf][0] + bv.x, acc[mf][nf][1] + bv.y);
                if (residual) { float2 o2 = *(const float2*)op; v.x += o2.x; v.y += o2.y; }
                *(float2*)op = v;
            }
            if (r1 < M) {
                float* op = out + (size_t)r1 * N + col;
                float2 v = make_float2(acc[mf][nf][2] + bv.x, acc[mf][nf][3] + bv.y);
                if (residual) { float2 o2 = *(const float2*)op; v.x += o2.x; v.y += o2.y; }
                *(float2*)op = v;
            }
        }
    }
}

// ---------------- block reduction helper ----------------
__device__ __forceinline__ float2 block_sum2(float2 v) {
    __shared__ float2 red[8];
    int lane = threadIdx.x & 31, warp = threadIdx.x >> 5;
#pragma unroll
    for (int off = 16; off; off >>= 1) {
        v.x += __shfl_xor_sync(0xffffffffu, v.x, off);
        v.y += __shfl_xor_sync(0xffffffffu, v.y, off);
    }
    if (lane == 0) red[warp] = v;
    __syncthreads();
    if (warp == 0) {
        float2 w = (lane < 8) ? red[lane] : make_float2(0.f, 0.f);
#pragma unroll
        for (int off = 4; off; off >>= 1) {
            w.x += __shfl_xor_sync(0xffffffffu, w.x, off);
            w.y += __shfl_xor_sync(0xffffffffu, w.y, off);
        }
        if (lane == 0) red[0] = w;
    }
    __syncthreads();
    return red[0];
}

// ---------------- LayerNorm (fp32 in, fp16 out for GEMM A) ----------
template <int CD>
__global__ __launch_bounds__(256) void ln_kernel(
    const float* __restrict__ in, const float* __restrict__ gamma,
    const float* __restrict__ beta, __half* __restrict__ out)
{
    constexpr int PER = CD / 256;
    const size_t base = (size_t)blockIdx.x * CD;
    float v[PER];
    float2 s = make_float2(0.f, 0.f);
#pragma unroll
    for (int i = 0; i < PER; i++) {
        v[i] = in[base + i*256 + threadIdx.x];
        s.x += v[i]; s.y += v[i]*v[i];
    }
    s = block_sum2(s);
    float mean = s.x * (1.f / CD);
    float var  = s.y * (1.f / CD) - mean * mean;
    float inv  = rsqrtf(var + EPS);
#pragma unroll
    for (int i = 0; i < PER; i++) {
        int c = i*256 + threadIdx.x;
        out[base + c] = __float2half_rn((v[i] - mean) * inv * gamma[c] + beta[c]);
    }
}

// ---------------- SwiGLU + inner LayerNorm (fp32 in, fp16 out) -------------
__global__ __launch_bounds__(256) void swiglu_ln_kernel(
    const float* __restrict__ G, const float* __restrict__ X,
    const float* __restrict__ gamma, const float* __restrict__ beta,
    __half* __restrict__ out)
{
    const size_t base = (size_t)blockIdx.x * HF;
    float u[8];
    float2 s = make_float2(0.f, 0.f);
#pragma unroll
    for (int i = 0; i < 8; i++) {
        int c = i*256 + threadIdx.x;
        float g = G[base + c];
        float x = X[base + c];
        float uu = (g / (1.f + __expf(-g))) * x;
        u[i] = uu; s.x += uu; s.y += uu*uu;
    }
    s = block_sum2(s);
    float mean = s.x * (1.f / HF);
    float var  = s.y * (1.f / HF) - mean * mean;
    float inv  = rsqrtf(var + EPS);
#pragma unroll
    for (int i = 0; i < 8; i++) {
        int c = i*256 + threadIdx.x;
        out[base + c] = __float2half_rn((u[i] - mean) * inv * gamma[c] + beta[c]);
    }
}

// ---------------- qkv bias build ----------------
__global__ void bias3_kernel(float* __restrict__ bias3,
                             const float* __restrict__ qb,
                             const float* __restrict__ vb)
{
    int idx = blockIdx.x * blockDim.x + threadIdx.x;
    if (idx >= LNUM * C3) return;
    int l = idx / C3, j = idx % C3;
    float v = 0.f;
    if (j < CDIM)         v = qb[l*CDIM + j];
    else if (j >= 2*CDIM) v = vb[l*CDIM + (j - 2*CDIM)];
    bias3[idx] = v;
}

// ---------------- RoPE (fp32, in place on qkv) ----------------
__global__ void rope_kernel(float* __restrict__ qkv, const float* __restrict__ rope)
{
    int idx = blockIdx.x * blockDim.x + threadIdx.x;
    if (idx >= TTOK * NH * (HDIM/2)) return;
    int pair = idx & 31;
    int h    = (idx >> 5) % NH;
    int t    = idx / (32 * NH);
    int n    = t % NTOK;
    if (n == 0) return;
    const float* rp = rope + (size_t)(n - 1) * (2*HDIM);
    int d0 = pair*2, d1 = d0 + 1;
    float s0 = rp[d0],        s1 = rp[d1];
    float c0 = rp[HDIM + d0], c1 = rp[HDIM + d1];
    size_t base = (size_t)t * C3 + h * HDIM;
    {
        float x0 = qkv[base + d0], x1 = qkv[base + d1];
        qkv[base + d0] = x0*c0 - x1*s0;
        qkv[base + d1] = x1*c1 + x0*s1;
    }
    {
        size_t kb = base + CDIM;
        float x0 = qkv[kb + d0], x1 = qkv[kb + d1];
        qkv[kb + d0] = x0*c0 - x1*s0;
        qkv[kb + d1] = x1*c1 + x0*s1;
    }
}

// ---------------- attention (fp32 math, fp16 output feeds proj GEMM) ---------
#define KP 65
#define ATTN_SMEM ((2*NTOK*KP + 8*HDIM + 8*NTOK) * 4)

__global__ __launch_bounds__(256) void attn_kernel(
    const float* __restrict__ qkv, __half* __restrict__ o)
{
    extern __shared__ float smA[];
    float* Ks = smA;
    float* Vs = Ks + NTOK*KP;
    float* qs = Vs + NTOK*KP;
    float* ps = qs + 8*HDIM;

    int bh = blockIdx.x;
    int b = bh / NH, h = bh % NH;
    size_t t0 = (size_t)b * NTOK;
    int tid = threadIdx.x, warp = tid >> 5, lane = tid & 31;

    for (int i = tid; i < NTOK*HDIM; i += 256) {
        int r = i >> 6, d = i & 63;
        size_t src = (t0 + r) * C3 + h * HDIM + d;
        Ks[r*KP + d] = qkv[src + CDIM];
        Vs[r*KP + d] = qkv[src + 2*CDIM];
    }
    __syncthreads();

    for (int r = warp; r < NTOK; r += 8) {
        const float* qrow = &qkv[(t0 + r) * C3 + h * HDIM];
        qs[warp*HDIM + lane]      = qrow[lane]      * SCALE;
        qs[warp*HDIM + lane + 32] = qrow[lane + 32] * SCALE;
        __syncwarp();

        float sc[7];
        float mx = -1e30f;
        int nc = 0;
        for (int c = lane; c < NTOK; c += 32) {
            float s = 0.f;
#pragma unroll
            for (int d = 0; d < HDIM; d++)
                s += qs[warp*HDIM + d] * Ks[c*KP + d];
            sc[nc++] = s;
            mx = fmaxf(mx, s);
        }
#pragma unroll
        for (int off = 16; off; off >>= 1)
            mx = fmaxf(mx, __shfl_xor_sync(0xffffffffu, mx, off));
        float sum = 0.f;
        for (int i = 0; i < nc; i++) { sc[i] = __expf(sc[i] - mx); sum += sc[i]; }
#pragma unroll
        for (int off = 16; off; off >>= 1)
            sum += __shfl_xor_sync(0xffffffffu, sum, off);
        float inv = 1.f / sum;
        nc = 0;
        for (int c = lane; c < NTOK; c += 32) ps[warp*NTOK + c] = sc[nc++] * inv;
        __syncwarp();

        float a0 = 0.f, a1 = 0.f;
        for (int c = 0; c < NTOK; c++) {
            float p = ps[warp*NTOK + c];
            a0 += p * Vs[c*KP + lane];
            a1 += p * Vs[c*KP + lane + 32];
        }
        size_t dst = (t0 + r) * CDIM + h * HDIM;
        o[dst + lane]      = __float2half_rn(a0);
        o[dst + lane + 32] = __float2half_rn(a1);
        __syncwarp();
    }
}

// ---------------- host orchestration ----------------
extern "C" void kernel_launch(void* const* d_in, const int* in_sizes, int n_in,
                              void* d_out, int out_size)
{
    const float* x      = (const float*)d_in[0];
    const float* rope   = (const float*)d_in[1];
    const float* qkv_w  = (const float*)d_in[2];
    const float* q_bias = (const float*)d_in[3];
    const float* v_bias = (const float*)d_in[4];
    const float* proj_w = (const float*)d_in[5];
    const float* proj_b = (const float*)d_in[6];
    const float* n1_g   = (const float*)d_in[7];
    const float* n1_b   = (const float*)d_in[8];
    const float* n2_g   = (const float*)d_in[9];
    const float* n2_b   = (const float*)d_in[10];
    const float* w1g    = (const float*)d_in[11];
    const float* b1g    = (const float*)d_in[12];
    const float* w1x    = (const float*)d_in[13];
    const float* b1x    = (const float*)d_in[14];
    const float* nm_g   = (const float*)d_in[15];
    const float* nm_b   = (const float*)d_in[16];
    const float* w2     = (const float*)d_in[17];
    const float* b2     = (const float*)d_in[18];
    float* out = (float*)d_out;

    __half *y, *o, *u, *wc;
    float *qkv, *gate, *up, *bias3;
    cudaGetSymbolAddress((void**)&y,     g_y);
    cudaGetSymbolAddress((void**)&o,     g_o);
    cudaGetSymbolAddress((void**)&u,     g_u);
    cudaGetSymbolAddress((void**)&qkv,   g_qkv);
    cudaGetSymbolAddress((void**)&gate,  g_gate);
    cudaGetSymbolAddress((void**)&up,    g_up);
    cudaGetSymbolAddress((void**)&bias3, g_bias3);
    cudaGetSymbolAddress((void**)&wc,    g_wc);

    __half* qkvw_c = wc + WC_QKV;
    __half* projw_c = wc + WC_PROJ;
    __half* w1g_c  = wc + WC_W1G;
    __half* w1x_c  = wc + WC_W1X;
    __half* w2_c   = wc + WC_W2;

    cudaFuncSetAttribute(attn_kernel,
        cudaFuncAttributeMaxDynamicSharedMemorySize, ATTN_SMEM);
    cudaFuncSetAttribute(tc_gemm,
        cudaFuncAttributeMaxDynamicSharedMemorySize, GEMM_SMEM);

    cudaMemcpyAsync(out, x, (size_t)TTOK * CDIM * sizeof(float),
                    cudaMemcpyDeviceToDevice);

    // pre-convert all weights to fp16 once per launch
    {
        int n;
        n = LNUM*C3*CDIM/4;   cvth_kernel<<<(n+255)/256, 256>>>(qkv_w,  qkvw_c,  n);
        n = LNUM*CDIM*CDIM/4; cvth_kernel<<<(n+255)/256, 256>>>(proj_w, projw_c, n);
        n = LNUM*HF*CDIM/4;   cvth_kernel<<<(n+255)/256, 256>>>(w1g,    w1g_c,   n);
        n = LNUM*HF*CDIM/4;   cvth_kernel<<<(n+255)/256, 256>>>(w1x,    w1x_c,   n);
        n = LNUM*CDIM*HF/4;   cvth_kernel<<<(n+255)/256, 256>>>(w2,     w2_c,    n);
    }

    bias3_kernel<<<(LNUM*C3 + 255)/256, 256>>>(bias3, q_bias, v_bias);

    const int MB = (TTOK + BM - 1) / BM;     // 99
    const int ropeThreads = TTOK * NH * (HDIM/2);

    for (int l = 0; l < LNUM; l++) {
        ln_kernel<CDIM><<<TTOK, 256>>>(out, n1_g + l*CDIM, n1_b + l*CDIM, y);
        tc_gemm<<<dim3(C3/BN, MB), 256, GEMM_SMEM>>>(
            y, qkvw_c + (size_t)l*C3*CDIM, bias3 + l*C3, qkv, TTOK, C3, CDIM, 0);
        rope_kernel<<<(ropeThreads + 255)/256, 256>>>(qkv, rope);
        attn_kernel<<<BB*NH, 256, ATTN_SMEM>>>(qkv, o);
        tc_gemm<<<dim3(CDIM/BN, MB), 256, GEMM_SMEM>>>(
            o, projw_c + (size_t)l*CDIM*CDIM, proj_b + l*CDIM, out, TTOK, CDIM, CDIM, 1);

        ln_kernel<CDIM><<<TTOK, 256>>>(out, n2_g + l*CDIM, n2_b + l*CDIM, y);
        tc_gemm<<<dim3(HF/BN, MB), 256, GEMM_SMEM>>>(
            y, w1g_c + (size_t)l*HF*CDIM, b1g + l*HF, gate, TTOK, HF, CDIM, 0);
        tc_gemm<<<dim3(HF/BN, MB), 256, GEMM_SMEM>>>(
            y, w1x_c + (size_t)l*HF*CDIM, b1x + l*HF, up, TTOK, HF, CDIM, 0);
        swiglu_ln_kernel<<<TTOK, 256>>>(gate, up, nm_g + l*HF, nm_b + l*HF, u);
        tc_gemm<<<dim3(CDIM/BN, MB), 256, GEMM_SMEM>>>(
            u, w2_c + (size_t)l*CDIM*HF, b2 + l*CDIM, out, TTOK, CDIM, HF, 1);
    }
}

// round 12
// speedup vs baseline: 6.4305x; 1.7799x over previous
#include <cuda_runtime.h>
#include <cuda_fp16.h>
#include <cstdint>
#include <cstddef>
#include <cstring>

// ---------------- problem constants ----------------
#define LNUM 4
#define BB   64
#define NTOK 197
#define CDIM 768
#define NH   12
#define HDIM 64
#define HF   2048
#define C3   (3*CDIM)
#define TTOK (BB*NTOK)          // 12608
#define SCALE 0.125f
#define EPS 1e-6f
#define NPAD 208                // 197 padded to multiple of 16

// ---------------- scratch (device globals: no allocs allowed) ----------------
__device__ __half g_y   [(size_t)TTOK*CDIM];     // fp16 GEMM A operands
__device__ __half g_o   [(size_t)TTOK*CDIM];
__device__ __half g_u   [(size_t)TTOK*HF];
__device__ float  g_qkv [(size_t)TTOK*C3];       // fp32 intermediates
__device__ float  g_gate[(size_t)TTOK*HF];
__device__ float  g_up  [(size_t)TTOK*HF];
__device__ float  g_bias3[LNUM*C3];
// packed fp16 attention operands, per (b,h): [NPAD][64], pad rows zeroed
__device__ __half g_qh[(size_t)BB*NH*NPAD*HDIM];
__device__ __half g_kh[(size_t)BB*NH*NPAD*HDIM];
__device__ __half g_vh[(size_t)BB*NH*NPAD*HDIM];

// pre-converted fp16 weights: qkv | proj | w1g | w1x | w2
#define WC_QKV  0
#define WC_PROJ ((size_t)LNUM*C3*CDIM)
#define WC_W1G  (WC_PROJ + (size_t)LNUM*CDIM*CDIM)
#define WC_W1X  (WC_W1G + (size_t)LNUM*HF*CDIM)
#define WC_W2   (WC_W1X + (size_t)LNUM*HF*CDIM)
#define WC_TOT  (WC_W2 + (size_t)LNUM*CDIM*HF)
__device__ __half g_wc[WC_TOT];

// ---------------- weight fp32 -> fp16 conversion ----------------
__global__ __launch_bounds__(256) void cvth_kernel(
    const float* __restrict__ in, __half* __restrict__ out, int n4)
{
    int i = blockIdx.x * blockDim.x + threadIdx.x;
    if (i >= n4) return;
    float4 v = ((const float4*)in)[i];
    ((__half2*)out)[2*i]   = __floats2half2_rn(v.x, v.y);
    ((__half2*)out)[2*i+1] = __floats2half2_rn(v.z, v.w);
}

// ================= shared PTX helpers =================
__device__ __forceinline__ uint32_t h2u(__half2 h) {
    uint32_t u; memcpy(&u, &h, 4); return u;
}
__device__ __forceinline__ uint32_t smem_addr_u32(const void* p) {
    uint32_t a;
    asm("{ .reg .u64 t; cvta.to.shared.u64 t, %1; cvt.u32.u64 %0, t; }"
        : "=r"(a) : "l"(p));
    return a;
}
__device__ __forceinline__ void cp16(uint32_t dst, const void* src, int sz) {
    asm volatile("cp.async.cg.shared.global [%0], [%1], 16, %2;"
                 :: "r"(dst), "l"(__cvta_generic_to_global(src)), "r"(sz));
}
__device__ __forceinline__ void ldsm_x4(uint32_t* r, uint32_t addr) {
    asm volatile("ldmatrix.sync.aligned.m8n8.x4.shared.b16 {%0,%1,%2,%3}, [%4];"
        : "=r"(r[0]), "=r"(r[1]), "=r"(r[2]), "=r"(r[3]) : "r"(addr));
}
__device__ __forceinline__ void ldsm_x4_t(uint32_t* r, uint32_t addr) {
    asm volatile("ldmatrix.sync.aligned.m8n8.x4.trans.shared.b16 {%0,%1,%2,%3}, [%4];"
        : "=r"(r[0]), "=r"(r[1]), "=r"(r[2]), "=r"(r[3]) : "r"(addr));
}
__device__ __forceinline__ void mma_f16(float* d, const uint32_t* a, const uint32_t* b) {
    asm volatile(
        "mma.sync.aligned.m16n8k16.row.col.f32.f16.f16.f32 "
        "{%0,%1,%2,%3}, {%4,%5,%6,%7}, {%8,%9}, {%0,%1,%2,%3};"
        : "+f"(d[0]), "+f"(d[1]), "+f"(d[2]), "+f"(d[3])
        : "r"(a[0]), "r"(a[1]), "r"(a[2]), "r"(a[3]), "r"(b[0]), "r"(b[1]));
}

// ================= fp16 mma.sync GEMM (m16n8k16) + ldmatrix =================
#define BM 128
#define BN 128
#define BK 64
#define SPH   72
#define BUFH  (BM * SPH)
#define GEMM_SMEM (4 * BUFH * 2)

__global__ __launch_bounds__(256, 2) void tc_gemm(
    const __half* __restrict__ A, const __half* __restrict__ W,
    const float* __restrict__ bias, float* __restrict__ out,
    int M, int N, int K, int residual)
{
    extern __shared__ __half sm[];
    __half* As0 = sm;
    __half* Ws0 = sm + BUFH;

    const int tid  = threadIdx.x;
    const int wid  = tid >> 5, lane = tid & 31;
    const int wm   = wid & 1;
    const int wn   = wid >> 1;
    const int qid  = lane >> 2;
    const int lid  = lane & 3;
    const int m0   = blockIdx.y * BM, n0 = blockIdx.x * BN;

    uint32_t aS[4], wS[4];
    const __half* aG[4]; const __half* wG[4]; int aSz[4];
#pragma unroll
    for (int i = 0; i < 4; i++) {
        int g = tid + i * 256;
        int r = g >> 3, s = g & 7;
        uint32_t off = (uint32_t)(r * SPH + s * 8) * 2u;
        aS[i] = smem_addr_u32(As0) + off;
        wS[i] = smem_addr_u32(Ws0) + off;
        int arow = m0 + r;
        int ok = arow < M;
        aSz[i] = ok ? 16 : 0;
        aG[i]  = A + (size_t)(ok ? arow : 0) * K + s * 8;
        wG[i]  = W + (size_t)(n0 + r) * K + s * 8;
    }
    const uint32_t bufStride = (uint32_t)(2 * BUFH) * 2u;

    const uint32_t a_lm = smem_addr_u32(
        As0 + (size_t)(wm * 64 + (lane & 15)) * SPH + (lane >> 4) * 8);
    const uint32_t b_lm = smem_addr_u32(
        Ws0 + (size_t)(wn * 32 + ((lane >> 4) & 1) * 8 + (lane & 7)) * SPH
            + ((lane >> 3) & 1) * 8);

    float acc[4][4][4];
#pragma unroll
    for (int mf = 0; mf < 4; mf++)
#pragma unroll
        for (int nf = 0; nf < 4; nf++)
#pragma unroll
            for (int q = 0; q < 4; q++) acc[mf][nf][q] = 0.f;

    const int NCH = K / BK;
#pragma unroll
    for (int i = 0; i < 4; i++) { cp16(aS[i], aG[i], aSz[i]); cp16(wS[i], wG[i], 16); }
    asm volatile("cp.async.commit_group;");

    for (int c = 0; c < NCH; c++) {
        const int buf = c & 1;
        if (c + 1 < NCH) {
            const uint32_t bo = ((c + 1) & 1) ? bufStride : 0u;
            const int koff = (c + 1) * BK;
#pragma unroll
            for (int i = 0; i < 4; i++) {
                cp16(aS[i] + bo, aG[i] + koff, aSz[i]);
                cp16(wS[i] + bo, wG[i] + koff, 16);
            }
            asm volatile("cp.async.commit_group;");
            asm volatile("cp.async.wait_group 1;" ::: "memory");
        } else {
            asm volatile("cp.async.wait_group 0;" ::: "memory");
        }
        __syncthreads();

        const uint32_t bofs = buf ? bufStride : 0u;
#pragma unroll
        for (int ks = 0; ks < 4; ks++) {
            uint32_t afr[4][4], bfr[4][2];
#pragma unroll
            for (int mf = 0; mf < 4; mf++)
                ldsm_x4(afr[mf], a_lm + bofs + (uint32_t)(mf * 16 * SPH + ks * 16) * 2u);
#pragma unroll
            for (int np = 0; np < 2; np++)
                ldsm_x4(&bfr[2*np][0], b_lm + bofs + (uint32_t)(np * 16 * SPH + ks * 16) * 2u);
#pragma unroll
            for (int mf = 0; mf < 4; mf++)
#pragma unroll
                for (int nf = 0; nf < 4; nf++)
                    mma_f16(acc[mf][nf], afr[mf], bfr[nf]);
        }
        __syncthreads();
    }

#pragma unroll
    for (int mf = 0; mf < 4; mf++) {
        int r0 = m0 + wm * 64 + mf * 16 + qid;
        int r1 = r0 + 8;
#pragma unroll
        for (int nf = 0; nf < 4; nf++) {
            int col = n0 + wn * 32 + nf * 8 + 2 * lid;
            float2 bv = *(const float2*)&bias[col];
            if (r0 < M) {
                float* op = out + (size_t)r0 * N + col;
                float2 v = make_float2(acc[mf][nf][0] + bv.x, acc[mf][nf][1] + bv.y);
                if (residual) { float2 o2 = *(const float2*)op; v.x += o2.x; v.y += o2.y; }
                *(float2*)op = v;
            }
            if (r1 < M) {
                float* op = out + (size_t)r1 * N + col;
                float2 v = make_float2(acc[mf][nf][2] + bv.x, acc[mf][nf][3] + bv.y);
                if (residual) { float2 o2 = *(const float2*)op; v.x += o2.x; v.y += o2.y; }
                *(float2*)op = v;
            }
        }
    }
}

// ---------------- block reduction helper ----------------
__device__ __forceinline__ float2 block_sum2(float2 v) {
    __shared__ float2 red[8];
    int lane = threadIdx.x & 31, warp = threadIdx.x >> 5;
#pragma unroll
    for (int off = 16; off; off >>= 1) {
        v.x += __shfl_xor_sync(0xffffffffu, v.x, off);
        v.y += __shfl_xor_sync(0xffffffffu, v.y, off);
    }
    if (lane == 0) red[warp] = v;
    __syncthreads();
    if (warp == 0) {
        float2 w = (lane < 8) ? red[lane] : make_float2(0.f, 0.f);
#pragma unroll
        for (int off = 4; off; off >>= 1) {
            w.x += __shfl_xor_sync(0xffffffffu, w.x, off);
            w.y += __shfl_xor_sync(0xffffffffu, w.y, off);
        }
        if (lane == 0) red[0] = w;
    }
    __syncthreads();
    return red[0];
}

// ---------------- LayerNorm (fp32 in, fp16 out) ----------
template <int CD>
__global__ __launch_bounds__(256) void ln_kernel(
    const float* __restrict__ in, const float* __restrict__ gamma,
    const float* __restrict__ beta, __half* __restrict__ out)
{
    constexpr int PER = CD / 256;
    const size_t base = (size_t)blockIdx.x * CD;
    float v[PER];
    float2 s = make_float2(0.f, 0.f);
#pragma unroll
    for (int i = 0; i < PER; i++) {
        v[i] = in[base + i*256 + threadIdx.x];
        s.x += v[i]; s.y += v[i]*v[i];
    }
    s = block_sum2(s);
    float mean = s.x * (1.f / CD);
    float var  = s.y * (1.f / CD) - mean * mean;
    float inv  = rsqrtf(var + EPS);
#pragma unroll
    for (int i = 0; i < PER; i++) {
        int c = i*256 + threadIdx.x;
        out[base + c] = __float2half_rn((v[i] - mean) * inv * gamma[c] + beta[c]);
    }
}

// ---------------- SwiGLU + inner LayerNorm ----------------
__global__ __launch_bounds__(256) void swiglu_ln_kernel(
    const float* __restrict__ G, const float* __restrict__ X,
    const float* __restrict__ gamma, const float* __restrict__ beta,
    __half* __restrict__ out)
{
    const size_t base = (size_t)blockIdx.x * HF;
    float u[8];
    float2 s = make_float2(0.f, 0.f);
#pragma unroll
    for (int i = 0; i < 8; i++) {
        int c = i*256 + threadIdx.x;
        float g = G[base + c];
        float x = X[base + c];
        float uu = (g / (1.f + __expf(-g))) * x;
        u[i] = uu; s.x += uu; s.y += uu*uu;
    }
    s = block_sum2(s);
    float mean = s.x * (1.f / HF);
    float var  = s.y * (1.f / HF) - mean * mean;
    float inv  = rsqrtf(var + EPS);
#pragma unroll
    for (int i = 0; i < 8; i++) {
        int c = i*256 + threadIdx.x;
        out[base + c] = __float2half_rn((u[i] - mean) * inv * gamma[c] + beta[c]);
    }
}

// ---------------- qkv bias build ----------------
__global__ void bias3_kernel(float* __restrict__ bias3,
                             const float* __restrict__ qb,
                             const float* __restrict__ vb)
{
    int idx = blockIdx.x * blockDim.x + threadIdx.x;
    if (idx >= LNUM * C3) return;
    int l = idx / C3, j = idx % C3;
    float v = 0.f;
    if (j < CDIM)         v = qb[l*CDIM + j];
    else if (j >= 2*CDIM) v = vb[l*CDIM + (j - 2*CDIM)];
    bias3[idx] = v;
}

// ---------------- RoPE + pack to fp16 per-head layout [bh][NPAD][64] ---------
__global__ __launch_bounds__(256) void rope_pack_kernel(
    const float* __restrict__ qkv, const float* __restrict__ rope,
    __half* __restrict__ qh, __half* __restrict__ kh, __half* __restrict__ vh)
{
    int idx = blockIdx.x * blockDim.x + threadIdx.x;
    if (idx >= BB*NH*NPAD*32) return;
    int p  = idx & 31;                       // d-pair
    int n  = (idx >> 5) % NPAD;
    int bh = idx / (32 * NPAD);
    int b  = bh / NH, h = bh % NH;
    int d0 = 2*p, d1 = d0 + 1;
    size_t ob = (size_t)bh * NPAD * HDIM + (size_t)n * HDIM + d0;
    if (n >= NTOK) {
        *(uint32_t*)&qh[ob] = 0; *(uint32_t*)&kh[ob] = 0; *(uint32_t*)&vh[ob] = 0;
        return;
    }
    size_t base = ((size_t)b * NTOK + n) * C3 + h * HDIM;
    float q0 = qkv[base + d0],          q1 = qkv[base + d1];
    float k0 = qkv[base + CDIM + d0],   k1 = qkv[base + CDIM + d1];
    float v0 = qkv[base + 2*CDIM + d0], v1 = qkv[base + 2*CDIM + d1];
    if (n > 0) {
        const float* rp = rope + (size_t)(n - 1) * (2*HDIM);
        float s0 = rp[d0], s1 = rp[d1], c0 = rp[HDIM + d0], c1 = rp[HDIM + d1];
        float tq0 = q0*c0 - q1*s0, tq1 = q1*c1 + q0*s1;
        float tk0 = k0*c0 - k1*s0, tk1 = k1*c1 + k0*s1;
        q0 = tq0; q1 = tq1; k0 = tk0; k1 = tk1;
    }
    *(__half2*)&qh[ob] = __floats2half2_rn(q0 * SCALE, q1 * SCALE);
    *(__half2*)&kh[ob] = __floats2half2_rn(k0, k1);
    *(__half2*)&vh[ob] = __floats2half2_rn(v0, v1);
}

// ---------------- tensor-core attention: one CTA per (b,h) ----------------
#define AP 72                                 // smem pitch (halves)
#define NT8 (NPAD/8)                          // 26 n8 tiles
#define ATTN_TC_SMEM (3 * NPAD * AP * 2)      // 89856 B

__global__ __launch_bounds__(256, 1) void attn_tc_kernel(
    const __half* __restrict__ qh, const __half* __restrict__ kh,
    const __half* __restrict__ vh, __half* __restrict__ o)
{
    extern __shared__ __half sm2[];
    __half* Qs = sm2;
    __half* Ks = Qs + NPAD*AP;
    __half* Vs = Ks + NPAD*AP;

    const int bh = blockIdx.x, b = bh / NH, h = bh % NH;
    const int tid = threadIdx.x, warp = tid >> 5, lane = tid & 31;
    const int qid = lane >> 2, lid = lane & 3;

    const __half* qg = qh + (size_t)bh * NPAD * HDIM;
    const __half* kg = kh + (size_t)bh * NPAD * HDIM;
    const __half* vg = vh + (size_t)bh * NPAD * HDIM;
    const uint32_t qsb = smem_addr_u32(Qs);
    const uint32_t ksb = smem_addr_u32(Ks);
    const uint32_t vsb = smem_addr_u32(Vs);

    for (int i = tid; i < NPAD * 8; i += 256) {      // 16B chunks per tensor
        int r = i >> 3, s = i & 7;
        uint32_t off = (uint32_t)(r * AP + s * 8) * 2u;
        const int gofs = r * HDIM + s * 8;
        cp16(qsb + off, qg + gofs, 16);
        cp16(ksb + off, kg + gofs, 16);
        cp16(vsb + off, vg + gofs, 16);
    }
    asm volatile("cp.async.commit_group;");
    asm volatile("cp.async.wait_group 0;" ::: "memory");
    __syncthreads();

    // per-lane ldmatrix bases
    const uint32_t a_base = qsb + (uint32_t)(((lane & 15) * AP) + (lane >> 4) * 8) * 2u;
    const uint32_t k_base = ksb + (uint32_t)((((lane >> 4) & 1) * 8 + (lane & 7)) * AP
                                             + ((lane >> 3) & 1) * 8) * 2u;
    const uint32_t v_base = vsb + (uint32_t)((((lane >> 3) & 1) * 8 + (lane & 7)) * AP
                                             + (lane >> 4) * 8) * 2u;

    for (int mt = warp; mt < NPAD/16; mt += 8) {
        const int m0 = mt * 16;
        // ---- QK^T: acc[26][4] fp32 ----
        uint32_t afr[4][4];
#pragma unroll
        for (int ks = 0; ks < 4; ks++)
            ldsm_x4(afr[ks], a_base + (uint32_t)(m0 * AP + ks * 16) * 2u);
        float acc[NT8][4];
#pragma unroll
        for (int nb = 0; nb < NT8; nb++)
#pragma unroll
            for (int q = 0; q < 4; q++) acc[nb][q] = 0.f;
#pragma unroll
        for (int ks = 0; ks < 4; ks++) {
#pragma unroll
            for (int np = 0; np < NT8/2; np++) {
                uint32_t bfr[4];
                ldsm_x4(bfr, k_base + (uint32_t)(np * 16 * AP + ks * 16) * 2u);
                mma_f16(acc[2*np],     afr[ks], bfr);
                mma_f16(acc[2*np + 1], afr[ks], bfr + 2);
            }
        }
        // ---- softmax (fp32, in registers; quad reduce) ----
        float mx0 = -1e30f, mx1 = -1e30f;
#pragma unroll
        for (int nb = 0; nb < NT8; nb++) {
#pragma unroll
            for (int e = 0; e < 2; e++) {
                int col = nb * 8 + 2 * lid + e;
                if (col < NTOK) {
                    mx0 = fmaxf(mx0, acc[nb][e]);
                    mx1 = fmaxf(mx1, acc[nb][2 + e]);
                }
            }
        }
        mx0 = fmaxf(mx0, __shfl_xor_sync(0xffffffffu, mx0, 1));
        mx0 = fmaxf(mx0, __shfl_xor_sync(0xffffffffu, mx0, 2));
        mx1 = fmaxf(mx1, __shfl_xor_sync(0xffffffffu, mx1, 1));
        mx1 = fmaxf(mx1, __shfl_xor_sync(0xffffffffu, mx1, 2));
        float sum0 = 0.f, sum1 = 0.f;
#pragma unroll
        for (int nb = 0; nb < NT8; nb++) {
#pragma unroll
            for (int e = 0; e < 2; e++) {
                int col = nb * 8 + 2 * lid + e;
                float p0 = (col < NTOK) ? __expf(acc[nb][e] - mx0) : 0.f;
                float p1 = (col < NTOK) ? __expf(acc[nb][2 + e] - mx1) : 0.f;
                acc[nb][e] = p0; acc[nb][2 + e] = p1;
                sum0 += p0; sum1 += p1;
            }
        }
        sum0 += __shfl_xor_sync(0xffffffffu, sum0, 1);
        sum0 += __shfl_xor_sync(0xffffffffu, sum0, 2);
        sum1 += __shfl_xor_sync(0xffffffffu, sum1, 1);
        sum1 += __shfl_xor_sync(0xffffffffu, sum1, 2);
        // ---- PV: P stays in registers (QK C-frag == PV A-frag layout) ----
        float oacc[8][4];
#pragma unroll
        for (int db = 0; db < 8; db++)
#pragma unroll
            for (int q = 0; q < 4; q++) oacc[db][q] = 0.f;
#pragma unroll
        for (int t = 0; t < NPAD/16; t++) {
            uint32_t pa[4];
            pa[0] = h2u(__floats2half2_rn(acc[2*t][0],   acc[2*t][1]));
            pa[1] = h2u(__floats2half2_rn(acc[2*t][2],   acc[2*t][3]));
            pa[2] = h2u(__floats2half2_rn(acc[2*t+1][0], acc[2*t+1][1]));
            pa[3] = h2u(__floats2half2_rn(acc[2*t+1][2], acc[2*t+1][3]));
#pragma unroll
            for (int dp = 0; dp < 4; dp++) {
                uint32_t bfr[4];
                ldsm_x4_t(bfr, v_base + (uint32_t)(t * 16 * AP + dp * 16) * 2u);
                mma_f16(oacc[2*dp],     pa, bfr);
                mma_f16(oacc[2*dp + 1], pa, bfr + 2);
            }
        }
        // ---- normalize + store ----
        float i0 = 1.f / sum0, i1 = 1.f / sum1;
        int r0 = m0 + qid, r1 = r0 + 8;
#pragma unroll
        for (int db = 0; db < 8; db++) {
            int col = h * HDIM + db * 8 + 2 * lid;
            if (r0 < NTOK) {
                __half2 v = __floats2half2_rn(oacc[db][0] * i0, oacc[db][1] * i0);
                *(__half2*)&o[((size_t)(b * NTOK + r0)) * CDIM + col] = v;
            }
            if (r1 < NTOK) {
                __half2 v = __floats2half2_rn(oacc[db][2] * i1, oacc[db][3] * i1);
                *(__half2*)&o[((size_t)(b * NTOK + r1)) * CDIM + col] = v;
            }
        }
    }
}

// ---------------- host orchestration ----------------
extern "C" void kernel_launch(void* const* d_in, const int* in_sizes, int n_in,
                              void* d_out, int out_size)
{
    const float* x      = (const float*)d_in[0];
    const float* rope   = (const float*)d_in[1];
    const float* qkv_w  = (const float*)d_in[2];
    const float* q_bias = (const float*)d_in[3];
    const float* v_bias = (const float*)d_in[4];
    const float* proj_w = (const float*)d_in[5];
    const float* proj_b = (const float*)d_in[6];
    const float* n1_g   = (const float*)d_in[7];
    const float* n1_b   = (const float*)d_in[8];
    const float* n2_g   = (const float*)d_in[9];
    const float* n2_b   = (const float*)d_in[10];
    const float* w1g    = (const float*)d_in[11];
    const float* b1g    = (const float*)d_in[12];
    const float* w1x    = (const float*)d_in[13];
    const float* b1x    = (const float*)d_in[14];
    const float* nm_g   = (const float*)d_in[15];
    const float* nm_b   = (const float*)d_in[16];
    const float* w2     = (const float*)d_in[17];
    const float* b2     = (const float*)d_in[18];
    float* out = (float*)d_out;

    __half *y, *o, *u, *wc, *qh, *kh, *vh;
    float *qkv, *gate, *up, *bias3;
    cudaGetSymbolAddress((void**)&y,     g_y);
    cudaGetSymbolAddress((void**)&o,     g_o);
    cudaGetSymbolAddress((void**)&u,     g_u);
    cudaGetSymbolAddress((void**)&qkv,   g_qkv);
    cudaGetSymbolAddress((void**)&gate,  g_gate);
    cudaGetSymbolAddress((void**)&up,    g_up);
    cudaGetSymbolAddress((void**)&bias3, g_bias3);
    cudaGetSymbolAddress((void**)&wc,    g_wc);
    cudaGetSymbolAddress((void**)&qh,    g_qh);
    cudaGetSymbolAddress((void**)&kh,    g_kh);
    cudaGetSymbolAddress((void**)&vh,    g_vh);

    __half* qkvw_c  = wc + WC_QKV;
    __half* projw_c = wc + WC_PROJ;
    __half* w1g_c   = wc + WC_W1G;
    __half* w1x_c   = wc + WC_W1X;
    __half* w2_c    = wc + WC_W2;

    cudaFuncSetAttribute(tc_gemm,
        cudaFuncAttributeMaxDynamicSharedMemorySize, GEMM_SMEM);
    cudaFuncSetAttribute(attn_tc_kernel,
        cudaFuncAttributeMaxDynamicSharedMemorySize, ATTN_TC_SMEM);

    cudaMemcpyAsync(out, x, (size_t)TTOK * CDIM * sizeof(float),
                    cudaMemcpyDeviceToDevice);

    {
        int n;
        n = LNUM*C3*CDIM/4;   cvth_kernel<<<(n+255)/256, 256>>>(qkv_w,  qkvw_c,  n);
        n = LNUM*CDIM*CDIM/4; cvth_kernel<<<(n+255)/256, 256>>>(proj_w, projw_c, n);
        n = LNUM*HF*CDIM/4;   cvth_kernel<<<(n+255)/256, 256>>>(w1g,    w1g_c,   n);
        n = LNUM*HF*CDIM/4;   cvth_kernel<<<(n+255)/256, 256>>>(w1x,    w1x_c,   n);
        n = LNUM*CDIM*HF/4;   cvth_kernel<<<(n+255)/256, 256>>>(w2,     w2_c,    n);
    }

    bias3_kernel<<<(LNUM*C3 + 255)/256, 256>>>(bias3, q_bias, v_bias);

    const int MB = (TTOK + BM - 1) / BM;     // 99
    const int packThreads = BB * NH * NPAD * 32;

    for (int l = 0; l < LNUM; l++) {
        ln_kernel<CDIM><<<TTOK, 256>>>(out, n1_g + l*CDIM, n1_b + l*CDIM, y);
        tc_gemm<<<dim3(C3/BN, MB), 256, GEMM_SMEM>>>(
            y, qkvw_c + (size_t)l*C3*CDIM, bias3 + l*C3, qkv, TTOK, C3, CDIM, 0);
        rope_pack_kernel<<<(packThreads + 255)/256, 256>>>(qkv, rope, qh, kh, vh);
        attn_tc_kernel<<<BB*NH, 256, ATTN_TC_SMEM>>>(qh, kh, vh, o);
        tc_gemm<<<dim3(CDIM/BN, MB), 256, GEMM_SMEM>>>(
            o, projw_c + (size_t)l*CDIM*CDIM, proj_b + l*CDIM, out, TTOK, CDIM, CDIM, 1);

        ln_kernel<CDIM><<<TTOK, 256>>>(out, n2_g + l*CDIM, n2_b + l*CDIM, y);
        tc_gemm<<<dim3(HF/BN, MB), 256, GEMM_SMEM>>>(
            y, w1g_c + (size_t)l*HF*CDIM, b1g + l*HF, gate, TTOK, HF, CDIM, 0);
        tc_gemm<<<dim3(HF/BN, MB), 256, GEMM_SMEM>>>(
            y, w1x_c + (size_t)l*HF*CDIM, b1x + l*HF, up, TTOK, HF, CDIM, 0);
        swiglu_ln_kernel<<<TTOK, 256>>>(gate, up, nm_g + l*HF, nm_b + l*HF, u);
        tc_gemm<<<dim3(CDIM/BN, MB), 256, GEMM_SMEM>>>(
            u, w2_c + (size_t)l*CDIM*HF, b2 + l*CDIM, out, TTOK, CDIM, HF, 1);
    }
}

// round 14
// speedup vs baseline: 6.5150x; 1.0131x over previous
#include <cuda_runtime.h>
#include <cuda_fp16.h>
#include <cstdint>
#include <cstddef>
#include <cstring>

// ---------------- problem constants ----------------
#define LNUM 4
#define BB   64
#define NTOK 197
#define CDIM 768
#define NH   12
#define HDIM 64
#define HF   2048
#define C3   (3*CDIM)
#define TTOK (BB*NTOK)          // 12608
#define SCALE 0.125f
#define EPS 1e-6f
#define NPAD 208                // 197 padded to multiple of 16

// ---------------- scratch (device globals: no allocs allowed) ----------------
__device__ __half g_y   [(size_t)TTOK*CDIM];     // fp16 GEMM A operands
__device__ __half g_o   [(size_t)TTOK*CDIM];
__device__ __half g_u   [(size_t)TTOK*HF];
__device__ __half g_qkv [(size_t)TTOK*C3];       // fp16 qkv (pre-rope)
__device__ __half g_gu  [(size_t)TTOK*2*HF];     // fused gate|up output
__device__ float  g_bias3[LNUM*C3];
__device__ float  g_bgu [LNUM*2*HF];
// packed fp16 attention operands, per (b,h): [NPAD][64], pad rows zeroed
__device__ __half g_qh[(size_t)BB*NH*NPAD*HDIM];
__device__ __half g_kh[(size_t)BB*NH*NPAD*HDIM];
__device__ __half g_vh[(size_t)BB*NH*NPAD*HDIM];

// pre-converted fp16 weights: qkv | proj | [w1g;w1x] packed | w2
#define WC_QKV  0
#define WC_PROJ ((size_t)LNUM*C3*CDIM)
#define WC_GU   (WC_PROJ + (size_t)LNUM*CDIM*CDIM)
#define WC_W2   (WC_GU + (size_t)LNUM*2*HF*CDIM)
#define WC_TOT  (WC_W2 + (size_t)LNUM*CDIM*HF)
__device__ __half g_wc[WC_TOT];

// ---------------- weight fp32 -> fp16 conversion ----------------
__global__ __launch_bounds__(256) void cvth_kernel(
    const float* __restrict__ in, __half* __restrict__ out, int n4)
{
    int i = blockIdx.x * blockDim.x + threadIdx.x;
    if (i >= n4) return;
    float4 v = ((const float4*)in)[i];
    ((__half2*)out)[2*i]   = __floats2half2_rn(v.x, v.y);
    ((__half2*)out)[2*i+1] = __floats2half2_rn(v.z, v.w);
}

// ================= shared PTX helpers =================
__device__ __forceinline__ uint32_t h2u(__half2 h) {
    uint32_t u; memcpy(&u, &h, 4); return u;
}
__device__ __forceinline__ uint32_t smem_addr_u32(const void* p) {
    uint32_t a;
    asm("{ .reg .u64 t; cvta.to.shared.u64 t, %1; cvt.u32.u64 %0, t; }"
        : "=r"(a) : "l"(p));
    return a;
}
__device__ __forceinline__ void cp16(uint32_t dst, const void* src, int sz) {
    asm volatile("cp.async.cg.shared.global [%0], [%1], 16, %2;"
                 :: "r"(dst), "l"(__cvta_generic_to_global(src)), "r"(sz));
}
__device__ __forceinline__ void ldsm_x4(uint32_t* r, uint32_t addr) {
    asm volatile("ldmatrix.sync.aligned.m8n8.x4.shared.b16 {%0,%1,%2,%3}, [%4];"
        : "=r"(r[0]), "=r"(r[1]), "=r"(r[2]), "=r"(r[3]) : "r"(addr));
}
__device__ __forceinline__ void ldsm_x4_t(uint32_t* r, uint32_t addr) {
    asm volatile("ldmatrix.sync.aligned.m8n8.x4.trans.shared.b16 {%0,%1,%2,%3}, [%4];"
        : "=r"(r[0]), "=r"(r[1]), "=r"(r[2]), "=r"(r[3]) : "r"(addr));
}
__device__ __forceinline__ void mma_f16(float* d, const uint32_t* a, const uint32_t* b) {
    asm volatile(
        "mma.sync.aligned.m16n8k16.row.col.f32.f16.f16.f32 "
        "{%0,%1,%2,%3}, {%4,%5,%6,%7}, {%8,%9}, {%0,%1,%2,%3};"
        : "+f"(d[0]), "+f"(d[1]), "+f"(d[2]), "+f"(d[3])
        : "r"(a[0]), "r"(a[1]), "r"(a[2]), "r"(a[3]), "r"(b[0]), "r"(b[1]));
}

// ================= fp16 mma.sync GEMM (m16n8k16) + ldmatrix =================
// OutT = float (optional residual) or __half (no residual).
#define BM 128
#define BN 128
#define BK 64
#define SPH   72
#define BUFH  (BM * SPH)
#define GEMM_SMEM (4 * BUFH * 2)

template <typename OutT>
__global__ __launch_bounds__(256, 2) void tc_gemm(
    const __half* __restrict__ A, const __half* __restrict__ W,
    const float* __restrict__ bias, OutT* __restrict__ out,
    int M, int N, int K, int residual)
{
    extern __shared__ __half sm[];
    __half* As0 = sm;
    __half* Ws0 = sm + BUFH;

    const int tid  = threadIdx.x;
    const int wid  = tid >> 5, lane = tid & 31;
    const int wm   = wid & 1;
    const int wn   = wid >> 1;
    const int qid  = lane >> 2;
    const int lid  = lane & 3;
    const int m0   = blockIdx.y * BM, n0 = blockIdx.x * BN;

    uint32_t aS[4], wS[4];
    const __half* aG[4]; const __half* wG[4]; int aSz[4];
#pragma unroll
    for (int i = 0; i < 4; i++) {
        int g = tid + i * 256;
        int r = g >> 3, s = g & 7;
        uint32_t off = (uint32_t)(r * SPH + s * 8) * 2u;
        aS[i] = smem_addr_u32(As0) + off;
        wS[i] = smem_addr_u32(Ws0) + off;
        int arow = m0 + r;
        int ok = arow < M;
        aSz[i] = ok ? 16 : 0;
        aG[i]  = A + (size_t)(ok ? arow : 0) * K + s * 8;
        wG[i]  = W + (size_t)(n0 + r) * K + s * 8;
    }
    const uint32_t bufStride = (uint32_t)(2 * BUFH) * 2u;

    const uint32_t a_lm = smem_addr_u32(
        As0 + (size_t)(wm * 64 + (lane & 15)) * SPH + (lane >> 4) * 8);
    const uint32_t b_lm = smem_addr_u32(
        Ws0 + (size_t)(wn * 32 + ((lane >> 4) & 1) * 8 + (lane & 7)) * SPH
            + ((lane >> 3) & 1) * 8);

    float acc[4][4][4];
#pragma unroll
    for (int mf = 0; mf < 4; mf++)
#pragma unroll
        for (int nf = 0; nf < 4; nf++)
#pragma unroll
            for (int q = 0; q < 4; q++) acc[mf][nf][q] = 0.f;

    const int NCH = K / BK;
#pragma unroll
    for (int i = 0; i < 4; i++) { cp16(aS[i], aG[i], aSz[i]); cp16(wS[i], wG[i], 16); }
    asm volatile("cp.async.commit_group;");

    for (int c = 0; c < NCH; c++) {
        const int buf = c & 1;
        if (c + 1 < NCH) {
            const uint32_t bo = ((c + 1) & 1) ? bufStride : 0u;
            const int koff = (c + 1) * BK;
#pragma unroll
            for (int i = 0; i < 4; i++) {
                cp16(aS[i] + bo, aG[i] + koff, aSz[i]);
                cp16(wS[i] + bo, wG[i] + koff, 16);
            }
            asm volatile("cp.async.commit_group;");
            asm volatile("cp.async.wait_group 1;" ::: "memory");
        } else {
            asm volatile("cp.async.wait_group 0;" ::: "memory");
        }
        __syncthreads();

        const uint32_t bofs = buf ? bufStride : 0u;
#pragma unroll
        for (int ks = 0; ks < 4; ks++) {
            uint32_t afr[4][4], bfr[4][2];
#pragma unroll
            for (int mf = 0; mf < 4; mf++)
                ldsm_x4(afr[mf], a_lm + bofs + (uint32_t)(mf * 16 * SPH + ks * 16) * 2u);
#pragma unroll
            for (int np = 0; np < 2; np++)
                ldsm_x4(&bfr[2*np][0], b_lm + bofs + (uint32_t)(np * 16 * SPH + ks * 16) * 2u);
#pragma unroll
            for (int mf = 0; mf < 4; mf++)
#pragma unroll
                for (int nf = 0; nf < 4; nf++)
                    mma_f16(acc[mf][nf], afr[mf], bfr[nf]);
        }
        __syncthreads();
    }

#pragma unroll
    for (int mf = 0; mf < 4; mf++) {
        int r0 = m0 + wm * 64 + mf * 16 + qid;
        int r1 = r0 + 8;
#pragma unroll
        for (int nf = 0; nf < 4; nf++) {
            int col = n0 + wn * 32 + nf * 8 + 2 * lid;
            float2 bv = *(const float2*)&bias[col];
            if constexpr (sizeof(OutT) == 4) {
                if (r0 < M) {
                    float* op = (float*)out + (size_t)r0 * N + col;
                    float2 v = make_float2(acc[mf][nf][0] + bv.x, acc[mf][nf][1] + bv.y);
                    if (residual) { float2 o2 = *(const float2*)op; v.x += o2.x; v.y += o2.y; }
                    *(float2*)op = v;
                }
                if (r1 < M) {
                    float* op = (float*)out + (size_t)r1 * N + col;
                    float2 v = make_float2(acc[mf][nf][2] + bv.x, acc[mf][nf][3] + bv.y);
                    if (residual) { float2 o2 = *(const float2*)op; v.x += o2.x; v.y += o2.y; }
                    *(float2*)op = v;
                }
            } else {
                if (r0 < M) {
                    __half2* op = (__half2*)((__half*)out + (size_t)r0 * N + col);
                    *op = __floats2half2_rn(acc[mf][nf][0] + bv.x, acc[mf][nf][1] + bv.y);
                }
                if (r1 < M) {
                    __half2* op = (__half2*)((__half*)out + (size_t)r1 * N + col);
                    *op = __floats2half2_rn(acc[mf][nf][2] + bv.x, acc[mf][nf][3] + bv.y);
                }
            }
        }
    }
}

// ---------------- block reduction helper ----------------
__device__ __forceinline__ float2 block_sum2(float2 v) {
    __shared__ float2 red[8];
    int lane = threadIdx.x & 31, warp = threadIdx.x >> 5;
#pragma unroll
    for (int off = 16; off; off >>= 1) {
        v.x += __shfl_xor_sync(0xffffffffu, v.x, off);
        v.y += __shfl_xor_sync(0xffffffffu, v.y, off);
    }
    if (lane == 0) red[warp] = v;
    __syncthreads();
    if (warp == 0) {
        float2 w = (lane < 8) ? red[lane] : make_float2(0.f, 0.f);
#pragma unroll
        for (int off = 4; off; off >>= 1) {
            w.x += __shfl_xor_sync(0xffffffffu, w.x, off);
            w.y += __shfl_xor_sync(0xffffffffu, w.y, off);
        }
        if (lane == 0) red[0] = w;
    }
    __syncthreads();
    return red[0];
}

// ---------------- LayerNorm (fp32 in, fp16 out) ----------
template <int CD>
__global__ __launch_bounds__(256) void ln_kernel(
    const float* __restrict__ in, const float* __restrict__ gamma,
    const float* __restrict__ beta, __half* __restrict__ out)
{
    constexpr int PER = CD / 256;
    const size_t base = (size_t)blockIdx.x * CD;
    float v[PER];
    float2 s = make_float2(0.f, 0.f);
#pragma unroll
    for (int i = 0; i < PER; i++) {
        v[i] = in[base + i*256 + threadIdx.x];
        s.x += v[i]; s.y += v[i]*v[i];
    }
    s = block_sum2(s);
    float mean = s.x * (1.f / CD);
    float var  = s.y * (1.f / CD) - mean * mean;
    float inv  = rsqrtf(var + EPS);
#pragma unroll
    for (int i = 0; i < PER; i++) {
        int c = i*256 + threadIdx.x;
        out[base + c] = __float2half_rn((v[i] - mean) * inv * gamma[c] + beta[c]);
    }
}

// ---------------- SwiGLU + inner LayerNorm (fp16 gu in, fp16 out) ------------
__global__ __launch_bounds__(256) void swiglu_ln_kernel(
    const __half* __restrict__ GU,
    const float* __restrict__ gamma, const float* __restrict__ beta,
    __half* __restrict__ out)
{
    const size_t base = (size_t)blockIdx.x * 2 * HF;
    float u[8];
    float2 s = make_float2(0.f, 0.f);
#pragma unroll
    for (int i = 0; i < 8; i++) {
        int c = i*256 + threadIdx.x;
        float g = __half2float(GU[base + c]);
        float x = __half2float(GU[base + HF + c]);
        float uu = (g / (1.f + __expf(-g))) * x;
        u[i] = uu; s.x += uu; s.y += uu*uu;
    }
    s = block_sum2(s);
    float mean = s.x * (1.f / HF);
    float var  = s.y * (1.f / HF) - mean * mean;
    float inv  = rsqrtf(var + EPS);
#pragma unroll
    for (int i = 0; i < 8; i++) {
        int c = i*256 + threadIdx.x;
        out[(size_t)blockIdx.x * HF + c] =
            __float2half_rn((u[i] - mean) * inv * gamma[c] + beta[c]);
    }
}

// ---------------- bias builders ----------------
__global__ void bias3_kernel(float* __restrict__ bias3,
                             const float* __restrict__ qb,
                             const float* __restrict__ vb)
{
    int idx = blockIdx.x * blockDim.x + threadIdx.x;
    if (idx >= LNUM * C3) return;
    int l = idx / C3, j = idx % C3;
    float v = 0.f;
    if (j < CDIM)         v = qb[l*CDIM + j];
    else if (j >= 2*CDIM) v = vb[l*CDIM + (j - 2*CDIM)];
    bias3[idx] = v;
}
__global__ void biasgu_kernel(float* __restrict__ bgu,
                              const float* __restrict__ bg,
                              const float* __restrict__ bx)
{
    int idx = blockIdx.x * blockDim.x + threadIdx.x;
    if (idx >= LNUM * 2 * HF) return;
    int l = idx / (2*HF), j = idx % (2*HF);
    bgu[idx] = (j < HF) ? bg[l*HF + j] : bx[l*HF + (j - HF)];
}

// ---------------- RoPE + pack (fp16 qkv in) to per-head [bh][NPAD][64] -------
__global__ __launch_bounds__(256) void rope_pack_kernel(
    const __half* __restrict__ qkv, const float* __restrict__ rope,
    __half* __restrict__ qh, __half* __restrict__ kh, __half* __restrict__ vh)
{
    int idx = blockIdx.x * blockDim.x + threadIdx.x;
    if (idx >= BB*NH*NPAD*32) return;
    int p  = idx & 31;                       // d-pair
    int n  = (idx >> 5) % NPAD;
    int bh = idx / (32 * NPAD);
    int b  = bh / NH, h = bh % NH;
    int d0 = 2*p, d1 = d0 + 1;
    size_t ob = (size_t)bh * NPAD * HDIM + (size_t)n * HDIM + d0;
    if (n >= NTOK) {
        *(uint32_t*)&qh[ob] = 0; *(uint32_t*)&kh[ob] = 0; *(uint32_t*)&vh[ob] = 0;
        return;
    }
    size_t base = ((size_t)b * NTOK + n) * C3 + h * HDIM;
    float2 qv = __half22float2(*(const __half2*)&qkv[base + d0]);
    float2 kv = __half22float2(*(const __half2*)&qkv[base + CDIM + d0]);
    float2 vv = __half22float2(*(const __half2*)&qkv[base + 2*CDIM + d0]);
    float q0 = qv.x, q1 = qv.y, k0 = kv.x, k1 = kv.y;
    if (n > 0) {
        const float* rp = rope + (size_t)(n - 1) * (2*HDIM);
        float s0 = rp[d0], s1 = rp[d1], c0 = rp[HDIM + d0], c1 = rp[HDIM + d1];
        float tq0 = q0*c0 - q1*s0, tq1 = q1*c1 + q0*s1;
        float tk0 = k0*c0 - k1*s0, tk1 = k1*c1 + k0*s1;
        q0 = tq0; q1 = tq1; k0 = tk0; k1 = tk1;
    }
    *(__half2*)&qh[ob] = __floats2half2_rn(q0 * SCALE, q1 * SCALE);
    *(__half2*)&kh[ob] = __floats2half2_rn(k0, k1);
    *(__half2*)&vh[ob] = __floats2half2_rn(vv.x, vv.y);
}

// ---------------- tensor-core attention: one CTA per (b,h) ----------------
#define AP 72                                 // smem pitch (halves)
#define NT8 (NPAD/8)                          // 26 n8 tiles
#define ATTN_TC_SMEM (3 * NPAD * AP * 2)      // 89856 B

__global__ __launch_bounds__(256, 1) void attn_tc_kernel(
    const __half* __restrict__ qh, const __half* __restrict__ kh,
    const __half* __restrict__ vh, __half* __restrict__ o)
{
    extern __shared__ __half sm2[];
    __half* Qs = sm2;
    __half* Ks = Qs + NPAD*AP;
    __half* Vs = Ks + NPAD*AP;

    const int bh = blockIdx.x, b = bh / NH, h = bh % NH;
    const int tid = threadIdx.x, warp = tid >> 5, lane = tid & 31;
    const int qid = lane >> 2, lid = lane & 3;

    const __half* qg = qh + (size_t)bh * NPAD * HDIM;
    const __half* kg = kh + (size_t)bh * NPAD * HDIM;
    const __half* vg = vh + (size_t)bh * NPAD * HDIM;
    const uint32_t qsb = smem_addr_u32(Qs);
    const uint32_t ksb = smem_addr_u32(Ks);
    const uint32_t vsb = smem_addr_u32(Vs);

    for (int i = tid; i < NPAD * 8; i += 256) {
        int r = i >> 3, s = i & 7;
        uint32_t off = (uint32_t)(r * AP + s * 8) * 2u;
        const int gofs = r * HDIM + s * 8;
        cp16(qsb + off, qg + gofs, 16);
        cp16(ksb + off, kg + gofs, 16);
        cp16(vsb + off, vg + gofs, 16);
    }
    asm volatile("cp.async.commit_group;");
    asm volatile("cp.async.wait_group 0;" ::: "memory");
    __syncthreads();

    const uint32_t a_base = qsb + (uint32_t)(((lane & 15) * AP) + (lane >> 4) * 8) * 2u;
    const uint32_t k_base = ksb + (uint32_t)((((lane >> 4) & 1) * 8 + (lane & 7)) * AP
                                             + ((lane >> 3) & 1) * 8) * 2u;
    const uint32_t v_base = vsb + (uint32_t)((((lane >> 3) & 1) * 8 + (lane & 7)) * AP
                                             + (lane >> 4) * 8) * 2u;

    for (int mt = warp; mt < NPAD/16; mt += 8) {
        const int m0 = mt * 16;
        uint32_t afr[4][4];
#pragma unroll
        for (int ks = 0; ks < 4; ks++)
            ldsm_x4(afr[ks], a_base + (uint32_t)(m0 * AP + ks * 16) * 2u);
        float acc[NT8][4];
#pragma unroll
        for (int nb = 0; nb < NT8; nb++)
#pragma unroll
            for (int q = 0; q < 4; q++) acc[nb][q] = 0.f;
#pragma unroll
        for (int ks = 0; ks < 4; ks++) {
#pragma unroll
            for (int np = 0; np < NT8/2; np++) {
                uint32_t bfr[4];
                ldsm_x4(bfr, k_base + (uint32_t)(np * 16 * AP + ks * 16) * 2u);
                mma_f16(acc[2*np],     afr[ks], bfr);
                mma_f16(acc[2*np + 1], afr[ks], bfr + 2);
            }
        }
        float mx0 = -1e30f, mx1 = -1e30f;
#pragma unroll
        for (int nb = 0; nb < NT8; nb++) {
#pragma unroll
            for (int e = 0; e < 2; e++) {
                int col = nb * 8 + 2 * lid + e;
                if (col < NTOK) {
                    mx0 = fmaxf(mx0, acc[nb][e]);
                    mx1 = fmaxf(mx1, acc[nb][2 + e]);
                }
            }
        }
        mx0 = fmaxf(mx0, __shfl_xor_sync(0xffffffffu, mx0, 1));
        mx0 = fmaxf(mx0, __shfl_xor_sync(0xffffffffu, mx0, 2));
        mx1 = fmaxf(mx1, __shfl_xor_sync(0xffffffffu, mx1, 1));
        mx1 = fmaxf(mx1, __shfl_xor_sync(0xffffffffu, mx1, 2));
        float sum0 = 0.f, sum1 = 0.f;
#pragma unroll
        for (int nb = 0; nb < NT8; nb++) {
#pragma unroll
            for (int e = 0; e < 2; e++) {
                int col = nb * 8 + 2 * lid + e;
                float p0 = (col < NTOK) ? __expf(acc[nb][e] - mx0) : 0.f;
                float p1 = (col < NTOK) ? __expf(acc[nb][2 + e] - mx1) : 0.f;
                acc[nb][e] = p0; acc[nb][2 + e] = p1;
                sum0 += p0; sum1 += p1;
            }
        }
        sum0 += __shfl_xor_sync(0xffffffffu, sum0, 1);
        sum0 += __shfl_xor_sync(0xffffffffu, sum0, 2);
        sum1 += __shfl_xor_sync(0xffffffffu, sum1, 1);
        sum1 += __shfl_xor_sync(0xffffffffu, sum1, 2);
        float oacc[8][4];
#pragma unroll
        for (int db = 0; db < 8; db++)
#pragma unroll
            for (int q = 0; q < 4; q++) oacc[db][q] = 0.f;
#pragma unroll
        for (int t = 0; t < NPAD/16; t++) {
            uint32_t pa[4];
            pa[0] = h2u(__floats2half2_rn(acc[2*t][0],   acc[2*t][1]));
            pa[1] = h2u(__floats2half2_rn(acc[2*t][2],   acc[2*t][3]));
            pa[2] = h2u(__floats2half2_rn(acc[2*t+1][0], acc[2*t+1][1]));
            pa[3] = h2u(__floats2half2_rn(acc[2*t+1][2], acc[2*t+1][3]));
#pragma unroll
            for (int dp = 0; dp < 4; dp++) {
                uint32_t bfr[4];
                ldsm_x4_t(bfr, v_base + (uint32_t)(t * 16 * AP + dp * 16) * 2u);
                mma_f16(oacc[2*dp],     pa, bfr);
                mma_f16(oacc[2*dp + 1], pa, bfr + 2);
            }
        }
        float i0 = 1.f / sum0, i1 = 1.f / sum1;
        int r0 = m0 + qid, r1 = r0 + 8;
#pragma unroll
        for (int db = 0; db < 8; db++) {
            int col = h * HDIM + db * 8 + 2 * lid;
            if (r0 < NTOK) {
                __half2 v = __floats2half2_rn(oacc[db][0] * i0, oacc[db][1] * i0);
                *(__half2*)&o[((size_t)(b * NTOK + r0)) * CDIM + col] = v;
            }
            if (r1 < NTOK) {
                __half2 v = __floats2half2_rn(oacc[db][2] * i1, oacc[db][3] * i1);
                *(__half2*)&o[((size_t)(b * NTOK + r1)) * CDIM + col] = v;
            }
        }
    }
}

// ---------------- host orchestration ----------------
extern "C" void kernel_launch(void* const* d_in, const int* in_sizes, int n_in,
                              void* d_out, int out_size)
{
    const float* x      = (const float*)d_in[0];
    const float* rope   = (const float*)d_in[1];
    const float* qkv_w  = (const float*)d_in[2];
    const float* q_bias = (const float*)d_in[3];
    const float* v_bias = (const float*)d_in[4];
    const float* proj_w = (const float*)d_in[5];
    const float* proj_b = (const float*)d_in[6];
    const float* n1_g   = (const float*)d_in[7];
    const float* n1_b   = (const float*)d_in[8];
    const float* n2_g   = (const float*)d_in[9];
    const float* n2_b   = (const float*)d_in[10];
    const float* w1g    = (const float*)d_in[11];
    const float* b1g    = (const float*)d_in[12];
    const float* w1x    = (const float*)d_in[13];
    const float* b1x    = (const float*)d_in[14];
    const float* nm_g   = (const float*)d_in[15];
    const float* nm_b   = (const float*)d_in[16];
    const float* w2     = (const float*)d_in[17];
    const float* b2     = (const float*)d_in[18];
    float* out = (float*)d_out;

    __half *y, *o, *u, *qkv, *gu, *wc, *qh, *kh, *vh;
    float *bias3, *bgu;
    cudaGetSymbolAddress((void**)&y,     g_y);
    cudaGetSymbolAddress((void**)&o,     g_o);
    cudaGetSymbolAddress((void**)&u,     g_u);
    cudaGetSymbolAddress((void**)&qkv,   g_qkv);
    cudaGetSymbolAddress((void**)&gu,    g_gu);
    cudaGetSymbolAddress((void**)&bias3, g_bias3);
    cudaGetSymbolAddress((void**)&bgu,   g_bgu);
    cudaGetSymbolAddress((void**)&wc,    g_wc);
    cudaGetSymbolAddress((void**)&qh,    g_qh);
    cudaGetSymbolAddress((void**)&kh,    g_kh);
    cudaGetSymbolAddress((void**)&vh,    g_vh);

    __half* qkvw_c  = wc + WC_QKV;
    __half* projw_c = wc + WC_PROJ;
    __half* guw_c   = wc + WC_GU;
    __half* w2_c    = wc + WC_W2;

    cudaFuncSetAttribute(tc_gemm<float>,
        cudaFuncAttributeMaxDynamicSharedMemorySize, GEMM_SMEM);
    cudaFuncSetAttribute(tc_gemm<__half>,
        cudaFuncAttributeMaxDynamicSharedMemorySize, GEMM_SMEM);
    cudaFuncSetAttribute(attn_tc_kernel,
        cudaFuncAttributeMaxDynamicSharedMemorySize, ATTN_TC_SMEM);

    cudaMemcpyAsync(out, x, (size_t)TTOK * CDIM * sizeof(float),
                    cudaMemcpyDeviceToDevice);

    // pre-convert weights to fp16; pack [w1g;w1x] per layer for fused GEMM
    {
        int n;
        n = LNUM*C3*CDIM/4;   cvth_kernel<<<(n+255)/256, 256>>>(qkv_w,  qkvw_c,  n);
        n = LNUM*CDIM*CDIM/4; cvth_kernel<<<(n+255)/256, 256>>>(proj_w, projw_c, n);
        n = HF*CDIM/4;
        for (int l = 0; l < LNUM; l++) {
            cvth_kernel<<<(n+255)/256, 256>>>(
                w1g + (size_t)l*HF*CDIM, guw_c + (size_t)l*2*HF*CDIM, n);
            cvth_kernel<<<(n+255)/256, 256>>>(
                w1x + (size_t)l*HF*CDIM, guw_c + (size_t)l*2*HF*CDIM + (size_t)HF*CDIM, n);
        }
        n = LNUM*CDIM*HF/4;   cvth_kernel<<<(n+255)/256, 256>>>(w2, w2_c, n);
    }

    bias3_kernel<<<(LNUM*C3 + 255)/256, 256>>>(bias3, q_bias, v_bias);
    biasgu_kernel<<<(LNUM*2*HF + 255)/256, 256>>>(bgu, b1g, b1x);

    const int MB = (TTOK + BM - 1) / BM;     // 99
    const int packThreads = BB * NH * NPAD * 32;

    for (int l = 0; l < LNUM; l++) {
        ln_kernel<CDIM><<<TTOK, 256>>>(out, n1_g + l*CDIM, n1_b + l*CDIM, y);
        tc_gemm<__half><<<dim3(C3/BN, MB), 256, GEMM_SMEM>>>(
            y, qkvw_c + (size_t)l*C3*CDIM, bias3 + l*C3, qkv, TTOK, C3, CDIM, 0);
        rope_pack_kernel<<<(packThreads + 255)/256, 256>>>(qkv, rope, qh, kh, vh);
        attn_tc_kernel<<<BB*NH, 256, ATTN_TC_SMEM>>>(qh, kh, vh, o);
        tc_gemm<float><<<dim3(CDIM/BN, MB), 256, GEMM_SMEM>>>(
            o, projw_c + (size_t)l*CDIM*CDIM, proj_b + l*CDIM, out, TTOK, CDIM, CDIM, 1);

        ln_kernel<CDIM><<<TTOK, 256>>>(out, n2_g + l*CDIM, n2_b + l*CDIM, y);
        tc_gemm<__half><<<dim3(2*HF/BN, MB), 256, GEMM_SMEM>>>(
            y, guw_c + (size_t)l*2*HF*CDIM, bgu + l*2*HF, gu, TTOK, 2*HF, CDIM, 0);
        swiglu_ln_kernel<<<TTOK, 256>>>(gu, nm_g + l*HF, nm_b + l*HF, u);
        tc_gemm<float><<<dim3(CDIM/BN, MB), 256, GEMM_SMEM>>>(
            u, w2_c + (size_t)l*CDIM*HF, b2 + l*CDIM, out, TTOK, CDIM, HF, 1);
    }
}

// round 15
// speedup vs baseline: 6.5300x; 1.0023x over previous
#include <cuda_runtime.h>
#include <cuda_fp16.h>
#include <cstdint>
#include <cstddef>
#include <cstring>

// ---------------- problem constants ----------------
#define LNUM 4
#define BB   64
#define NTOK 197
#define CDIM 768
#define NH   12
#define HDIM 64
#define HF   2048
#define C3   (3*CDIM)
#define TTOK (BB*NTOK)          // 12608
#define SCALE 0.125f
#define EPS 1e-6f
#define NPAD 208                // 197 padded to multiple of 16

// ---------------- scratch (device globals: no allocs allowed) ----------------
__device__ __half g_y   [(size_t)TTOK*CDIM];     // fp16 GEMM A operands
__device__ __half g_o   [(size_t)TTOK*CDIM];
__device__ __half g_u   [(size_t)TTOK*HF];
__device__ __half g_gu  [(size_t)TTOK*2*HF];     // fused gate|up output
__device__ float  g_bias3[LNUM*C3];
__device__ float  g_bgu [LNUM*2*HF];
// packed fp16 attention operands, per (b,h): [NPAD][64], pad rows zeroed
__device__ __half g_qh[(size_t)BB*NH*NPAD*HDIM];
__device__ __half g_kh[(size_t)BB*NH*NPAD*HDIM];
__device__ __half g_vh[(size_t)BB*NH*NPAD*HDIM];

// pre-converted fp16 weights: qkv | proj | [w1g;w1x] packed | w2
#define WC_QKV  0
#define WC_PROJ ((size_t)LNUM*C3*CDIM)
#define WC_GU   (WC_PROJ + (size_t)LNUM*CDIM*CDIM)
#define WC_W2   (WC_GU + (size_t)LNUM*2*HF*CDIM)
#define WC_TOT  (WC_W2 + (size_t)LNUM*CDIM*HF)
__device__ __half g_wc[WC_TOT];

// ---------------- weight fp32 -> fp16 conversion ----------------
__global__ __launch_bounds__(256) void cvth_kernel(
    const float* __restrict__ in, __half* __restrict__ out, int n4)
{
    int i = blockIdx.x * blockDim.x + threadIdx.x;
    if (i >= n4) return;
    float4 v = ((const float4*)in)[i];
    ((__half2*)out)[2*i]   = __floats2half2_rn(v.x, v.y);
    ((__half2*)out)[2*i+1] = __floats2half2_rn(v.z, v.w);
}

// ---------------- one-time pad-row zeroing for qh/kh/vh ----------------
__global__ void padzero_kernel(__half* __restrict__ qh, __half* __restrict__ kh,
                               __half* __restrict__ vh)
{
    const int perbh = (NPAD - NTOK) * HDIM / 2;      // 352 half2 per (b,h)
    int idx = blockIdx.x * blockDim.x + threadIdx.x;
    if (idx >= BB * NH * perbh) return;
    int bh = idx / perbh, r = idx % perbh;
    size_t off = (size_t)bh * NPAD * HDIM + (size_t)NTOK * HDIM + (size_t)r * 2;
    *(uint32_t*)&qh[off] = 0; *(uint32_t*)&kh[off] = 0; *(uint32_t*)&vh[off] = 0;
}

// ================= shared PTX helpers =================
__device__ __forceinline__ uint32_t h2u(__half2 h) {
    uint32_t u; memcpy(&u, &h, 4); return u;
}
__device__ __forceinline__ uint32_t smem_addr_u32(const void* p) {
    uint32_t a;
    asm("{ .reg .u64 t; cvta.to.shared.u64 t, %1; cvt.u32.u64 %0, t; }"
        : "=r"(a) : "l"(p));
    return a;
}
__device__ __forceinline__ void cp16(uint32_t dst, const void* src, int sz) {
    asm volatile("cp.async.cg.shared.global [%0], [%1], 16, %2;"
                 :: "r"(dst), "l"(__cvta_generic_to_global(src)), "r"(sz));
}
__device__ __forceinline__ void ldsm_x4(uint32_t* r, uint32_t addr) {
    asm volatile("ldmatrix.sync.aligned.m8n8.x4.shared.b16 {%0,%1,%2,%3}, [%4];"
        : "=r"(r[0]), "=r"(r[1]), "=r"(r[2]), "=r"(r[3]) : "r"(addr));
}
__device__ __forceinline__ void ldsm_x4_t(uint32_t* r, uint32_t addr) {
    asm volatile("ldmatrix.sync.aligned.m8n8.x4.trans.shared.b16 {%0,%1,%2,%3}, [%4];"
        : "=r"(r[0]), "=r"(r[1]), "=r"(r[2]), "=r"(r[3]) : "r"(addr));
}
__device__ __forceinline__ void mma_f16(float* d, const uint32_t* a, const uint32_t* b) {
    asm volatile(
        "mma.sync.aligned.m16n8k16.row.col.f32.f16.f16.f32 "
        "{%0,%1,%2,%3}, {%4,%5,%6,%7}, {%8,%9}, {%0,%1,%2,%3};"
        : "+f"(d[0]), "+f"(d[1]), "+f"(d[2]), "+f"(d[3])
        : "r"(a[0]), "r"(a[1]), "r"(a[2]), "r"(a[3]), "r"(b[0]), "r"(b[1]));
}

// ================= fp16 mma.sync GEMM (m16n8k16) + ldmatrix =================
// MODE_RES: float out + optional residual. MODE_H16: half out.
// MODE_QKV: fused RoPE+scale epilogue scattering to per-head q/k/v layouts.
#define MODE_RES 0
#define MODE_H16 1
#define MODE_QKV 2
#define BM 128
#define BN 128
#define BK 64
#define SPH   72
#define BUFH  (BM * SPH)
#define GEMM_SMEM (4 * BUFH * 2)

template <int MODE>
__global__ __launch_bounds__(256, 2) void tc_gemm(
    const __half* __restrict__ A, const __half* __restrict__ W,
    const float* __restrict__ bias,
    float* __restrict__ outF, __half* __restrict__ outH,
    const float* __restrict__ rope,
    __half* __restrict__ qh, __half* __restrict__ kh, __half* __restrict__ vh,
    int M, int N, int K, int residual)
{
    extern __shared__ __half sm[];
    __half* As0 = sm;
    __half* Ws0 = sm + BUFH;

    const int tid  = threadIdx.x;
    const int wid  = tid >> 5, lane = tid & 31;
    const int wm   = wid & 1;
    const int wn   = wid >> 1;
    const int qid  = lane >> 2;
    const int lid  = lane & 3;
    const int m0   = blockIdx.y * BM, n0 = blockIdx.x * BN;

    uint32_t aS[4], wS[4];
    const __half* aG[4]; const __half* wG[4]; int aSz[4];
#pragma unroll
    for (int i = 0; i < 4; i++) {
        int g = tid + i * 256;
        int r = g >> 3, s = g & 7;
        uint32_t off = (uint32_t)(r * SPH + s * 8) * 2u;
        aS[i] = smem_addr_u32(As0) + off;
        wS[i] = smem_addr_u32(Ws0) + off;
        int arow = m0 + r;
        int ok = arow < M;
        aSz[i] = ok ? 16 : 0;
        aG[i]  = A + (size_t)(ok ? arow : 0) * K + s * 8;
        wG[i]  = W + (size_t)(n0 + r) * K + s * 8;
    }
    const uint32_t bufStride = (uint32_t)(2 * BUFH) * 2u;

    const uint32_t a_lm = smem_addr_u32(
        As0 + (size_t)(wm * 64 + (lane & 15)) * SPH + (lane >> 4) * 8);
    const uint32_t b_lm = smem_addr_u32(
        Ws0 + (size_t)(wn * 32 + ((lane >> 4) & 1) * 8 + (lane & 7)) * SPH
            + ((lane >> 3) & 1) * 8);

    float acc[4][4][4];
#pragma unroll
    for (int mf = 0; mf < 4; mf++)
#pragma unroll
        for (int nf = 0; nf < 4; nf++)
#pragma unroll
            for (int q = 0; q < 4; q++) acc[mf][nf][q] = 0.f;

    const int NCH = K / BK;
#pragma unroll
    for (int i = 0; i < 4; i++) { cp16(aS[i], aG[i], aSz[i]); cp16(wS[i], wG[i], 16); }
    asm volatile("cp.async.commit_group;");

    for (int c = 0; c < NCH; c++) {
        const int buf = c & 1;
        if (c + 1 < NCH) {
            const uint32_t bo = ((c + 1) & 1) ? bufStride : 0u;
            const int koff = (c + 1) * BK;
#pragma unroll
            for (int i = 0; i < 4; i++) {
                cp16(aS[i] + bo, aG[i] + koff, aSz[i]);
                cp16(wS[i] + bo, wG[i] + koff, 16);
            }
            asm volatile("cp.async.commit_group;");
            asm volatile("cp.async.wait_group 1;" ::: "memory");
        } else {
            asm volatile("cp.async.wait_group 0;" ::: "memory");
        }
        __syncthreads();

        const uint32_t bofs = buf ? bufStride : 0u;
#pragma unroll
        for (int ks = 0; ks < 4; ks++) {
            uint32_t afr[4][4], bfr[4][2];
#pragma unroll
            for (int mf = 0; mf < 4; mf++)
                ldsm_x4(afr[mf], a_lm + bofs + (uint32_t)(mf * 16 * SPH + ks * 16) * 2u);
#pragma unroll
            for (int np = 0; np < 2; np++)
                ldsm_x4(&bfr[2*np][0], b_lm + bofs + (uint32_t)(np * 16 * SPH + ks * 16) * 2u);
#pragma unroll
            for (int mf = 0; mf < 4; mf++)
#pragma unroll
                for (int nf = 0; nf < 4; nf++)
                    mma_f16(acc[mf][nf], afr[mf], bfr[nf]);
        }
        __syncthreads();
    }

    // ---- epilogue ----
    const int sec = (MODE == MODE_QKV) ? (n0 / CDIM) : 0;   // CTA-uniform
    __half* dsth = (MODE == MODE_QKV) ? ((sec == 0) ? qh : (sec == 1) ? kh : vh)
                                      : outH;

#pragma unroll
    for (int mf = 0; mf < 4; mf++) {
        int r0 = m0 + wm * 64 + mf * 16 + qid;
        int r1 = r0 + 8;
#pragma unroll
        for (int nf = 0; nf < 4; nf++) {
            int col = n0 + wn * 32 + nf * 8 + 2 * lid;
            float2 bv = *(const float2*)&bias[col];
            if constexpr (MODE == MODE_RES) {
                if (r0 < M) {
                    float* op = outF + (size_t)r0 * N + col;
                    float2 v = make_float2(acc[mf][nf][0] + bv.x, acc[mf][nf][1] + bv.y);
                    if (residual) { float2 o2 = *(const float2*)op; v.x += o2.x; v.y += o2.y; }
                    *(float2*)op = v;
                }
                if (r1 < M) {
                    float* op = outF + (size_t)r1 * N + col;
                    float2 v = make_float2(acc[mf][nf][2] + bv.x, acc[mf][nf][3] + bv.y);
                    if (residual) { float2 o2 = *(const float2*)op; v.x += o2.x; v.y += o2.y; }
                    *(float2*)op = v;
                }
            } else if constexpr (MODE == MODE_H16) {
                if (r0 < M) {
                    __half2* op = (__half2*)(dsth + (size_t)r0 * N + col);
                    *op = __floats2half2_rn(acc[mf][nf][0] + bv.x, acc[mf][nf][1] + bv.y);
                }
                if (r1 < M) {
                    __half2* op = (__half2*)(dsth + (size_t)r1 * N + col);
                    *op = __floats2half2_rn(acc[mf][nf][2] + bv.x, acc[mf][nf][3] + bv.y);
                }
            } else {
                // MODE_QKV: fused bias + RoPE + scale, scatter to per-head layout
                int cc = col - sec * CDIM;
                int h  = cc >> 6, d0 = cc & 63;
#pragma unroll
                for (int rr = 0; rr < 2; rr++) {
                    int t = rr ? r1 : r0;
                    if (t >= M) continue;
                    int b = t / NTOK, n = t - b * NTOK;
                    float v0 = acc[mf][nf][2*rr]     + bv.x;
                    float v1 = acc[mf][nf][2*rr + 1] + bv.y;
                    if (sec < 2 && n > 0) {
                        const float* rp = rope + (size_t)(n - 1) * (2*HDIM);
                        float2 sv = *(const float2*)&rp[d0];
                        float2 cv = *(const float2*)&rp[HDIM + d0];
                        float t0 = v0 * cv.x - v1 * sv.x;
                        float t1 = v1 * cv.y + v0 * sv.y;
                        v0 = t0; v1 = t1;
                    }
                    if (sec == 0) { v0 *= SCALE; v1 *= SCALE; }
                    size_t ob = ((size_t)(b * NH + h)) * NPAD * HDIM
                              + (size_t)n * HDIM + d0;
                    *(__half2*)&dsth[ob] = __floats2half2_rn(v0, v1);
                }
            }
        }
    }
}

// ---------------- block reduction helper ----------------
__device__ __forceinline__ float2 block_sum2(float2 v) {
    __shared__ float2 red[8];
    int lane = threadIdx.x & 31, warp = threadIdx.x >> 5;
#pragma unroll
    for (int off = 16; off; off >>= 1) {
        v.x += __shfl_xor_sync(0xffffffffu, v.x, off);
        v.y += __shfl_xor_sync(0xffffffffu, v.y, off);
    }
    if (lane == 0) red[warp] = v;
    __syncthreads();
    if (warp == 0) {
        float2 w = (lane < 8) ? red[lane] : make_float2(0.f, 0.f);
#pragma unroll
        for (int off = 4; off; off >>= 1) {
            w.x += __shfl_xor_sync(0xffffffffu, w.x, off);
            w.y += __shfl_xor_sync(0xffffffffu, w.y, off);
        }
        if (lane == 0) red[0] = w;
    }
    __syncthreads();
    return red[0];
}

// ---------------- LayerNorm (fp32 in, fp16 out) ----------
template <int CD>
__global__ __launch_bounds__(256) void ln_kernel(
    const float* __restrict__ in, const float* __restrict__ gamma,
    const float* __restrict__ beta, __half* __restrict__ out)
{
    constexpr int PER = CD / 256;
    const size_t base = (size_t)blockIdx.x * CD;
    float v[PER];
    float2 s = make_float2(0.f, 0.f);
#pragma unroll
    for (int i = 0; i < PER; i++) {
        v[i] = in[base + i*256 + threadIdx.x];
        s.x += v[i]; s.y += v[i]*v[i];
    }
    s = block_sum2(s);
    float mean = s.x * (1.f / CD);
    float var  = s.y * (1.f / CD) - mean * mean;
    float inv  = rsqrtf(var + EPS);
#pragma unroll
    for (int i = 0; i < PER; i++) {
        int c = i*256 + threadIdx.x;
        out[base + c] = __float2half_rn((v[i] - mean) * inv * gamma[c] + beta[c]);
    }
}

// ---------------- SwiGLU + inner LayerNorm (fp16 gu in, fp16 out) ------------
__global__ __launch_bounds__(256) void swiglu_ln_kernel(
    const __half* __restrict__ GU,
    const float* __restrict__ gamma, const float* __restrict__ beta,
    __half* __restrict__ out)
{
    const size_t base = (size_t)blockIdx.x * 2 * HF;
    float u[8];
    float2 s = make_float2(0.f, 0.f);
#pragma unroll
    for (int i = 0; i < 8; i++) {
        int c = i*256 + threadIdx.x;
        float g = __half2float(GU[base + c]);
        float x = __half2float(GU[base + HF + c]);
        float uu = (g / (1.f + __expf(-g))) * x;
        u[i] = uu; s.x += uu; s.y += uu*uu;
    }
    s = block_sum2(s);
    float mean = s.x * (1.f / HF);
    float var  = s.y * (1.f / HF) - mean * mean;
    float inv  = rsqrtf(var + EPS);
#pragma unroll
    for (int i = 0; i < 8; i++) {
        int c = i*256 + threadIdx.x;
        out[(size_t)blockIdx.x * HF + c] =
            __float2half_rn((u[i] - mean) * inv * gamma[c] + beta[c]);
    }
}

// ---------------- bias builders ----------------
__global__ void bias3_kernel(float* __restrict__ bias3,
                             const float* __restrict__ qb,
                             const float* __restrict__ vb)
{
    int idx = blockIdx.x * blockDim.x + threadIdx.x;
    if (idx >= LNUM * C3) return;
    int l = idx / C3, j = idx % C3;
    float v = 0.f;
    if (j < CDIM)         v = qb[l*CDIM + j];
    else if (j >= 2*CDIM) v = vb[l*CDIM + (j - 2*CDIM)];
    bias3[idx] = v;
}
__global__ void biasgu_kernel(float* __restrict__ bgu,
                              const float* __restrict__ bg,
                              const float* __restrict__ bx)
{
    int idx = blockIdx.x * blockDim.x + threadIdx.x;
    if (idx >= LNUM * 2 * HF) return;
    int l = idx / (2*HF), j = idx % (2*HF);
    bgu[idx] = (j < HF) ? bg[l*HF + j] : bx[l*HF + (j - HF)];
}

// ---------------- tensor-core attention: one CTA per (b,h) ----------------
#define AP 72                                 // smem pitch (halves)
#define NT8 (NPAD/8)                          // 26 n8 tiles
#define ATTN_TC_SMEM (3 * NPAD * AP * 2)      // 89856 B

__global__ __launch_bounds__(256, 1) void attn_tc_kernel(
    const __half* __restrict__ qh, const __half* __restrict__ kh,
    const __half* __restrict__ vh, __half* __restrict__ o)
{
    extern __shared__ __half sm2[];
    __half* Qs = sm2;
    __half* Ks = Qs + NPAD*AP;
    __half* Vs = Ks + NPAD*AP;

    const int bh = blockIdx.x, b = bh / NH, h = bh % NH;
    const int tid = threadIdx.x, warp = tid >> 5, lane = tid & 31;
    const int qid = lane >> 2, lid = lane & 3;

    const __half* qg = qh + (size_t)bh * NPAD * HDIM;
    const __half* kg = kh + (size_t)bh * NPAD * HDIM;
    const __half* vg = vh + (size_t)bh * NPAD * HDIM;
    const uint32_t qsb = smem_addr_u32(Qs);
    const uint32_t ksb = smem_addr_u32(Ks);
    const uint32_t vsb = smem_addr_u32(Vs);

    for (int i = tid; i < NPAD * 8; i += 256) {
        int r = i >> 3, s = i & 7;
        uint32_t off = (uint32_t)(r * AP + s * 8) * 2u;
        const int gofs = r * HDIM + s * 8;
        cp16(qsb + off, qg + gofs, 16);
        cp16(ksb + off, kg + gofs, 16);
        cp16(vsb + off, vg + gofs, 16);
    }
    asm volatile("cp.async.commit_group;");
    asm volatile("cp.async.wait_group 0;" ::: "memory");
    __syncthreads();

    const uint32_t a_base = qsb + (uint32_t)(((lane & 15) * AP) + (lane >> 4) * 8) * 2u;
    const uint32_t k_base = ksb + (uint32_t)((((lane >> 4) & 1) * 8 + (lane & 7)) * AP
                                             + ((lane >> 3) & 1) * 8) * 2u;
    const uint32_t v_base = vsb + (uint32_t)((((lane >> 3) & 1) * 8 + (lane & 7)) * AP
                                             + (lane >> 4) * 8) * 2u;

    for (int mt = warp; mt < NPAD/16; mt += 8) {
        const int m0 = mt * 16;
        uint32_t afr[4][4];
#pragma unroll
        for (int ks = 0; ks < 4; ks++)
            ldsm_x4(afr[ks], a_base + (uint32_t)(m0 * AP + ks * 16) * 2u);
        float acc[NT8][4];
#pragma unroll
        for (int nb = 0; nb < NT8; nb++)
#pragma unroll
            for (int q = 0; q < 4; q++) acc[nb][q] = 0.f;
#pragma unroll
        for (int ks = 0; ks < 4; ks++) {
#pragma unroll
            for (int np = 0; np < NT8/2; np++) {
                uint32_t bfr[4];
                ldsm_x4(bfr, k_base + (uint32_t)(np * 16 * AP + ks * 16) * 2u);
                mma_f16(acc[2*np],     afr[ks], bfr);
                mma_f16(acc[2*np + 1], afr[ks], bfr + 2);
            }
        }
        float mx0 = -1e30f, mx1 = -1e30f;
#pragma unroll
        for (int nb = 0; nb < NT8; nb++) {
#pragma unroll
            for (int e = 0; e < 2; e++) {
                int col = nb * 8 + 2 * lid + e;
                if (col < NTOK) {
                    mx0 = fmaxf(mx0, acc[nb][e]);
                    mx1 = fmaxf(mx1, acc[nb][2 + e]);
                }
            }
        }
        mx0 = fmaxf(mx0, __shfl_xor_sync(0xffffffffu, mx0, 1));
        mx0 = fmaxf(mx0, __shfl_xor_sync(0xffffffffu, mx0, 2));
        mx1 = fmaxf(mx1, __shfl_xor_sync(0xffffffffu, mx1, 1));
        mx1 = fmaxf(mx1, __shfl_xor_sync(0xffffffffu, mx1, 2));
        float sum0 = 0.f, sum1 = 0.f;
#pragma unroll
        for (int nb = 0; nb < NT8; nb++) {
#pragma unroll
            for (int e = 0; e < 2; e++) {
                int col = nb * 8 + 2 * lid + e;
                float p0 = (col < NTOK) ? __expf(acc[nb][e] - mx0) : 0.f;
                float p1 = (col < NTOK) ? __expf(acc[nb][2 + e] - mx1) : 0.f;
                acc[nb][e] = p0; acc[nb][2 + e] = p1;
                sum0 += p0; sum1 += p1;
            }
        }
        sum0 += __shfl_xor_sync(0xffffffffu, sum0, 1);
        sum0 += __shfl_xor_sync(0xffffffffu, sum0, 2);
        sum1 += __shfl_xor_sync(0xffffffffu, sum1, 1);
        sum1 += __shfl_xor_sync(0xffffffffu, sum1, 2);
        float oacc[8][4];
#pragma unroll
        for (int db = 0; db < 8; db++)
#pragma unroll
            for (int q = 0; q < 4; q++) oacc[db][q] = 0.f;
#pragma unroll
        for (int t = 0; t < NPAD/16; t++) {
            uint32_t pa[4];
            pa[0] = h2u(__floats2half2_rn(acc[2*t][0],   acc[2*t][1]));
            pa[1] = h2u(__floats2half2_rn(acc[2*t][2],   acc[2*t][3]));
            pa[2] = h2u(__floats2half2_rn(acc[2*t+1][0], acc[2*t+1][1]));
            pa[3] = h2u(__floats2half2_rn(acc[2*t+1][2], acc[2*t+1][3]));
#pragma unroll
            for (int dp = 0; dp < 4; dp++) {
                uint32_t bfr[4];
                ldsm_x4_t(bfr, v_base + (uint32_t)(t * 16 * AP + dp * 16) * 2u);
                mma_f16(oacc[2*dp],     pa, bfr);
                mma_f16(oacc[2*dp + 1], pa, bfr + 2);
            }
        }
        float i0 = 1.f / sum0, i1 = 1.f / sum1;
        int r0 = m0 + qid, r1 = r0 + 8;
#pragma unroll
        for (int db = 0; db < 8; db++) {
            int col = h * HDIM + db * 8 + 2 * lid;
            if (r0 < NTOK) {
                __half2 v = __floats2half2_rn(oacc[db][0] * i0, oacc[db][1] * i0);
                *(__half2*)&o[((size_t)(b * NTOK + r0)) * CDIM + col] = v;
            }
            if (r1 < NTOK) {
                __half2 v = __floats2half2_rn(oacc[db][2] * i1, oacc[db][3] * i1);
                *(__half2*)&o[((size_t)(b * NTOK + r1)) * CDIM + col] = v;
            }
        }
    }
}

// ---------------- host orchestration ----------------
extern "C" void kernel_launch(void* const* d_in, const int* in_sizes, int n_in,
                              void* d_out, int out_size)
{
    const float* x      = (const float*)d_in[0];
    const float* rope   = (const float*)d_in[1];
    const float* qkv_w  = (const float*)d_in[2];
    const float* q_bias = (const float*)d_in[3];
    const float* v_bias = (const float*)d_in[4];
    const float* proj_w = (const float*)d_in[5];
    const float* proj_b = (const float*)d_in[6];
    const float* n1_g   = (const float*)d_in[7];
    const float* n1_b   = (const float*)d_in[8];
    const float* n2_g   = (const float*)d_in[9];
    const float* n2_b   = (const float*)d_in[10];
    const float* w1g    = (const float*)d_in[11];
    const float* b1g    = (const float*)d_in[12];
    const float* w1x    = (const float*)d_in[13];
    const float* b1x    = (const float*)d_in[14];
    const float* nm_g   = (const float*)d_in[15];
    const float* nm_b   = (const float*)d_in[16];
    const float* w2     = (const float*)d_in[17];
    const float* b2     = (const float*)d_in[18];
    float* out = (float*)d_out;

    __half *y, *o, *u, *gu, *wc, *qh, *kh, *vh;
    float *bias3, *bgu;
    cudaGetSymbolAddress((void**)&y,     g_y);
    cudaGetSymbolAddress((void**)&o,     g_o);
    cudaGetSymbolAddress((void**)&u,     g_u);
    cudaGetSymbolAddress((void**)&gu,    g_gu);
    cudaGetSymbolAddress((void**)&bias3, g_bias3);
    cudaGetSymbolAddress((void**)&bgu,   g_bgu);
    cudaGetSymbolAddress((void**)&wc,    g_wc);
    cudaGetSymbolAddress((void**)&qh,    g_qh);
    cudaGetSymbolAddress((void**)&kh,    g_kh);
    cudaGetSymbolAddress((void**)&vh,    g_vh);

    __half* qkvw_c  = wc + WC_QKV;
    __half* projw_c = wc + WC_PROJ;
    __half* guw_c   = wc + WC_GU;
    __half* w2_c    = wc + WC_W2;

    cudaFuncSetAttribute(tc_gemm<MODE_RES>,
        cudaFuncAttributeMaxDynamicSharedMemorySize, GEMM_SMEM);
    cudaFuncSetAttribute(tc_gemm<MODE_H16>,
        cudaFuncAttributeMaxDynamicSharedMemorySize, GEMM_SMEM);
    cudaFuncSetAttribute(tc_gemm<MODE_QKV>,
        cudaFuncAttributeMaxDynamicSharedMemorySize, GEMM_SMEM);
    cudaFuncSetAttribute(attn_tc_kernel,
        cudaFuncAttributeMaxDynamicSharedMemorySize, ATTN_TC_SMEM);

    cudaMemcpyAsync(out, x, (size_t)TTOK * CDIM * sizeof(float),
                    cudaMemcpyDeviceToDevice);

    // pre-convert weights to fp16; pack [w1g;w1x] per layer for fused GEMM
    {
        int n;
        n = LNUM*C3*CDIM/4;   cvth_kernel<<<(n+255)/256, 256>>>(qkv_w,  qkvw_c,  n);
        n = LNUM*CDIM*CDIM/4; cvth_kernel<<<(n+255)/256, 256>>>(proj_w, projw_c, n);
        n = HF*CDIM/4;
        for (int l = 0; l < LNUM; l++) {
            cvth_kernel<<<(n+255)/256, 256>>>(
                w1g + (size_t)l*HF*CDIM, guw_c + (size_t)l*2*HF*CDIM, n);
            cvth_kernel<<<(n+255)/256, 256>>>(
                w1x + (size_t)l*HF*CDIM, guw_c + (size_t)l*2*HF*CDIM + (size_t)HF*CDIM, n);
        }
        n = LNUM*CDIM*HF/4;   cvth_kernel<<<(n+255)/256, 256>>>(w2, w2_c, n);
    }

    bias3_kernel<<<(LNUM*C3 + 255)/256, 256>>>(bias3, q_bias, v_bias);
    biasgu_kernel<<<(LNUM*2*HF + 255)/256, 256>>>(bgu, b1g, b1x);
    {
        int n = BB * NH * (NPAD - NTOK) * HDIM / 2;
        padzero_kernel<<<(n + 255)/256, 256>>>(qh, kh, vh);
    }

    const int MB = (TTOK + BM - 1) / BM;     // 99

    for (int l = 0; l < LNUM; l++) {
        ln_kernel<CDIM><<<TTOK, 256>>>(out, n1_g + l*CDIM, n1_b + l*CDIM, y);
        tc_gemm<MODE_QKV><<<dim3(C3/BN, MB), 256, GEMM_SMEM>>>(
            y, qkvw_c + (size_t)l*C3*CDIM, bias3 + l*C3,
            nullptr, nullptr, rope, qh, kh, vh, TTOK, C3, CDIM, 0);
        attn_tc_kernel<<<BB*NH, 256, ATTN_TC_SMEM>>>(qh, kh, vh, o);
        tc_gemm<MODE_RES><<<dim3(CDIM/BN, MB), 256, GEMM_SMEM>>>(
            o, projw_c + (size_t)l*CDIM*CDIM, proj_b + l*CDIM,
            out, nullptr, nullptr, nullptr, nullptr, nullptr, TTOK, CDIM, CDIM, 1);

        ln_kernel<CDIM><<<TTOK, 256>>>(out, n2_g + l*CDIM, n2_b + l*CDIM, y);
        tc_gemm<MODE_H16><<<dim3(2*HF/BN, MB), 256, GEMM_SMEM>>>(
            y, guw_c + (size_t)l*2*HF*CDIM, bgu + l*2*HF,
            nullptr, gu, nullptr, nullptr, nullptr, nullptr, TTOK, 2*HF, CDIM, 0);
        swiglu_ln_kernel<<<TTOK, 256>>>(gu, nm_g + l*HF, nm_b + l*HF, u);
        tc_gemm<MODE_RES><<<dim3(CDIM/BN, MB), 256, GEMM_SMEM>>>(
            u, w2_c + (size_t)l*CDIM*HF, b2 + l*CDIM,
            out, nullptr, nullptr, nullptr, nullptr, nullptr, TTOK, CDIM, HF, 1);
    }
}

// round 16
// speedup vs baseline: 6.5848x; 1.0084x over previous
#include <cuda_runtime.h>
#include <cuda_fp16.h>
#include <cstdint>
#include <cstddef>
#include <cstring>

// ---------------- problem constants ----------------
#define LNUM 4
#define BB   64
#define NTOK 197
#define CDIM 768
#define NH   12
#define HDIM 64
#define HF   2048
#define C3   (3*CDIM)
#define TTOK (BB*NTOK)          // 12608
#define SCALE 0.125f
#define EPS 1e-6f
#define NPAD 208                // 197 padded to multiple of 16

// ---------------- scratch (device globals: no allocs allowed) ----------------
__device__ __half g_y   [(size_t)TTOK*CDIM];     // fp16 GEMM A operands
__device__ __half g_o   [(size_t)TTOK*CDIM];
__device__ __half g_u   [(size_t)TTOK*HF];
__device__ __half g_gu  [(size_t)TTOK*2*HF];     // fused gate|up output
__device__ float  g_bias3[LNUM*C3];
__device__ float  g_bgu [LNUM*2*HF];
// packed fp16 attention operands, per (b,h): [NPAD][64], pad rows zeroed
__device__ __half g_qh[(size_t)BB*NH*NPAD*HDIM];
__device__ __half g_kh[(size_t)BB*NH*NPAD*HDIM];
__device__ __half g_vh[(size_t)BB*NH*NPAD*HDIM];

// pre-converted fp16 weights: qkv | proj | [w1g;w1x] packed | w2
#define WC_QKV  0
#define WC_PROJ ((size_t)LNUM*C3*CDIM)
#define WC_GU   (WC_PROJ + (size_t)LNUM*CDIM*CDIM)
#define WC_W2   (WC_GU + (size_t)LNUM*2*HF*CDIM)
#define WC_TOT  (WC_W2 + (size_t)LNUM*CDIM*HF)
__device__ __half g_wc[WC_TOT];

// ---------------- weight fp32 -> fp16 conversion ----------------
__global__ __launch_bounds__(256) void cvth_kernel(
    const float* __restrict__ in, __half* __restrict__ out, int n4)
{
    int i = blockIdx.x * blockDim.x + threadIdx.x;
    if (i >= n4) return;
    float4 v = ((const float4*)in)[i];
    ((__half2*)out)[2*i]   = __floats2half2_rn(v.x, v.y);
    ((__half2*)out)[2*i+1] = __floats2half2_rn(v.z, v.w);
}

// ---------------- one-time pad-row zeroing for qh/kh/vh ----------------
__global__ void padzero_kernel(__half* __restrict__ qh, __half* __restrict__ kh,
                               __half* __restrict__ vh)
{
    const int perbh = (NPAD - NTOK) * HDIM / 2;      // 352 half2 per (b,h)
    int idx = blockIdx.x * blockDim.x + threadIdx.x;
    if (idx >= BB * NH * perbh) return;
    int bh = idx / perbh, r = idx % perbh;
    size_t off = (size_t)bh * NPAD * HDIM + (size_t)NTOK * HDIM + (size_t)r * 2;
    *(uint32_t*)&qh[off] = 0; *(uint32_t*)&kh[off] = 0; *(uint32_t*)&vh[off] = 0;
}

// ================= shared PTX helpers =================
__device__ __forceinline__ uint32_t h2u(__half2 h) {
    uint32_t u; memcpy(&u, &h, 4); return u;
}
__device__ __forceinline__ uint32_t smem_addr_u32(const void* p) {
    uint32_t a;
    asm("{ .reg .u64 t; cvta.to.shared.u64 t, %1; cvt.u32.u64 %0, t; }"
        : "=r"(a) : "l"(p));
    return a;
}
__device__ __forceinline__ void cp16(uint32_t dst, const void* src, int sz) {
    asm volatile("cp.async.cg.shared.global [%0], [%1], 16, %2;"
                 :: "r"(dst), "l"(__cvta_generic_to_global(src)), "r"(sz));
}
__device__ __forceinline__ void ldsm_x4(uint32_t* r, uint32_t addr) {
    asm volatile("ldmatrix.sync.aligned.m8n8.x4.shared.b16 {%0,%1,%2,%3}, [%4];"
        : "=r"(r[0]), "=r"(r[1]), "=r"(r[2]), "=r"(r[3]) : "r"(addr));
}
__device__ __forceinline__ void ldsm_x4_t(uint32_t* r, uint32_t addr) {
    asm volatile("ldmatrix.sync.aligned.m8n8.x4.trans.shared.b16 {%0,%1,%2,%3}, [%4];"
        : "=r"(r[0]), "=r"(r[1]), "=r"(r[2]), "=r"(r[3]) : "r"(addr));
}
__device__ __forceinline__ void mma_f16(float* d, const uint32_t* a, const uint32_t* b) {
    asm volatile(
        "mma.sync.aligned.m16n8k16.row.col.f32.f16.f16.f32 "
        "{%0,%1,%2,%3}, {%4,%5,%6,%7}, {%8,%9}, {%0,%1,%2,%3};"
        : "+f"(d[0]), "+f"(d[1]), "+f"(d[2]), "+f"(d[3])
        : "r"(a[0]), "r"(a[1]), "r"(a[2]), "r"(a[3]), "r"(b[0]), "r"(b[1]));
}

// ================= fp16 mma.sync GEMM (m16n8k16) + ldmatrix =================
// MODE_RES: float out + optional residual. MODE_H16: half out.
// MODE_QKV: fused RoPE+scale epilogue scattering to per-head q/k/v layouts.
#define MODE_RES 0
#define MODE_H16 1
#define MODE_QKV 2
#define BM 128
#define BN 128
#define BK 64
#define SPH   72
#define BUFH  (BM * SPH)
#define GEMM_SMEM (4 * BUFH * 2)

template <int MODE>
__global__ __launch_bounds__(256, 2) void tc_gemm(
    const __half* __restrict__ A, const __half* __restrict__ W,
    const float* __restrict__ bias,
    float* __restrict__ outF, __half* __restrict__ outH,
    const float* __restrict__ rope,
    __half* __restrict__ qh, __half* __restrict__ kh, __half* __restrict__ vh,
    int M, int N, int K, int residual)
{
    extern __shared__ __half sm[];
    __half* As0 = sm;
    __half* Ws0 = sm + BUFH;

    const int tid  = threadIdx.x;
    const int wid  = tid >> 5, lane = tid & 31;
    const int wm   = wid & 1;
    const int wn   = wid >> 1;
    const int qid  = lane >> 2;
    const int lid  = lane & 3;
    const int m0   = blockIdx.y * BM, n0 = blockIdx.x * BN;

    uint32_t aS[4], wS[4];
    const __half* aG[4]; const __half* wG[4]; int aSz[4];
#pragma unroll
    for (int i = 0; i < 4; i++) {
        int g = tid + i * 256;
        int r = g >> 3, s = g & 7;
        uint32_t off = (uint32_t)(r * SPH + s * 8) * 2u;
        aS[i] = smem_addr_u32(As0) + off;
        wS[i] = smem_addr_u32(Ws0) + off;
        int arow = m0 + r;
        int ok = arow < M;
        aSz[i] = ok ? 16 : 0;
        aG[i]  = A + (size_t)(ok ? arow : 0) * K + s * 8;
        wG[i]  = W + (size_t)(n0 + r) * K + s * 8;
    }
    const uint32_t bufStride = (uint32_t)(2 * BUFH) * 2u;

    const uint32_t a_lm = smem_addr_u32(
        As0 + (size_t)(wm * 64 + (lane & 15)) * SPH + (lane >> 4) * 8);
    const uint32_t b_lm = smem_addr_u32(
        Ws0 + (size_t)(wn * 32 + ((lane >> 4) & 1) * 8 + (lane & 7)) * SPH
            + ((lane >> 3) & 1) * 8);

    float acc[4][4][4];
#pragma unroll
    for (int mf = 0; mf < 4; mf++)
#pragma unroll
        for (int nf = 0; nf < 4; nf++)
#pragma unroll
            for (int q = 0; q < 4; q++) acc[mf][nf][q] = 0.f;

    const int NCH = K / BK;
#pragma unroll
    for (int i = 0; i < 4; i++) { cp16(aS[i], aG[i], aSz[i]); cp16(wS[i], wG[i], 16); }
    asm volatile("cp.async.commit_group;");

    for (int c = 0; c < NCH; c++) {
        const int buf = c & 1;
        if (c + 1 < NCH) {
            const uint32_t bo = ((c + 1) & 1) ? bufStride : 0u;
            const int koff = (c + 1) * BK;
#pragma unroll
            for (int i = 0; i < 4; i++) {
                cp16(aS[i] + bo, aG[i] + koff, aSz[i]);
                cp16(wS[i] + bo, wG[i] + koff, 16);
            }
            asm volatile("cp.async.commit_group;");
            asm volatile("cp.async.wait_group 1;" ::: "memory");
        } else {
            asm volatile("cp.async.wait_group 0;" ::: "memory");
        }
        __syncthreads();

        const uint32_t bofs = buf ? bufStride : 0u;
#pragma unroll
        for (int ks = 0; ks < 4; ks++) {
            uint32_t afr[4][4], bfr[4][2];
#pragma unroll
            for (int mf = 0; mf < 4; mf++)
                ldsm_x4(afr[mf], a_lm + bofs + (uint32_t)(mf * 16 * SPH + ks * 16) * 2u);
#pragma unroll
            for (int np = 0; np < 2; np++)
                ldsm_x4(&bfr[2*np][0], b_lm + bofs + (uint32_t)(np * 16 * SPH + ks * 16) * 2u);
#pragma unroll
            for (int mf = 0; mf < 4; mf++)
#pragma unroll
                for (int nf = 0; nf < 4; nf++)
                    mma_f16(acc[mf][nf], afr[mf], bfr[nf]);
        }
        __syncthreads();
    }

    // ---- epilogue ----
    const int sec = (MODE == MODE_QKV) ? (n0 / CDIM) : 0;   // CTA-uniform
    __half* dsth = (MODE == MODE_QKV) ? ((sec == 0) ? qh : (sec == 1) ? kh : vh)
                                      : outH;

#pragma unroll
    for (int mf = 0; mf < 4; mf++) {
        int r0 = m0 + wm * 64 + mf * 16 + qid;
        int r1 = r0 + 8;
#pragma unroll
        for (int nf = 0; nf < 4; nf++) {
            int col = n0 + wn * 32 + nf * 8 + 2 * lid;
            float2 bv = *(const float2*)&bias[col];
            if constexpr (MODE == MODE_RES) {
                if (r0 < M) {
                    float* op = outF + (size_t)r0 * N + col;
                    float2 v = make_float2(acc[mf][nf][0] + bv.x, acc[mf][nf][1] + bv.y);
                    if (residual) { float2 o2 = *(const float2*)op; v.x += o2.x; v.y += o2.y; }
                    *(float2*)op = v;
                }
                if (r1 < M) {
                    float* op = outF + (size_t)r1 * N + col;
                    float2 v = make_float2(acc[mf][nf][2] + bv.x, acc[mf][nf][3] + bv.y);
                    if (residual) { float2 o2 = *(const float2*)op; v.x += o2.x; v.y += o2.y; }
                    *(float2*)op = v;
                }
            } else if constexpr (MODE == MODE_H16) {
                if (r0 < M) {
                    __half2* op = (__half2*)(dsth + (size_t)r0 * N + col);
                    *op = __floats2half2_rn(acc[mf][nf][0] + bv.x, acc[mf][nf][1] + bv.y);
                }
                if (r1 < M) {
                    __half2* op = (__half2*)(dsth + (size_t)r1 * N + col);
                    *op = __floats2half2_rn(acc[mf][nf][2] + bv.x, acc[mf][nf][3] + bv.y);
                }
            } else {
                // MODE_QKV: fused bias + RoPE + scale, scatter to per-head layout
                int cc = col - sec * CDIM;
                int h  = cc >> 6, d0 = cc & 63;
#pragma unroll
                for (int rr = 0; rr < 2; rr++) {
                    int t = rr ? r1 : r0;
                    if (t >= M) continue;
                    int b = t / NTOK, n = t - b * NTOK;
                    float v0 = acc[mf][nf][2*rr]     + bv.x;
                    float v1 = acc[mf][nf][2*rr + 1] + bv.y;
                    if (sec < 2 && n > 0) {
                        const float* rp = rope + (size_t)(n - 1) * (2*HDIM);
                        float2 sv = *(const float2*)&rp[d0];
                        float2 cv = *(const float2*)&rp[HDIM + d0];
                        float t0 = v0 * cv.x - v1 * sv.x;
                        float t1 = v1 * cv.y + v0 * sv.y;
                        v0 = t0; v1 = t1;
                    }
                    if (sec == 0) { v0 *= SCALE; v1 *= SCALE; }
                    size_t ob = ((size_t)(b * NH + h)) * NPAD * HDIM
                              + (size_t)n * HDIM + d0;
                    *(__half2*)&dsth[ob] = __floats2half2_rn(v0, v1);
                }
            }
        }
    }
}

// ---------------- block reduction helper ----------------
__device__ __forceinline__ float2 block_sum2(float2 v) {
    __shared__ float2 red[8];
    int lane = threadIdx.x & 31, warp = threadIdx.x >> 5;
#pragma unroll
    for (int off = 16; off; off >>= 1) {
        v.x += __shfl_xor_sync(0xffffffffu, v.x, off);
        v.y += __shfl_xor_sync(0xffffffffu, v.y, off);
    }
    if (lane == 0) red[warp] = v;
    __syncthreads();
    if (warp == 0) {
        float2 w = (lane < 8) ? red[lane] : make_float2(0.f, 0.f);
#pragma unroll
        for (int off = 4; off; off >>= 1) {
            w.x += __shfl_xor_sync(0xffffffffu, w.x, off);
            w.y += __shfl_xor_sync(0xffffffffu, w.y, off);
        }
        if (lane == 0) red[0] = w;
    }
    __syncthreads();
    return red[0];
}

// ---------------- LayerNorm (fp32 in, fp16 out) ----------
template <int CD>
__global__ __launch_bounds__(256) void ln_kernel(
    const float* __restrict__ in, const float* __restrict__ gamma,
    const float* __restrict__ beta, __half* __restrict__ out)
{
    constexpr int PER = CD / 256;
    const size_t base = (size_t)blockIdx.x * CD;
    float v[PER];
    float2 s = make_float2(0.f, 0.f);
#pragma unroll
    for (int i = 0; i < PER; i++) {
        v[i] = in[base + i*256 + threadIdx.x];
        s.x += v[i]; s.y += v[i]*v[i];
    }
    s = block_sum2(s);
    float mean = s.x * (1.f / CD);
    float var  = s.y * (1.f / CD) - mean * mean;
    float inv  = rsqrtf(var + EPS);
#pragma unroll
    for (int i = 0; i < PER; i++) {
        int c = i*256 + threadIdx.x;
        out[base + c] = __float2half_rn((v[i] - mean) * inv * gamma[c] + beta[c]);
    }
}

// ---------------- SwiGLU + inner LayerNorm (fp16 gu in, fp16 out) ------------
__global__ __launch_bounds__(256) void swiglu_ln_kernel(
    const __half* __restrict__ GU,
    const float* __restrict__ gamma, const float* __restrict__ beta,
    __half* __restrict__ out)
{
    const size_t base = (size_t)blockIdx.x * 2 * HF;
    float u[8];
    float2 s = make_float2(0.f, 0.f);
#pragma unroll
    for (int i = 0; i < 8; i++) {
        int c = i*256 + threadIdx.x;
        float g = __half2float(GU[base + c]);
        float x = __half2float(GU[base + HF + c]);
        float uu = (g / (1.f + __expf(-g))) * x;
        u[i] = uu; s.x += uu; s.y += uu*uu;
    }
    s = block_sum2(s);
    float mean = s.x * (1.f / HF);
    float var  = s.y * (1.f / HF) - mean * mean;
    float inv  = rsqrtf(var + EPS);
#pragma unroll
    for (int i = 0; i < 8; i++) {
        int c = i*256 + threadIdx.x;
        out[(size_t)blockIdx.x * HF + c] =
            __float2half_rn((u[i] - mean) * inv * gamma[c] + beta[c]);
    }
}

// ---------------- bias builders ----------------
__global__ void bias3_kernel(float* __restrict__ bias3,
                             const float* __restrict__ qb,
                             const float* __restrict__ vb)
{
    int idx = blockIdx.x * blockDim.x + threadIdx.x;
    if (idx >= LNUM * C3) return;
    int l = idx / C3, j = idx % C3;
    float v = 0.f;
    if (j < CDIM)         v = qb[l*CDIM + j];
    else if (j >= 2*CDIM) v = vb[l*CDIM + (j - 2*CDIM)];
    bias3[idx] = v;
}
__global__ void biasgu_kernel(float* __restrict__ bgu,
                              const float* __restrict__ bg,
                              const float* __restrict__ bx)
{
    int idx = blockIdx.x * blockDim.x + threadIdx.x;
    if (idx >= LNUM * 2 * HF) return;
    int l = idx / (2*HF), j = idx % (2*HF);
    bgu[idx] = (j < HF) ? bg[l*HF + j] : bx[l*HF + (j - HF)];
}

// ---------------- tensor-core attention: one CTA per (b,h), 128 thr, 2/SM ----
#define AP 72                                 // smem pitch (halves)
#define NT8 (NPAD/8)                          // 26 n8 tiles
#define ATTN_TC_SMEM (3 * NPAD * AP * 2)      // 89856 B

__global__ __launch_bounds__(128, 2) void attn_tc_kernel(
    const __half* __restrict__ qh, const __half* __restrict__ kh,
    const __half* __restrict__ vh, __half* __restrict__ o)
{
    extern __shared__ __half sm2[];
    __half* Qs = sm2;
    __half* Ks = Qs + NPAD*AP;
    __half* Vs = Ks + NPAD*AP;

    const int bh = blockIdx.x, b = bh / NH, h = bh % NH;
    const int tid = threadIdx.x, warp = tid >> 5, lane = tid & 31;
    const int qid = lane >> 2, lid = lane & 3;

    const __half* qg = qh + (size_t)bh * NPAD * HDIM;
    const __half* kg = kh + (size_t)bh * NPAD * HDIM;
    const __half* vg = vh + (size_t)bh * NPAD * HDIM;
    const uint32_t qsb = smem_addr_u32(Qs);
    const uint32_t ksb = smem_addr_u32(Ks);
    const uint32_t vsb = smem_addr_u32(Vs);

    for (int i = tid; i < NPAD * 8; i += 128) {
        int r = i >> 3, s = i & 7;
        uint32_t off = (uint32_t)(r * AP + s * 8) * 2u;
        const int gofs = r * HDIM + s * 8;
        cp16(qsb + off, qg + gofs, 16);
        cp16(ksb + off, kg + gofs, 16);
        cp16(vsb + off, vg + gofs, 16);
    }
    asm volatile("cp.async.commit_group;");
    asm volatile("cp.async.wait_group 0;" ::: "memory");
    __syncthreads();

    const uint32_t a_base = qsb + (uint32_t)(((lane & 15) * AP) + (lane >> 4) * 8) * 2u;
    const uint32_t k_base = ksb + (uint32_t)((((lane >> 4) & 1) * 8 + (lane & 7)) * AP
                                             + ((lane >> 3) & 1) * 8) * 2u;
    const uint32_t v_base = vsb + (uint32_t)((((lane >> 3) & 1) * 8 + (lane & 7)) * AP
                                             + (lane >> 4) * 8) * 2u;

    for (int mt = warp; mt < NPAD/16; mt += 4) {
        const int m0 = mt * 16;
        uint32_t afr[4][4];
#pragma unroll
        for (int ks = 0; ks < 4; ks++)
            ldsm_x4(afr[ks], a_base + (uint32_t)(m0 * AP + ks * 16) * 2u);
        float acc[NT8][4];
#pragma unroll
        for (int nb = 0; nb < NT8; nb++)
#pragma unroll
            for (int q = 0; q < 4; q++) acc[nb][q] = 0.f;
#pragma unroll
        for (int ks = 0; ks < 4; ks++) {
#pragma unroll
            for (int np = 0; np < NT8/2; np++) {
                uint32_t bfr[4];
                ldsm_x4(bfr, k_base + (uint32_t)(np * 16 * AP + ks * 16) * 2u);
                mma_f16(acc[2*np],     afr[ks], bfr);
                mma_f16(acc[2*np + 1], afr[ks], bfr + 2);
            }
        }
        float mx0 = -1e30f, mx1 = -1e30f;
#pragma unroll
        for (int nb = 0; nb < NT8; nb++) {
#pragma unroll
            for (int e = 0; e < 2; e++) {
                int col = nb * 8 + 2 * lid + e;
                if (col < NTOK) {
                    mx0 = fmaxf(mx0, acc[nb][e]);
                    mx1 = fmaxf(mx1, acc[nb][2 + e]);
                }
            }
        }
        mx0 = fmaxf(mx0, __shfl_xor_sync(0xffffffffu, mx0, 1));
        mx0 = fmaxf(mx0, __shfl_xor_sync(0xffffffffu, mx0, 2));
        mx1 = fmaxf(mx1, __shfl_xor_sync(0xffffffffu, mx1, 1));
        mx1 = fmaxf(mx1, __shfl_xor_sync(0xffffffffu, mx1, 2));
        float sum0 = 0.f, sum1 = 0.f;
#pragma unroll
        for (int nb = 0; nb < NT8; nb++) {
#pragma unroll
            for (int e = 0; e < 2; e++) {
                int col = nb * 8 + 2 * lid + e;
                float p0 = (col < NTOK) ? __expf(acc[nb][e] - mx0) : 0.f;
                float p1 = (col < NTOK) ? __expf(acc[nb][2 + e] - mx1) : 0.f;
                acc[nb][e] = p0; acc[nb][2 + e] = p1;
                sum0 += p0; sum1 += p1;
            }
        }
        sum0 += __shfl_xor_sync(0xffffffffu, sum0, 1);
        sum0 += __shfl_xor_sync(0xffffffffu, sum0, 2);
        sum1 += __shfl_xor_sync(0xffffffffu, sum1, 1);
        sum1 += __shfl_xor_sync(0xffffffffu, sum1, 2);
        float oacc[8][4];
#pragma unroll
        for (int db = 0; db < 8; db++)
#pragma unroll
            for (int q = 0; q < 4; q++) oacc[db][q] = 0.f;
#pragma unroll
        for (int t = 0; t < NPAD/16; t++) {
            uint32_t pa[4];
            pa[0] = h2u(__floats2half2_rn(acc[2*t][0],   acc[2*t][1]));
            pa[1] = h2u(__floats2half2_rn(acc[2*t][2],   acc[2*t][3]));
            pa[2] = h2u(__floats2half2_rn(acc[2*t+1][0], acc[2*t+1][1]));
            pa[3] = h2u(__floats2half2_rn(acc[2*t+1][2], acc[2*t+1][3]));
#pragma unroll
            for (int dp = 0; dp < 4; dp++) {
                uint32_t bfr[4];
                ldsm_x4_t(bfr, v_base + (uint32_t)(t * 16 * AP + dp * 16) * 2u);
                mma_f16(oacc[2*dp],     pa, bfr);
                mma_f16(oacc[2*dp + 1], pa, bfr + 2);
            }
        }
        float i0 = 1.f / sum0, i1 = 1.f / sum1;
        int r0 = m0 + qid, r1 = r0 + 8;
#pragma unroll
        for (int db = 0; db < 8; db++) {
            int col = h * HDIM + db * 8 + 2 * lid;
            if (r0 < NTOK) {
                __half2 v = __floats2half2_rn(oacc[db][0] * i0, oacc[db][1] * i0);
                *(__half2*)&o[((size_t)(b * NTOK + r0)) * CDIM + col] = v;
            }
            if (r1 < NTOK) {
                __half2 v = __floats2half2_rn(oacc[db][2] * i1, oacc[db][3] * i1);
                *(__half2*)&o[((size_t)(b * NTOK + r1)) * CDIM + col] = v;
            }
        }
    }
}

// ---------------- host orchestration ----------------
extern "C" void kernel_launch(void* const* d_in, const int* in_sizes, int n_in,
                              void* d_out, int out_size)
{
    const float* x      = (const float*)d_in[0];
    const float* rope   = (const float*)d_in[1];
    const float* qkv_w  = (const float*)d_in[2];
    const float* q_bias = (const float*)d_in[3];
    const float* v_bias = (const float*)d_in[4];
    const float* proj_w = (const float*)d_in[5];
    const float* proj_b = (const float*)d_in[6];
    const float* n1_g   = (const float*)d_in[7];
    const float* n1_b   = (const float*)d_in[8];
    const float* n2_g   = (const float*)d_in[9];
    const float* n2_b   = (const float*)d_in[10];
    const float* w1g    = (const float*)d_in[11];
    const float* b1g    = (const float*)d_in[12];
    const float* w1x    = (const float*)d_in[13];
    const float* b1x    = (const float*)d_in[14];
    const float* nm_g   = (const float*)d_in[15];
    const float* nm_b   = (const float*)d_in[16];
    const float* w2     = (const float*)d_in[17];
    const float* b2     = (const float*)d_in[18];
    float* out = (float*)d_out;

    __half *y, *o, *u, *gu, *wc, *qh, *kh, *vh;
    float *bias3, *bgu;
    cudaGetSymbolAddress((void**)&y,     g_y);
    cudaGetSymbolAddress((void**)&o,     g_o);
    cudaGetSymbolAddress((void**)&u,     g_u);
    cudaGetSymbolAddress((void**)&gu,    g_gu);
    cudaGetSymbolAddress((void**)&bias3, g_bias3);
    cudaGetSymbolAddress((void**)&bgu,   g_bgu);
    cudaGetSymbolAddress((void**)&wc,    g_wc);
    cudaGetSymbolAddress((void**)&qh,    g_qh);
    cudaGetSymbolAddress((void**)&kh,    g_kh);
    cudaGetSymbolAddress((void**)&vh,    g_vh);

    __half* qkvw_c  = wc + WC_QKV;
    __half* projw_c = wc + WC_PROJ;
    __half* guw_c   = wc + WC_GU;
    __half* w2_c    = wc + WC_W2;

    cudaFuncSetAttribute(tc_gemm<MODE_RES>,
        cudaFuncAttributeMaxDynamicSharedMemorySize, GEMM_SMEM);
    cudaFuncSetAttribute(tc_gemm<MODE_H16>,
        cudaFuncAttributeMaxDynamicSharedMemorySize, GEMM_SMEM);
    cudaFuncSetAttribute(tc_gemm<MODE_QKV>,
        cudaFuncAttributeMaxDynamicSharedMemorySize, GEMM_SMEM);
    cudaFuncSetAttribute(attn_tc_kernel,
        cudaFuncAttributeMaxDynamicSharedMemorySize, ATTN_TC_SMEM);

    cudaMemcpyAsync(out, x, (size_t)TTOK * CDIM * sizeof(float),
                    cudaMemcpyDeviceToDevice);

    // pre-convert weights to fp16; pack [w1g;w1x] per layer for fused GEMM
    {
        int n;
        n = LNUM*C3*CDIM/4;   cvth_kernel<<<(n+255)/256, 256>>>(qkv_w,  qkvw_c,  n);
        n = LNUM*CDIM*CDIM/4; cvth_kernel<<<(n+255)/256, 256>>>(proj_w, projw_c, n);
        n = HF*CDIM/4;
        for (int l = 0; l < LNUM; l++) {
            cvth_kernel<<<(n+255)/256, 256>>>(
                w1g + (size_t)l*HF*CDIM, guw_c + (size_t)l*2*HF*CDIM, n);
            cvth_kernel<<<(n+255)/256, 256>>>(
                w1x + (size_t)l*HF*CDIM, guw_c + (size_t)l*2*HF*CDIM + (size_t)HF*CDIM, n);
        }
        n = LNUM*CDIM*HF/4;   cvth_kernel<<<(n+255)/256, 256>>>(w2, w2_c, n);
    }

    bias3_kernel<<<(LNUM*C3 + 255)/256, 256>>>(bias3, q_bias, v_bias);
    biasgu_kernel<<<(LNUM*2*HF + 255)/256, 256>>>(bgu, b1g, b1x);
    {
        int n = BB * NH * (NPAD - NTOK) * HDIM / 2;
        padzero_kernel<<<(n + 255)/256, 256>>>(qh, kh, vh);
    }

    const int MB = (TTOK + BM - 1) / BM;     // 99

    for (int l = 0; l < LNUM; l++) {
        ln_kernel<CDIM><<<TTOK, 256>>>(out, n1_g + l*CDIM, n1_b + l*CDIM, y);
        tc_gemm<MODE_QKV><<<dim3(C3/BN, MB), 256, GEMM_SMEM>>>(
            y, qkvw_c + (size_t)l*C3*CDIM, bias3 + l*C3,
            nullptr, nullptr, rope, qh, kh, vh, TTOK, C3, CDIM, 0);
        attn_tc_kernel<<<BB*NH, 128, ATTN_TC_SMEM>>>(qh, kh, vh, o);
        tc_gemm<MODE_RES><<<dim3(CDIM/BN, MB), 256, GEMM_SMEM>>>(
            o, projw_c + (size_t)l*CDIM*CDIM, proj_b + l*CDIM,
            out, nullptr, nullptr, nullptr, nullptr, nullptr, TTOK, CDIM, CDIM, 1);

        ln_kernel<CDIM><<<TTOK, 256>>>(out, n2_g + l*CDIM, n2_b + l*CDIM, y);
        tc_gemm<MODE_H16><<<dim3(2*HF/BN, MB), 256, GEMM_SMEM>>>(
            y, guw_c + (size_t)l*2*HF*CDIM, bgu + l*2*HF,
            nullptr, gu, nullptr, nullptr, nullptr, nullptr, TTOK, 2*HF, CDIM, 0);
        swiglu_ln_kernel<<<TTOK, 256>>>(gu, nm_g + l*HF, nm_b + l*HF, u);
        tc_gemm<MODE_RES><<<dim3(CDIM/BN, MB), 256, GEMM_SMEM>>>(
            u, w2_c + (size_t)l*CDIM*HF, b2 + l*CDIM,
            out, nullptr, nullptr, nullptr, nullptr, nullptr, TTOK, CDIM, HF, 1);
    }
}

// round 17
// speedup vs baseline: 7.1122x; 1.0801x over previous
#include <cuda_runtime.h>
#include <cuda_fp16.h>
#include <cstdint>
#include <cstddef>
#include <cstring>

// ---------------- problem constants ----------------
#define LNUM 4
#define BB   64
#define NTOK 197
#define CDIM 768
#define NH   12
#define HDIM 64
#define HF   2048
#define C3   (3*CDIM)
#define TTOK (BB*NTOK)          // 12608
#define SCALE 0.125f
#define EPS 1e-6f
#define NPAD 208                // 197 padded to multiple of 16

// ---------------- scratch (device globals: no allocs allowed) ----------------
__device__ __half g_y   [(size_t)TTOK*CDIM];     // fp16 GEMM A operands
__device__ __half g_o   [(size_t)TTOK*CDIM];
__device__ __half g_u   [(size_t)TTOK*HF];
__device__ __half g_gu  [(size_t)TTOK*2*HF];     // fused gate|up output
__device__ float  g_bias3[LNUM*C3];
__device__ float  g_bgu [LNUM*2*HF];
// packed fp16 attention operands, per (b,h): [NPAD][64], pad rows zeroed
__device__ __half g_qh[(size_t)BB*NH*NPAD*HDIM];
__device__ __half g_kh[(size_t)BB*NH*NPAD*HDIM];
__device__ __half g_vh[(size_t)BB*NH*NPAD*HDIM];

// pre-converted fp16 weights: qkv | proj | [w1g;w1x] packed | w2
#define WC_QKV  0
#define WC_PROJ ((size_t)LNUM*C3*CDIM)
#define WC_GU   (WC_PROJ + (size_t)LNUM*CDIM*CDIM)
#define WC_W2   (WC_GU + (size_t)LNUM*2*HF*CDIM)
#define WC_TOT  (WC_W2 + (size_t)LNUM*CDIM*HF)
__device__ __half g_wc[WC_TOT];

// ---------------- weight fp32 -> fp16 conversion ----------------
__global__ __launch_bounds__(256) void cvth_kernel(
    const float* __restrict__ in, __half* __restrict__ out, int n4)
{
    int i = blockIdx.x * blockDim.x + threadIdx.x;
    if (i >= n4) return;
    float4 v = ((const float4*)in)[i];
    ((__half2*)out)[2*i]   = __floats2half2_rn(v.x, v.y);
    ((__half2*)out)[2*i+1] = __floats2half2_rn(v.z, v.w);
}

// ---------------- one-time pad-row zeroing for qh/kh/vh ----------------
__global__ void padzero_kernel(__half* __restrict__ qh, __half* __restrict__ kh,
                               __half* __restrict__ vh)
{
    const int perbh = (NPAD - NTOK) * HDIM / 2;      // 352 half2 per (b,h)
    int idx = blockIdx.x * blockDim.x + threadIdx.x;
    if (idx >= BB * NH * perbh) return;
    int bh = idx / perbh, r = idx % perbh;
    size_t off = (size_t)bh * NPAD * HDIM + (size_t)NTOK * HDIM + (size_t)r * 2;
    *(uint32_t*)&qh[off] = 0; *(uint32_t*)&kh[off] = 0; *(uint32_t*)&vh[off] = 0;
}

// ================= shared PTX helpers =================
__device__ __forceinline__ uint32_t h2u(__half2 h) {
    uint32_t u; memcpy(&u, &h, 4); return u;
}
__device__ __forceinline__ uint32_t smem_addr_u32(const void* p) {
    uint32_t a;
    asm("{ .reg .u64 t; cvta.to.shared.u64 t, %1; cvt.u32.u64 %0, t; }"
        : "=r"(a) : "l"(p));
    return a;
}
__device__ __forceinline__ void cp16(uint32_t dst, const void* src, int sz) {
    asm volatile("cp.async.cg.shared.global [%0], [%1], 16, %2;"
                 :: "r"(dst), "l"(__cvta_generic_to_global(src)), "r"(sz));
}
__device__ __forceinline__ void ldsm_x4(uint32_t* r, uint32_t addr) {
    asm volatile("ldmatrix.sync.aligned.m8n8.x4.shared.b16 {%0,%1,%2,%3}, [%4];"
        : "=r"(r[0]), "=r"(r[1]), "=r"(r[2]), "=r"(r[3]) : "r"(addr));
}
__device__ __forceinline__ void ldsm_x4_t(uint32_t* r, uint32_t addr) {
    asm volatile("ldmatrix.sync.aligned.m8n8.x4.trans.shared.b16 {%0,%1,%2,%3}, [%4];"
        : "=r"(r[0]), "=r"(r[1]), "=r"(r[2]), "=r"(r[3]) : "r"(addr));
}
__device__ __forceinline__ void mma_f16(float* d, const uint32_t* a, const uint32_t* b) {
    asm volatile(
        "mma.sync.aligned.m16n8k16.row.col.f32.f16.f16.f32 "
        "{%0,%1,%2,%3}, {%4,%5,%6,%7}, {%8,%9}, {%0,%1,%2,%3};"
        : "+f"(d[0]), "+f"(d[1]), "+f"(d[2]), "+f"(d[3])
        : "r"(a[0]), "r"(a[1]), "r"(a[2]), "r"(a[3]), "r"(b[0]), "r"(b[1]));
}

// ================= fp16 mma.sync GEMM (m16n8k16) + ldmatrix =================
// MODE_RES: float out (+residual); gridDim.z>1 => split-K atomic accumulate.
// MODE_H16: half out. MODE_QKV: fused RoPE+scale scatter to per-head layouts.
#define MODE_RES 0
#define MODE_H16 1
#define MODE_QKV 2
#define BM 128
#define BN 128
#define BK 64
#define SPH   72
#define BUFH  (BM * SPH)
#define GEMM_SMEM (4 * BUFH * 2)

template <int MODE>
__global__ __launch_bounds__(256, 2) void tc_gemm(
    const __half* __restrict__ A, const __half* __restrict__ W,
    const float* __restrict__ bias,
    float* __restrict__ outF, __half* __restrict__ outH,
    const float* __restrict__ rope,
    __half* __restrict__ qh, __half* __restrict__ kh, __half* __restrict__ vh,
    int M, int N, int K, int residual)
{
    extern __shared__ __half sm[];
    __half* As0 = sm;
    __half* Ws0 = sm + BUFH;

    const int tid  = threadIdx.x;
    const int wid  = tid >> 5, lane = tid & 31;
    const int wm   = wid & 1;
    const int wn   = wid >> 1;
    const int qid  = lane >> 2;
    const int lid  = lane & 3;
    const int m0   = blockIdx.y * BM, n0 = blockIdx.x * BN;

    // split-K: this CTA covers K range [k0g, k0g+kLen)
    const int kLen = K / gridDim.z;
    const int k0g  = blockIdx.z * kLen;

    uint32_t aS[4], wS[4];
    const __half* aG[4]; const __half* wG[4]; int aSz[4];
#pragma unroll
    for (int i = 0; i < 4; i++) {
        int g = tid + i * 256;
        int r = g >> 3, s = g & 7;
        uint32_t off = (uint32_t)(r * SPH + s * 8) * 2u;
        aS[i] = smem_addr_u32(As0) + off;
        wS[i] = smem_addr_u32(Ws0) + off;
        int arow = m0 + r;
        int ok = arow < M;
        aSz[i] = ok ? 16 : 0;
        aG[i]  = A + (size_t)(ok ? arow : 0) * K + k0g + s * 8;
        wG[i]  = W + (size_t)(n0 + r) * K + k0g + s * 8;
    }
    const uint32_t bufStride = (uint32_t)(2 * BUFH) * 2u;

    const uint32_t a_lm = smem_addr_u32(
        As0 + (size_t)(wm * 64 + (lane & 15)) * SPH + (lane >> 4) * 8);
    const uint32_t b_lm = smem_addr_u32(
        Ws0 + (size_t)(wn * 32 + ((lane >> 4) & 1) * 8 + (lane & 7)) * SPH
            + ((lane >> 3) & 1) * 8);

    float acc[4][4][4];
#pragma unroll
    for (int mf = 0; mf < 4; mf++)
#pragma unroll
        for (int nf = 0; nf < 4; nf++)
#pragma unroll
            for (int q = 0; q < 4; q++) acc[mf][nf][q] = 0.f;

    const int NCH = kLen / BK;
#pragma unroll
    for (int i = 0; i < 4; i++) { cp16(aS[i], aG[i], aSz[i]); cp16(wS[i], wG[i], 16); }
    asm volatile("cp.async.commit_group;");

    for (int c = 0; c < NCH; c++) {
        const int buf = c & 1;
        if (c + 1 < NCH) {
            const uint32_t bo = ((c + 1) & 1) ? bufStride : 0u;
            const int koff = (c + 1) * BK;
#pragma unroll
            for (int i = 0; i < 4; i++) {
                cp16(aS[i] + bo, aG[i] + koff, aSz[i]);
                cp16(wS[i] + bo, wG[i] + koff, 16);
            }
            asm volatile("cp.async.commit_group;");
            asm volatile("cp.async.wait_group 1;" ::: "memory");
        } else {
            asm volatile("cp.async.wait_group 0;" ::: "memory");
        }
        __syncthreads();

        const uint32_t bofs = buf ? bufStride : 0u;
#pragma unroll
        for (int ks = 0; ks < 4; ks++) {
            uint32_t afr[4][4], bfr[4][2];
#pragma unroll
            for (int mf = 0; mf < 4; mf++)
                ldsm_x4(afr[mf], a_lm + bofs + (uint32_t)(mf * 16 * SPH + ks * 16) * 2u);
#pragma unroll
            for (int np = 0; np < 2; np++)
                ldsm_x4(&bfr[2*np][0], b_lm + bofs + (uint32_t)(np * 16 * SPH + ks * 16) * 2u);
#pragma unroll
            for (int mf = 0; mf < 4; mf++)
#pragma unroll
                for (int nf = 0; nf < 4; nf++)
                    mma_f16(acc[mf][nf], afr[mf], bfr[nf]);
        }
        __syncthreads();
    }

    // ---- epilogue ----
    const int sec = (MODE == MODE_QKV) ? (n0 / CDIM) : 0;   // CTA-uniform
    __half* dsth = (MODE == MODE_QKV) ? ((sec == 0) ? qh : (sec == 1) ? kh : vh)
                                      : outH;
    const bool splitk = (gridDim.z > 1);
    const float bscale = (splitk && blockIdx.z != 0) ? 0.f : 1.f;

#pragma unroll
    for (int mf = 0; mf < 4; mf++) {
        int r0 = m0 + wm * 64 + mf * 16 + qid;
        int r1 = r0 + 8;
#pragma unroll
        for (int nf = 0; nf < 4; nf++) {
            int col = n0 + wn * 32 + nf * 8 + 2 * lid;
            float2 bv = *(const float2*)&bias[col];
            if constexpr (MODE == MODE_RES) {
                if (!splitk) {
                    if (r0 < M) {
                        float* op = outF + (size_t)r0 * N + col;
                        float2 v = make_float2(acc[mf][nf][0] + bv.x, acc[mf][nf][1] + bv.y);
                        if (residual) { float2 o2 = *(const float2*)op; v.x += o2.x; v.y += o2.y; }
                        *(float2*)op = v;
                    }
                    if (r1 < M) {
                        float* op = outF + (size_t)r1 * N + col;
                        float2 v = make_float2(acc[mf][nf][2] + bv.x, acc[mf][nf][3] + bv.y);
                        if (residual) { float2 o2 = *(const float2*)op; v.x += o2.x; v.y += o2.y; }
                        *(float2*)op = v;
                    }
                } else {
                    // split-K: out already holds the residual; accumulate atomically
                    if (r0 < M) {
                        float* op = outF + (size_t)r0 * N + col;
                        atomicAdd(op,     acc[mf][nf][0] + bv.x * bscale);
                        atomicAdd(op + 1, acc[mf][nf][1] + bv.y * bscale);
                    }
                    if (r1 < M) {
                        float* op = outF + (size_t)r1 * N + col;
                        atomicAdd(op,     acc[mf][nf][2] + bv.x * bscale);
                        atomicAdd(op + 1, acc[mf][nf][3] + bv.y * bscale);
                    }
                }
            } else if constexpr (MODE == MODE_H16) {
                if (r0 < M) {
                    __half2* op = (__half2*)(dsth + (size_t)r0 * N + col);
                    *op = __floats2half2_rn(acc[mf][nf][0] + bv.x, acc[mf][nf][1] + bv.y);
                }
                if (r1 < M) {
                    __half2* op = (__half2*)(dsth + (size_t)r1 * N + col);
                    *op = __floats2half2_rn(acc[mf][nf][2] + bv.x, acc[mf][nf][3] + bv.y);
                }
            } else {
                // MODE_QKV: fused bias + RoPE + scale, scatter to per-head layout
                int cc = col - sec * CDIM;
                int h  = cc >> 6, d0 = cc & 63;
#pragma unroll
                for (int rr = 0; rr < 2; rr++) {
                    int t = rr ? r1 : r0;
                    if (t >= M) continue;
                    int b = t / NTOK, n = t - b * NTOK;
                    float v0 = acc[mf][nf][2*rr]     + bv.x;
                    float v1 = acc[mf][nf][2*rr + 1] + bv.y;
                    if (sec < 2 && n > 0) {
                        const float* rp = rope + (size_t)(n - 1) * (2*HDIM);
                        float2 sv = *(const float2*)&rp[d0];
                        float2 cv = *(const float2*)&rp[HDIM + d0];
                        float t0 = v0 * cv.x - v1 * sv.x;
                        float t1 = v1 * cv.y + v0 * sv.y;
                        v0 = t0; v1 = t1;
                    }
                    if (sec == 0) { v0 *= SCALE; v1 *= SCALE; }
                    size_t ob = ((size_t)(b * NH + h)) * NPAD * HDIM
                              + (size_t)n * HDIM + d0;
                    *(__half2*)&dsth[ob] = __floats2half2_rn(v0, v1);
                }
            }
        }
    }
}

// ---------------- block reduction helper ----------------
__device__ __forceinline__ float2 block_sum2(float2 v) {
    __shared__ float2 red[8];
    int lane = threadIdx.x & 31, warp = threadIdx.x >> 5;
#pragma unroll
    for (int off = 16; off; off >>= 1) {
        v.x += __shfl_xor_sync(0xffffffffu, v.x, off);
        v.y += __shfl_xor_sync(0xffffffffu, v.y, off);
    }
    if (lane == 0) red[warp] = v;
    __syncthreads();
    if (warp == 0) {
        float2 w = (lane < 8) ? red[lane] : make_float2(0.f, 0.f);
#pragma unroll
        for (int off = 4; off; off >>= 1) {
            w.x += __shfl_xor_sync(0xffffffffu, w.x, off);
            w.y += __shfl_xor_sync(0xffffffffu, w.y, off);
        }
        if (lane == 0) red[0] = w;
    }
    __syncthreads();
    return red[0];
}

// ---------------- LayerNorm: warp-per-row, float4 loads, shfl-only ----------
template <int CD>
__global__ __launch_bounds__(256) void ln_kernel(
    const float* __restrict__ in, const float* __restrict__ gamma,
    const float* __restrict__ beta, __half* __restrict__ out)
{
    constexpr int PL = CD / 128;                 // float4 per lane (6 for 768)
    const int warp = threadIdx.x >> 5, lane = threadIdx.x & 31;
    const int row = blockIdx.x * 8 + warp;
    if (row >= TTOK) return;
    const float4* rp = (const float4*)(in + (size_t)row * CD);
    float4 v[PL];
    float s = 0.f, s2 = 0.f;
#pragma unroll
    for (int i = 0; i < PL; i++) {
        v[i] = rp[lane + 32*i];
        s  += v[i].x + v[i].y + v[i].z + v[i].w;
        s2 += v[i].x*v[i].x + v[i].y*v[i].y + v[i].z*v[i].z + v[i].w*v[i].w;
    }
#pragma unroll
    for (int off = 16; off; off >>= 1) {
        s  += __shfl_xor_sync(0xffffffffu, s,  off);
        s2 += __shfl_xor_sync(0xffffffffu, s2, off);
    }
    float mean = s * (1.f / CD);
    float var  = s2 * (1.f / CD) - mean * mean;
    float inv  = rsqrtf(var + EPS);
    const float4* gp = (const float4*)gamma;
    const float4* bp = (const float4*)beta;
    __half2* op = (__half2*)(out + (size_t)row * CD);
#pragma unroll
    for (int i = 0; i < PL; i++) {
        float4 g = gp[lane + 32*i], b = bp[lane + 32*i];
        float o0 = (v[i].x - mean) * inv * g.x + b.x;
        float o1 = (v[i].y - mean) * inv * g.y + b.y;
        float o2 = (v[i].z - mean) * inv * g.z + b.z;
        float o3 = (v[i].w - mean) * inv * g.w + b.w;
        op[2*(lane + 32*i)]     = __floats2half2_rn(o0, o1);
        op[2*(lane + 32*i) + 1] = __floats2half2_rn(o2, o3);
    }
}

// ---------------- SwiGLU + inner LayerNorm (half2-vectorized) ----------------
__global__ __launch_bounds__(256) void swiglu_ln_kernel(
    const __half* __restrict__ GU,
    const float* __restrict__ gamma, const float* __restrict__ beta,
    __half* __restrict__ out)
{
    const size_t base = (size_t)blockIdx.x * 2 * HF;
    const __half2* gp = (const __half2*)(GU + base);
    const __half2* xp = (const __half2*)(GU + base + HF);
    float2 u2[4];
    float2 s = make_float2(0.f, 0.f);
#pragma unroll
    for (int i = 0; i < 4; i++) {
        int c = threadIdx.x + 256*i;
        float2 g = __half22float2(gp[c]);
        float2 x = __half22float2(xp[c]);
        float u0 = (g.x / (1.f + __expf(-g.x))) * x.x;
        float u1 = (g.y / (1.f + __expf(-g.y))) * x.y;
        u2[i] = make_float2(u0, u1);
        s.x += u0 + u1; s.y += u0*u0 + u1*u1;
    }
    s = block_sum2(s);
    float mean = s.x * (1.f / HF);
    float var  = s.y * (1.f / HF) - mean * mean;
    float inv  = rsqrtf(var + EPS);
    __half2* op = (__half2*)(out + (size_t)blockIdx.x * HF);
    const float2* g2 = (const float2*)gamma;
    const float2* b2 = (const float2*)beta;
#pragma unroll
    for (int i = 0; i < 4; i++) {
        int c = threadIdx.x + 256*i;
        float2 gm = g2[c], bt = b2[c];
        op[c] = __floats2half2_rn((u2[i].x - mean) * inv * gm.x + bt.x,
                                  (u2[i].y - mean) * inv * gm.y + bt.y);
    }
}

// ---------------- bias builders ----------------
__global__ void bias3_kernel(float* __restrict__ bias3,
                             const float* __restrict__ qb,
                             const float* __restrict__ vb)
{
    int idx = blockIdx.x * blockDim.x + threadIdx.x;
    if (idx >= LNUM * C3) return;
    int l = idx / C3, j = idx % C3;
    float v = 0.f;
    if (j < CDIM)         v = qb[l*CDIM + j];
    else if (j >= 2*CDIM) v = vb[l*CDIM + (j - 2*CDIM)];
    bias3[idx] = v;
}
__global__ void biasgu_kernel(float* __restrict__ bgu,
                              const float* __restrict__ bg,
                              const float* __restrict__ bx)
{
    int idx = blockIdx.x * blockDim.x + threadIdx.x;
    if (idx >= LNUM * 2 * HF) return;
    int l = idx / (2*HF), j = idx % (2*HF);
    bgu[idx] = (j < HF) ? bg[l*HF + j] : bx[l*HF + (j - HF)];
}

// ---------------- tensor-core attention: one CTA per (b,h), 128 thr, 2/SM ----
#define AP 72                                 // smem pitch (halves)
#define NT8 (NPAD/8)                          // 26 n8 tiles
#define ATTN_TC_SMEM (3 * NPAD * AP * 2)      // 89856 B

__global__ __launch_bounds__(128, 2) void attn_tc_kernel(
    const __half* __restrict__ qh, const __half* __restrict__ kh,
    const __half* __restrict__ vh, __half* __restrict__ o)
{
    extern __shared__ __half sm2[];
    __half* Qs = sm2;
    __half* Ks = Qs + NPAD*AP;
    __half* Vs = Ks + NPAD*AP;

    const int bh = blockIdx.x, b = bh / NH, h = bh % NH;
    const int tid = threadIdx.x, warp = tid >> 5, lane = tid & 31;
    const int qid = lane >> 2, lid = lane & 3;

    const __half* qg = qh + (size_t)bh * NPAD * HDIM;
    const __half* kg = kh + (size_t)bh * NPAD * HDIM;
    const __half* vg = vh + (size_t)bh * NPAD * HDIM;
    const uint32_t qsb = smem_addr_u32(Qs);
    const uint32_t ksb = smem_addr_u32(Ks);
    const uint32_t vsb = smem_addr_u32(Vs);

    for (int i = tid; i < NPAD * 8; i += 128) {
        int r = i >> 3, s = i & 7;
        uint32_t off = (uint32_t)(r * AP + s * 8) * 2u;
        const int gofs = r * HDIM + s * 8;
        cp16(qsb + off, qg + gofs, 16);
        cp16(ksb + off, kg + gofs, 16);
        cp16(vsb + off, vg + gofs, 16);
    }
    asm volatile("cp.async.commit_group;");
    asm volatile("cp.async.wait_group 0;" ::: "memory");
    __syncthreads();

    const uint32_t a_base = qsb + (uint32_t)(((lane & 15) * AP) + (lane >> 4) * 8) * 2u;
    const uint32_t k_base = ksb + (uint32_t)((((lane >> 4) & 1) * 8 + (lane & 7)) * AP
                                             + ((lane >> 3) & 1) * 8) * 2u;
    const uint32_t v_base = vsb + (uint32_t)((((lane >> 3) & 1) * 8 + (lane & 7)) * AP
                                             + (lane >> 4) * 8) * 2u;

    for (int mt = warp; mt < NPAD/16; mt += 4) {
        const int m0 = mt * 16;
        uint32_t afr[4][4];
#pragma unroll
        for (int ks = 0; ks < 4; ks++)
            ldsm_x4(afr[ks], a_base + (uint32_t)(m0 * AP + ks * 16) * 2u);
        float acc[NT8][4];
#pragma unroll
        for (int nb = 0; nb < NT8; nb++)
#pragma unroll
            for (int q = 0; q < 4; q++) acc[nb][q] = 0.f;
#pragma unroll
        for (int ks = 0; ks < 4; ks++) {
#pragma unroll
            for (int np = 0; np < NT8/2; np++) {
                uint32_t bfr[4];
                ldsm_x4(bfr, k_base + (uint32_t)(np * 16 * AP + ks * 16) * 2u);
                mma_f16(acc[2*np],     afr[ks], bfr);
                mma_f16(acc[2*np + 1], afr[ks], bfr + 2);
            }
        }
        float mx0 = -1e30f, mx1 = -1e30f;
#pragma unroll
        for (int nb = 0; nb < NT8; nb++) {
#pragma unroll
            for (int e = 0; e < 2; e++) {
                int col = nb * 8 + 2 * lid + e;
                if (col < NTOK) {
                    mx0 = fmaxf(mx0, acc[nb][e]);
                    mx1 = fmaxf(mx1, acc[nb][2 + e]);
                }
            }
        }
        mx0 = fmaxf(mx0, __shfl_xor_sync(0xffffffffu, mx0, 1));
        mx0 = fmaxf(mx0, __shfl_xor_sync(0xffffffffu, mx0, 2));
        mx1 = fmaxf(mx1, __shfl_xor_sync(0xffffffffu, mx1, 1));
        mx1 = fmaxf(mx1, __shfl_xor_sync(0xffffffffu, mx1, 2));
        float sum0 = 0.f, sum1 = 0.f;
#pragma unroll
        for (int nb = 0; nb < NT8; nb++) {
#pragma unroll
            for (int e = 0; e < 2; e++) {
                int col = nb * 8 + 2 * lid + e;
                float p0 = (col < NTOK) ? __expf(acc[nb][e] - mx0) : 0.f;
                float p1 = (col < NTOK) ? __expf(acc[nb][2 + e] - mx1) : 0.f;
                acc[nb][e] = p0; acc[nb][2 + e] = p1;
                sum0 += p0; sum1 += p1;
            }
        }
        sum0 += __shfl_xor_sync(0xffffffffu, sum0, 1);
        sum0 += __shfl_xor_sync(0xffffffffu, sum0, 2);
        sum1 += __shfl_xor_sync(0xffffffffu, sum1, 1);
        sum1 += __shfl_xor_sync(0xffffffffu, sum1, 2);
        float oacc[8][4];
#pragma unroll
        for (int db = 0; db < 8; db++)
#pragma unroll
            for (int q = 0; q < 4; q++) oacc[db][q] = 0.f;
#pragma unroll
        for (int t = 0; t < NPAD/16; t++) {
            uint32_t pa[4];
            pa[0] = h2u(__floats2half2_rn(acc[2*t][0],   acc[2*t][1]));
            pa[1] = h2u(__floats2half2_rn(acc[2*t][2],   acc[2*t][3]));
            pa[2] = h2u(__floats2half2_rn(acc[2*t+1][0], acc[2*t+1][1]));
            pa[3] = h2u(__floats2half2_rn(acc[2*t+1][2], acc[2*t+1][3]));
#pragma unroll
            for (int dp = 0; dp < 4; dp++) {
                uint32_t bfr[4];
                ldsm_x4_t(bfr, v_base + (uint32_t)(t * 16 * AP + dp * 16) * 2u);
                mma_f16(oacc[2*dp],     pa, bfr);
                mma_f16(oacc[2*dp + 1], pa, bfr + 2);
            }
        }
        float i0 = 1.f / sum0, i1 = 1.f / sum1;
        int r0 = m0 + qid, r1 = r0 + 8;
#pragma unroll
        for (int db = 0; db < 8; db++) {
            int col = h * HDIM + db * 8 + 2 * lid;
            if (r0 < NTOK) {
                __half2 v = __floats2half2_rn(oacc[db][0] * i0, oacc[db][1] * i0);
                *(__half2*)&o[((size_t)(b * NTOK + r0)) * CDIM + col] = v;
            }
            if (r1 < NTOK) {
                __half2 v = __floats2half2_rn(oacc[db][2] * i1, oacc[db][3] * i1);
                *(__half2*)&o[((size_t)(b * NTOK + r1)) * CDIM + col] = v;
            }
        }
    }
}

// ---------------- host orchestration ----------------
extern "C" void kernel_launch(void* const* d_in, const int* in_sizes, int n_in,
                              void* d_out, int out_size)
{
    const float* x      = (const float*)d_in[0];
    const float* rope   = (const float*)d_in[1];
    const float* qkv_w  = (const float*)d_in[2];
    const float* q_bias = (const float*)d_in[3];
    const float* v_bias = (const float*)d_in[4];
    const float* proj_w = (const float*)d_in[5];
    const float* proj_b = (const float*)d_in[6];
    const float* n1_g   = (const float*)d_in[7];
    const float* n1_b   = (const float*)d_in[8];
    const float* n2_g   = (const float*)d_in[9];
    const float* n2_b   = (const float*)d_in[10];
    const float* w1g    = (const float*)d_in[11];
    const float* b1g    = (const float*)d_in[12];
    const float* w1x    = (const float*)d_in[13];
    const float* b1x    = (const float*)d_in[14];
    const float* nm_g   = (const float*)d_in[15];
    const float* nm_b   = (const float*)d_in[16];
    const float* w2     = (const float*)d_in[17];
    const float* b2     = (const float*)d_in[18];
    float* out = (float*)d_out;

    __half *y, *o, *u, *gu, *wc, *qh, *kh, *vh;
    float *bias3, *bgu;
    cudaGetSymbolAddress((void**)&y,     g_y);
    cudaGetSymbolAddress((void**)&o,     g_o);
    cudaGetSymbolAddress((void**)&u,     g_u);
    cudaGetSymbolAddress((void**)&gu,    g_gu);
    cudaGetSymbolAddress((void**)&bias3, g_bias3);
    cudaGetSymbolAddress((void**)&bgu,   g_bgu);
    cudaGetSymbolAddress((void**)&wc,    g_wc);
    cudaGetSymbolAddress((void**)&qh,    g_qh);
    cudaGetSymbolAddress((void**)&kh,    g_kh);
    cudaGetSymbolAddress((void**)&vh,    g_vh);

    __half* qkvw_c  = wc + WC_QKV;
    __half* projw_c = wc + WC_PROJ;
    __half* guw_c   = wc + WC_GU;
    __half* w2_c    = wc + WC_W2;

    cudaFuncSetAttribute(tc_gemm<MODE_RES>,
        cudaFuncAttributeMaxDynamicSharedMemorySize, GEMM_SMEM);
    cudaFuncSetAttribute(tc_gemm<MODE_H16>,
        cudaFuncAttributeMaxDynamicSharedMemorySize, GEMM_SMEM);
    cudaFuncSetAttribute(tc_gemm<MODE_QKV>,
        cudaFuncAttributeMaxDynamicSharedMemorySize, GEMM_SMEM);
    cudaFuncSetAttribute(attn_tc_kernel,
        cudaFuncAttributeMaxDynamicSharedMemorySize, ATTN_TC_SMEM);

    cudaMemcpyAsync(out, x, (size_t)TTOK * CDIM * sizeof(float),
                    cudaMemcpyDeviceToDevice);

    // pre-convert weights to fp16; pack [w1g;w1x] per layer for fused GEMM
    {
        int n;
        n = LNUM*C3*CDIM/4;   cvth_kernel<<<(n+255)/256, 256>>>(qkv_w,  qkvw_c,  n);
        n = LNUM*CDIM*CDIM/4; cvth_kernel<<<(n+255)/256, 256>>>(proj_w, projw_c, n);
        n = HF*CDIM/4;
        for (int l = 0; l < LNUM; l++) {
            cvth_kernel<<<(n+255)/256, 256>>>(
                w1g + (size_t)l*HF*CDIM, guw_c + (size_t)l*2*HF*CDIM, n);
            cvth_kernel<<<(n+255)/256, 256>>>(
                w1x + (size_t)l*HF*CDIM, guw_c + (size_t)l*2*HF*CDIM + (size_t)HF*CDIM, n);
        }
        n = LNUM*CDIM*HF/4;   cvth_kernel<<<(n+255)/256, 256>>>(w2, w2_c, n);
    }

    bias3_kernel<<<(LNUM*C3 + 255)/256, 256>>>(bias3, q_bias, v_bias);
    biasgu_kernel<<<(LNUM*2*HF + 255)/256, 256>>>(bgu, b1g, b1x);
    {
        int n = BB * NH * (NPAD - NTOK) * HDIM / 2;
        padzero_kernel<<<(n + 255)/256, 256>>>(qh, kh, vh);
    }

    const int MB = (TTOK + BM - 1) / BM;     // 99
    const int LNG = (TTOK + 7) / 8;          // warp-per-row LN grid

    for (int l = 0; l < LNUM; l++) {
        ln_kernel<CDIM><<<LNG, 256>>>(out, n1_g + l*CDIM, n1_b + l*CDIM, y);
        tc_gemm<MODE_QKV><<<dim3(C3/BN, MB), 256, GEMM_SMEM>>>(
            y, qkvw_c + (size_t)l*C3*CDIM, bias3 + l*C3,
            nullptr, nullptr, rope, qh, kh, vh, TTOK, C3, CDIM, 0);
        attn_tc_kernel<<<BB*NH, 128, ATTN_TC_SMEM>>>(qh, kh, vh, o);
        tc_gemm<MODE_RES><<<dim3(CDIM/BN, MB), 256, GEMM_SMEM>>>(
            o, projw_c + (size_t)l*CDIM*CDIM, proj_b + l*CDIM,
            out, nullptr, nullptr, nullptr, nullptr, nullptr, TTOK, CDIM, CDIM, 1);

        ln_kernel<CDIM><<<LNG, 256>>>(out, n2_g + l*CDIM, n2_b + l*CDIM, y);
        tc_gemm<MODE_H16><<<dim3(2*HF/BN, MB), 256, GEMM_SMEM>>>(
            y, guw_c + (size_t)l*2*HF*CDIM, bgu + l*2*HF,
            nullptr, gu, nullptr, nullptr, nullptr, nullptr, TTOK, 2*HF, CDIM, 0);
        swiglu_ln_kernel<<<TTOK, 256>>>(gu, nm_g + l*HF, nm_b + l*HF, u);
        // w2: split-K=2 (gridDim.z=2), atomic accumulate onto residual in `out`
        tc_gemm<MODE_RES><<<dim3(CDIM/BN, MB, 2), 256, GEMM_SMEM>>>(
            u, w2_c + (size_t)l*CDIM*HF, b2 + l*CDIM,
            out, nullptr, nullptr, nullptr, nullptr, nullptr, TTOK, CDIM, HF, 1);
    }
}